// round 1
// baseline (speedup 1.0000x reference)
#include <cuda_runtime.h>
#include <math.h>

#define B_   4
#define S_   2048
#define DM   1024
#define H_   8
#define DK   128
#define DC   32
#define DHR  32
#define DQK  160            // DK + DHR
#define BS_  (B_*S_)        // 8192

// ---------------- scratch (device globals; no allocations allowed) ----------
__device__ float g_cq [BS_*DC];
__device__ float g_ckv[BS_*DC];
__device__ float g_kr [BS_*DC];
__device__ float g_q[(size_t)B_*H_*S_*DQK];   // [B,H,S,160]
__device__ float g_k[(size_t)B_*H_*S_*DQK];   // [B,H,S,160]
__device__ float g_v[(size_t)B_*H_*S_*DK];    // [B,H,S,128]
__device__ float g_o[(size_t)BS_*H_*DK];      // [B,S,H*128]

// ---------------------------------------------------------------------------
// Kernel 1: down projections  c_q = h@W_DQ+b, c_kv = h@W_DKV+b, kr = h@W_KR+b
// block: 256 thr, 32 rows x 96 cols, K=1024 in chunks of 64
// ---------------------------------------------------------------------------
__global__ void __launch_bounds__(256) down_proj_kernel(
    const float* __restrict__ h,
    const float* __restrict__ Wdq,  const float* __restrict__ bdq,
    const float* __restrict__ Wdkv, const float* __restrict__ bdkv,
    const float* __restrict__ Wkr,  const float* __restrict__ bkr)
{
    __shared__ float h_s[32*64];
    __shared__ float w_s[64*96];
    const int tid  = threadIdx.x;
    const int row0 = blockIdx.x * 32;
    const int ty = tid >> 5, tx = tid & 31;

    float acc[4][3];
#pragma unroll
    for (int i = 0; i < 4; i++)
#pragma unroll
        for (int j = 0; j < 3; j++) acc[i][j] = 0.f;

    for (int kc = 0; kc < 16; kc++) {
        __syncthreads();
#pragma unroll
        for (int i = 0; i < 2; i++) {
            int idx4 = tid + i*256;
            int r = idx4 >> 4, c4 = idx4 & 15;
            float4 v = *(const float4*)(h + (size_t)(row0+r)*DM + kc*64 + c4*4);
            *(float4*)(h_s + r*64 + c4*4) = v;
        }
#pragma unroll
        for (int i = 0; i < 24; i++) {
            int idx = tid + i*256;
            int k = idx / 96, c = idx - k*96;
            int gk = kc*64 + k;
            float w;
            if (c < 32)      w = Wdq [gk*32 + c];
            else if (c < 64) w = Wdkv[gk*32 + (c-32)];
            else             w = Wkr [gk*32 + (c-64)];
            w_s[k*96 + c] = w;
        }
        __syncthreads();
#pragma unroll 8
        for (int kk = 0; kk < 64; kk++) {
            float a0 = h_s[(ty*4+0)*64 + kk];
            float a1 = h_s[(ty*4+1)*64 + kk];
            float a2 = h_s[(ty*4+2)*64 + kk];
            float a3 = h_s[(ty*4+3)*64 + kk];
            float b0 = w_s[kk*96 + tx];
            float b1 = w_s[kk*96 + tx + 32];
            float b2 = w_s[kk*96 + tx + 64];
            acc[0][0] += a0*b0; acc[0][1] += a0*b1; acc[0][2] += a0*b2;
            acc[1][0] += a1*b0; acc[1][1] += a1*b1; acc[1][2] += a1*b2;
            acc[2][0] += a2*b0; acc[2][1] += a2*b1; acc[2][2] += a2*b2;
            acc[3][0] += a3*b0; acc[3][1] += a3*b1; acc[3][2] += a3*b2;
        }
    }
#pragma unroll
    for (int i = 0; i < 4; i++) {
        int row = row0 + ty*4 + i;
        g_cq [row*32 + tx] = acc[i][0] + bdq [tx];
        g_ckv[row*32 + tx] = acc[i][1] + bdkv[tx];
        g_kr [row*32 + tx] = acc[i][2] + bkr [tx];
    }
}

// ---------------------------------------------------------------------------
// Kernel 2: up projections (K=32).  grid.x tile -> which matrix/col range,
// grid.y -> 64-row tile.  ct==13 broadcasts k_r across heads.
// ---------------------------------------------------------------------------
__global__ void __launch_bounds__(256) up_proj_kernel(
    const float* __restrict__ Wuq, const float* __restrict__ buq,
    const float* __restrict__ Wuk, const float* __restrict__ buk,
    const float* __restrict__ Wuv, const float* __restrict__ buv,
    const float* __restrict__ Wqr, const float* __restrict__ bqr)
{
    __shared__ float w_s[32*256];
    __shared__ float c_s[64*32];
    __shared__ float bias_s[256];

    const int tid  = threadIdx.x;
    const int ct   = blockIdx.x;
    const int row0 = blockIdx.y * 64;

    if (ct == 13) {
        // k_r broadcast across heads: cols = 8 heads x 32 dims
        int hh = tid >> 5, c = tid & 31;
        for (int r = 0; r < 64; r++) {
            int row = row0 + r;
            int bb = row >> 11, ss = row & 2047;
            float v = g_kr[row*32 + c];
            g_k[((size_t)(bb*H_ + hh)*S_ + ss)*DQK + 128 + c] = v;
        }
        return;
    }

    const float *W, *bias, *src;
    int colbase, Wn, dest;                 // dest: 0=q_c 1=q_r 2=k_c 3=v_c
    if (ct < 4)      { W=Wuq; bias=buq; src=g_cq;  colbase=ct*256;     Wn=1024; dest=0; }
    else if (ct==4)  { W=Wqr; bias=bqr; src=g_cq;  colbase=0;          Wn=256;  dest=1; }
    else if (ct < 9) { W=Wuk; bias=buk; src=g_ckv; colbase=(ct-5)*256; Wn=1024; dest=2; }
    else             { W=Wuv; bias=buv; src=g_ckv; colbase=(ct-9)*256; Wn=1024; dest=3; }

#pragma unroll
    for (int k = 0; k < 32; k++) w_s[k*256 + tid] = W[k*Wn + colbase + tid];
    bias_s[tid] = bias[colbase + tid];
#pragma unroll
    for (int i = 0; i < 8; i++) {
        int idx = tid + i*256;
        c_s[idx] = src[row0*32 + idx];
    }
    __syncthreads();

    const int gcol = colbase + tid;
    for (int r = 0; r < 64; r++) {
        float acc = bias_s[tid];
#pragma unroll
        for (int k = 0; k < 32; k++) acc += c_s[r*32 + k] * w_s[k*256 + tid];
        int row = row0 + r;
        int bb = row >> 11, ss = row & 2047;
        if (dest == 0) {
            int hh = gcol >> 7, d = gcol & 127;
            g_q[((size_t)(bb*H_ + hh)*S_ + ss)*DQK + d] = acc;
        } else if (dest == 1) {
            int hh = gcol >> 5, d = gcol & 31;
            g_q[((size_t)(bb*H_ + hh)*S_ + ss)*DQK + 128 + d] = acc;
        } else if (dest == 2) {
            int hh = gcol >> 7, d = gcol & 127;
            g_k[((size_t)(bb*H_ + hh)*S_ + ss)*DQK + d] = acc;
        } else {
            int hh = gcol >> 7, d = gcol & 127;
            g_v[((size_t)(bb*H_ + hh)*S_ + ss)*DK + d] = acc;
        }
    }
}

// ---------------------------------------------------------------------------
// Kernel 3: flash attention, fp32. One block = one (b,h) x 64-query tile.
// 256 threads = 16x16; QK^T 4x4 per thread, PV 4x8 per thread.
// ---------------------------------------------------------------------------
#define QS 161
#define KS 161
#define VS 132
#define PS 65
#define ATTN_SMEM_FLOATS (64*QS + 64*KS + 64*VS + 64*PS)

__global__ void __launch_bounds__(256) attn_kernel()
{
    extern __shared__ float sm[];
    float* q_s = sm;
    float* k_s = q_s + 64*QS;
    float* v_s = k_s + 64*KS;
    float* p_s = v_s + 64*VS;

    const int tid = threadIdx.x;
    const int ty = tid >> 4, tx = tid & 15;
    const int bh = blockIdx.y;
    const int q0 = blockIdx.x * 64;

    const float* qg = g_q + ((size_t)bh*S_ + q0)*DQK;
    const float* kg = g_k + (size_t)bh*S_*DQK;
    const float* vg = g_v + (size_t)bh*S_*DK;

    const float scale = 0.07905694150420948f;  // 1/sqrt(160)

    // load Q tile, pre-scaled
#pragma unroll
    for (int i = 0; i < 10; i++) {
        int idx4 = tid + i*256;
        int r = idx4 / 40, c4 = idx4 - r*40;
        float4 v = *(const float4*)(qg + (size_t)r*DQK + c4*4);
        q_s[r*QS + c4*4 + 0] = v.x * scale;
        q_s[r*QS + c4*4 + 1] = v.y * scale;
        q_s[r*QS + c4*4 + 2] = v.z * scale;
        q_s[r*QS + c4*4 + 3] = v.w * scale;
    }

    float m0[4], l0[4], acc[4][8];
#pragma unroll
    for (int i = 0; i < 4; i++) {
        m0[i] = -1e30f; l0[i] = 0.f;
#pragma unroll
        for (int j = 0; j < 8; j++) acc[i][j] = 0.f;
    }

    for (int kt = 0; kt < S_/64; kt++) {
        __syncthreads();                       // prior PV done -> safe to overwrite
        const int key0 = kt * 64;
#pragma unroll
        for (int i = 0; i < 10; i++) {
            int idx4 = tid + i*256;
            int r = idx4 / 40, c4 = idx4 - r*40;
            float4 v = *(const float4*)(kg + (size_t)(key0+r)*DQK + c4*4);
            k_s[r*KS + c4*4 + 0] = v.x;
            k_s[r*KS + c4*4 + 1] = v.y;
            k_s[r*KS + c4*4 + 2] = v.z;
            k_s[r*KS + c4*4 + 3] = v.w;
        }
#pragma unroll
        for (int i = 0; i < 8; i++) {
            int idx4 = tid + i*256;
            int r = idx4 >> 5, c4 = idx4 & 31;
            float4 v = *(const float4*)(vg + (size_t)(key0+r)*DK + c4*4);
            *(float4*)(v_s + r*VS + c4*4) = v;
        }
        __syncthreads();

        // S = Q K^T  (Q pre-scaled)
        float s[4][4];
#pragma unroll
        for (int i = 0; i < 4; i++)
#pragma unroll
            for (int j = 0; j < 4; j++) s[i][j] = 0.f;

#pragma unroll 8
        for (int kd = 0; kd < DQK; kd++) {
            float a[4], b[4];
#pragma unroll
            for (int i = 0; i < 4; i++) a[i] = q_s[(ty*4+i)*QS + kd];
#pragma unroll
            for (int j = 0; j < 4; j++) b[j] = k_s[(tx*4+j)*KS + kd];
#pragma unroll
            for (int i = 0; i < 4; i++)
#pragma unroll
                for (int j = 0; j < 4; j++) s[i][j] += a[i]*b[j];
        }

        // online softmax update
#pragma unroll
        for (int i = 0; i < 4; i++) {
            float mx = fmaxf(fmaxf(s[i][0], s[i][1]), fmaxf(s[i][2], s[i][3]));
            mx = fmaxf(mx, __shfl_xor_sync(0xffffffffu, mx, 1));
            mx = fmaxf(mx, __shfl_xor_sync(0xffffffffu, mx, 2));
            mx = fmaxf(mx, __shfl_xor_sync(0xffffffffu, mx, 4));
            mx = fmaxf(mx, __shfl_xor_sync(0xffffffffu, mx, 8));
            float newm = fmaxf(m0[i], mx);
            float alpha = __expf(m0[i] - newm);
            m0[i] = newm;
            float p0 = __expf(s[i][0] - newm);
            float p1 = __expf(s[i][1] - newm);
            float p2 = __expf(s[i][2] - newm);
            float p3 = __expf(s[i][3] - newm);
            float rs = (p0+p1) + (p2+p3);
            rs += __shfl_xor_sync(0xffffffffu, rs, 1);
            rs += __shfl_xor_sync(0xffffffffu, rs, 2);
            rs += __shfl_xor_sync(0xffffffffu, rs, 4);
            rs += __shfl_xor_sync(0xffffffffu, rs, 8);
            l0[i] = l0[i]*alpha + rs;
#pragma unroll
            for (int j = 0; j < 8; j++) acc[i][j] *= alpha;
            p_s[(ty*4+i)*PS + tx*4 + 0] = p0;
            p_s[(ty*4+i)*PS + tx*4 + 1] = p1;
            p_s[(ty*4+i)*PS + tx*4 + 2] = p2;
            p_s[(ty*4+i)*PS + tx*4 + 3] = p3;
        }
        __syncthreads();

        // O += P V
#pragma unroll 4
        for (int t = 0; t < 64; t++) {
            float a[4];
#pragma unroll
            for (int i = 0; i < 4; i++) a[i] = p_s[(ty*4+i)*PS + t];
            float4 b0 = *(const float4*)(v_s + t*VS + tx*8);
            float4 b1 = *(const float4*)(v_s + t*VS + tx*8 + 4);
#pragma unroll
            for (int i = 0; i < 4; i++) {
                acc[i][0] += a[i]*b0.x; acc[i][1] += a[i]*b0.y;
                acc[i][2] += a[i]*b0.z; acc[i][3] += a[i]*b0.w;
                acc[i][4] += a[i]*b1.x; acc[i][5] += a[i]*b1.y;
                acc[i][6] += a[i]*b1.z; acc[i][7] += a[i]*b1.w;
            }
        }
    }

    const int bb = bh >> 3, hh = bh & 7;
#pragma unroll
    for (int i = 0; i < 4; i++) {
        float inv = 1.f / l0[i];
        int srow = q0 + ty*4 + i;
        float* op = g_o + ((size_t)(bb*S_ + srow)*H_ + hh)*DK + tx*8;
        float4 o0 = make_float4(acc[i][0]*inv, acc[i][1]*inv, acc[i][2]*inv, acc[i][3]*inv);
        float4 o1 = make_float4(acc[i][4]*inv, acc[i][5]*inv, acc[i][6]*inv, acc[i][7]*inv);
        *(float4*)(op)     = o0;
        *(float4*)(op + 4) = o1;
    }
}

// ---------------------------------------------------------------------------
// Kernel 4: out = g_o @ W_O + b_O   ([8192,1024] x [1024,1024])
// 64x64 tiles, 256 thr, 4x4 per thread, K chunks of 32
// ---------------------------------------------------------------------------
__global__ void __launch_bounds__(256) out_proj_kernel(
    const float* __restrict__ Wo, const float* __restrict__ bo,
    float* __restrict__ out)
{
    __shared__ float a_s[64*33];
    __shared__ float b_s[32*68];
    const int tid = threadIdx.x;
    const int ty = tid >> 4, tx = tid & 15;
    const int col0 = blockIdx.x * 64;
    const int row0 = blockIdx.y * 64;

    float acc[4][4];
#pragma unroll
    for (int i = 0; i < 4; i++)
#pragma unroll
        for (int j = 0; j < 4; j++) acc[i][j] = 0.f;

    for (int kc = 0; kc < 32; kc++) {
        __syncthreads();
#pragma unroll
        for (int i = 0; i < 2; i++) {
            int idx4 = tid + i*256;
            int r = idx4 >> 3, k4 = idx4 & 7;
            float4 v = *(const float4*)(g_o + (size_t)(row0+r)*DM + kc*32 + k4*4);
            a_s[r*33 + k4*4 + 0] = v.x;
            a_s[r*33 + k4*4 + 1] = v.y;
            a_s[r*33 + k4*4 + 2] = v.z;
            a_s[r*33 + k4*4 + 3] = v.w;
        }
#pragma unroll
        for (int i = 0; i < 2; i++) {
            int idx4 = tid + i*256;
            int k = idx4 >> 4, n4 = idx4 & 15;
            float4 v = *(const float4*)(Wo + (size_t)(kc*32+k)*DM + col0 + n4*4);
            *(float4*)(b_s + k*68 + n4*4) = v;
        }
        __syncthreads();
#pragma unroll 8
        for (int kk = 0; kk < 32; kk++) {
            float a[4];
#pragma unroll
            for (int i = 0; i < 4; i++) a[i] = a_s[(ty*4+i)*33 + kk];
            float4 b4 = *(const float4*)(b_s + kk*68 + tx*4);
#pragma unroll
            for (int i = 0; i < 4; i++) {
                acc[i][0] += a[i]*b4.x; acc[i][1] += a[i]*b4.y;
                acc[i][2] += a[i]*b4.z; acc[i][3] += a[i]*b4.w;
            }
        }
    }
#pragma unroll
    for (int i = 0; i < 4; i++) {
        float4 o;
        o.x = acc[i][0] + bo[col0 + tx*4 + 0];
        o.y = acc[i][1] + bo[col0 + tx*4 + 1];
        o.z = acc[i][2] + bo[col0 + tx*4 + 2];
        o.w = acc[i][3] + bo[col0 + tx*4 + 3];
        *(float4*)(out + (size_t)(row0 + ty*4 + i)*DM + col0 + tx*4) = o;
    }
}

// ---------------------------------------------------------------------------
extern "C" void kernel_launch(void* const* d_in, const int* in_sizes, int n_in,
                              void* d_out, int out_size)
{
    (void)in_sizes; (void)n_in; (void)out_size;
    const float* h    = (const float*)d_in[0];
    const float* Wdq  = (const float*)d_in[1];
    const float* bdq  = (const float*)d_in[2];
    const float* Wuq  = (const float*)d_in[3];
    const float* buq  = (const float*)d_in[4];
    const float* Wdkv = (const float*)d_in[5];
    const float* bdkv = (const float*)d_in[6];
    const float* Wuk  = (const float*)d_in[7];
    const float* buk  = (const float*)d_in[8];
    const float* Wuv  = (const float*)d_in[9];
    const float* buv  = (const float*)d_in[10];
    const float* Wqr  = (const float*)d_in[11];
    const float* bqr  = (const float*)d_in[12];
    const float* Wkr  = (const float*)d_in[13];
    const float* bkr  = (const float*)d_in[14];
    const float* Wo   = (const float*)d_in[15];
    const float* bo   = (const float*)d_in[16];
    float* out = (float*)d_out;

    cudaFuncSetAttribute(attn_kernel, cudaFuncAttributeMaxDynamicSharedMemorySize,
                         ATTN_SMEM_FLOATS * (int)sizeof(float));

    down_proj_kernel<<<BS_/32, 256>>>(h, Wdq, bdq, Wdkv, bdkv, Wkr, bkr);
    up_proj_kernel<<<dim3(14, BS_/64), 256>>>(Wuq, buq, Wuk, buk, Wuv, buv, Wqr, bqr);
    attn_kernel<<<dim3(S_/64, B_*H_), 256, ATTN_SMEM_FLOATS * sizeof(float)>>>();
    out_proj_kernel<<<dim3(DM/64, BS_/64), 256>>>(Wo, bo, out);
}

// round 2
// speedup vs baseline: 3.0984x; 3.0984x over previous
#include <cuda_runtime.h>
#include <math.h>
#include <stdint.h>

#define B_   4
#define S_   2048
#define DM   1024
#define H_   8
#define DK   128
#define DC   32
#define DHR  32
#define DQK  160            // DK + DHR
#define BS_  (B_*S_)        // 8192

// ---------------- scratch (device globals; no allocations allowed) ----------
__device__ float g_cq [BS_*DC];
__device__ float g_ckv[BS_*DC];
__device__ float g_kr [BS_*DC];
__device__ float g_q[(size_t)B_*H_*S_*DQK];   // [B,H,S,160]
__device__ float g_k[(size_t)B_*H_*S_*DQK];   // [B,H,S,160]
__device__ float g_v[(size_t)B_*H_*S_*DK];    // [B,H,S,128]
__device__ float g_o[(size_t)BS_*H_*DK];      // [B,S,H*128]

// ---------------- tf32 helpers ----------------------------------------------
__device__ __forceinline__ float to_tf32(float x) {
    uint32_t u;
    asm("cvt.rna.tf32.f32 %0, %1;" : "=r"(u) : "f"(x));
    return __uint_as_float(u);
}

__device__ __forceinline__ void mma_tf32(float* d, const float* a, const float* b) {
    asm("mma.sync.aligned.m16n8k8.row.col.f32.tf32.tf32.f32 "
        "{%0,%1,%2,%3}, {%4,%5,%6,%7}, {%8,%9}, {%0,%1,%2,%3};"
        : "+f"(d[0]), "+f"(d[1]), "+f"(d[2]), "+f"(d[3])
        : "r"(__float_as_uint(a[0])), "r"(__float_as_uint(a[1])),
          "r"(__float_as_uint(a[2])), "r"(__float_as_uint(a[3])),
          "r"(__float_as_uint(b[0])), "r"(__float_as_uint(b[1])));
}

// ---------------------------------------------------------------------------
// Kernel 1: down projections  c_q = h@W_DQ+b, c_kv = h@W_DKV+b, kr = h@W_KR+b
// ---------------------------------------------------------------------------
__global__ void __launch_bounds__(256) down_proj_kernel(
    const float* __restrict__ h,
    const float* __restrict__ Wdq,  const float* __restrict__ bdq,
    const float* __restrict__ Wdkv, const float* __restrict__ bdkv,
    const float* __restrict__ Wkr,  const float* __restrict__ bkr)
{
    __shared__ float h_s[32*64];
    __shared__ float w_s[64*96];
    const int tid  = threadIdx.x;
    const int row0 = blockIdx.x * 32;
    const int ty = tid >> 5, tx = tid & 31;

    float acc[4][3];
#pragma unroll
    for (int i = 0; i < 4; i++)
#pragma unroll
        for (int j = 0; j < 3; j++) acc[i][j] = 0.f;

    for (int kc = 0; kc < 16; kc++) {
        __syncthreads();
#pragma unroll
        for (int i = 0; i < 2; i++) {
            int idx4 = tid + i*256;
            int r = idx4 >> 4, c4 = idx4 & 15;
            float4 v = *(const float4*)(h + (size_t)(row0+r)*DM + kc*64 + c4*4);
            *(float4*)(h_s + r*64 + c4*4) = v;
        }
#pragma unroll
        for (int i = 0; i < 24; i++) {
            int idx = tid + i*256;
            int k = idx / 96, c = idx - k*96;
            int gk = kc*64 + k;
            float w;
            if (c < 32)      w = Wdq [gk*32 + c];
            else if (c < 64) w = Wdkv[gk*32 + (c-32)];
            else             w = Wkr [gk*32 + (c-64)];
            w_s[k*96 + c] = w;
        }
        __syncthreads();
#pragma unroll 8
        for (int kk = 0; kk < 64; kk++) {
            float a0 = h_s[(ty*4+0)*64 + kk];
            float a1 = h_s[(ty*4+1)*64 + kk];
            float a2 = h_s[(ty*4+2)*64 + kk];
            float a3 = h_s[(ty*4+3)*64 + kk];
            float b0 = w_s[kk*96 + tx];
            float b1 = w_s[kk*96 + tx + 32];
            float b2 = w_s[kk*96 + tx + 64];
            acc[0][0] += a0*b0; acc[0][1] += a0*b1; acc[0][2] += a0*b2;
            acc[1][0] += a1*b0; acc[1][1] += a1*b1; acc[1][2] += a1*b2;
            acc[2][0] += a2*b0; acc[2][1] += a2*b1; acc[2][2] += a2*b2;
            acc[3][0] += a3*b0; acc[3][1] += a3*b1; acc[3][2] += a3*b2;
        }
    }
#pragma unroll
    for (int i = 0; i < 4; i++) {
        int row = row0 + ty*4 + i;
        g_cq [row*32 + tx] = acc[i][0] + bdq [tx];
        g_ckv[row*32 + tx] = acc[i][1] + bdkv[tx];
        g_kr [row*32 + tx] = acc[i][2] + bkr [tx];
    }
}

// ---------------------------------------------------------------------------
// Kernel 2: up projections (K=32)
// ---------------------------------------------------------------------------
__global__ void __launch_bounds__(256) up_proj_kernel(
    const float* __restrict__ Wuq, const float* __restrict__ buq,
    const float* __restrict__ Wuk, const float* __restrict__ buk,
    const float* __restrict__ Wuv, const float* __restrict__ buv,
    const float* __restrict__ Wqr, const float* __restrict__ bqr)
{
    __shared__ float w_s[32*256];
    __shared__ float c_s[64*32];
    __shared__ float bias_s[256];

    const int tid  = threadIdx.x;
    const int ct   = blockIdx.x;
    const int row0 = blockIdx.y * 64;

    if (ct == 13) {
        int hh = tid >> 5, c = tid & 31;
        for (int r = 0; r < 64; r++) {
            int row = row0 + r;
            int bb = row >> 11, ss = row & 2047;
            float v = g_kr[row*32 + c];
            g_k[((size_t)(bb*H_ + hh)*S_ + ss)*DQK + 128 + c] = v;
        }
        return;
    }

    const float *W, *bias, *src;
    int colbase, Wn, dest;                 // 0=q_c 1=q_r 2=k_c 3=v_c
    if (ct < 4)      { W=Wuq; bias=buq; src=g_cq;  colbase=ct*256;     Wn=1024; dest=0; }
    else if (ct==4)  { W=Wqr; bias=bqr; src=g_cq;  colbase=0;          Wn=256;  dest=1; }
    else if (ct < 9) { W=Wuk; bias=buk; src=g_ckv; colbase=(ct-5)*256; Wn=1024; dest=2; }
    else             { W=Wuv; bias=buv; src=g_ckv; colbase=(ct-9)*256; Wn=1024; dest=3; }

#pragma unroll
    for (int k = 0; k < 32; k++) w_s[k*256 + tid] = W[k*Wn + colbase + tid];
    bias_s[tid] = bias[colbase + tid];
#pragma unroll
    for (int i = 0; i < 8; i++) {
        int idx = tid + i*256;
        c_s[idx] = src[row0*32 + idx];
    }
    __syncthreads();

    const int gcol = colbase + tid;
    for (int r = 0; r < 64; r++) {
        float acc = bias_s[tid];
#pragma unroll
        for (int k = 0; k < 32; k++) acc += c_s[r*32 + k] * w_s[k*256 + tid];
        int row = row0 + r;
        int bb = row >> 11, ss = row & 2047;
        if (dest == 0) {
            int hh = gcol >> 7, d = gcol & 127;
            g_q[((size_t)(bb*H_ + hh)*S_ + ss)*DQK + d] = acc;
        } else if (dest == 1) {
            int hh = gcol >> 5, d = gcol & 31;
            g_q[((size_t)(bb*H_ + hh)*S_ + ss)*DQK + 128 + d] = acc;
        } else if (dest == 2) {
            int hh = gcol >> 7, d = gcol & 127;
            g_k[((size_t)(bb*H_ + hh)*S_ + ss)*DQK + d] = acc;
        } else {
            int hh = gcol >> 7, d = gcol & 127;
            g_v[((size_t)(bb*H_ + hh)*S_ + ss)*DK + d] = acc;
        }
    }
}

// ---------------------------------------------------------------------------
// Kernel 3: flash attention with tf32 mma.sync (m16n8k8).
// Block = 256 thr = 8 warps. Q tile 128 (16 rows/warp), key tile 64.
// ---------------------------------------------------------------------------
#define SQ 164   // q_s row stride  (164 % 32 == 4 -> conflict-free A frags)
#define SKK 164  // k_s row stride
#define SV 136   // v_s row stride  (136 % 32 == 8 -> conflict-free B frags)
#define SP 68    // p_s row stride  (68 % 32 == 4)
#define ATTN_SMEM_FLOATS (128*SQ + 64*SKK + 64*SV + 128*SP)

__global__ void __launch_bounds__(256, 1) attn_kernel()
{
    extern __shared__ float sm[];
    float* q_s = sm;
    float* k_s = q_s + 128*SQ;
    float* v_s = k_s + 64*SKK;
    float* p_s = v_s + 64*SV;

    const int tid  = threadIdx.x;
    const int lane = tid & 31;
    const int warp = tid >> 5;
    const int gid  = lane >> 2;   // groupID 0..7
    const int tig  = lane & 3;    // thread-in-group 0..3
    const int bh   = blockIdx.y;
    const int q0   = blockIdx.x * 128;

    const float* qg = g_q + ((size_t)bh*S_ + q0)*DQK;
    const float* kg = g_k + (size_t)bh*S_*DQK;
    const float* vg = g_v + (size_t)bh*S_*DK;

    const float scale = 0.07905694150420948f;  // 1/sqrt(160)

    // ---- load Q tile (pre-scaled, tf32-rounded) ----
#pragma unroll
    for (int i = 0; i < 20; i++) {
        int idx4 = tid + i*256;
        int r = idx4 / 40, c4 = idx4 - r*40;
        float4 v = *(const float4*)(qg + (size_t)r*DQK + c4*4);
        q_s[r*SQ + c4*4 + 0] = to_tf32(v.x * scale);
        q_s[r*SQ + c4*4 + 1] = to_tf32(v.y * scale);
        q_s[r*SQ + c4*4 + 2] = to_tf32(v.z * scale);
        q_s[r*SQ + c4*4 + 3] = to_tf32(v.w * scale);
    }

    const int r0 = warp*16 + gid;        // first row this thread touches
    float m0 = -1e30f, m1 = -1e30f, l0 = 0.f, l1 = 0.f;
    float o[16][4];
#pragma unroll
    for (int i = 0; i < 16; i++)
#pragma unroll
        for (int j = 0; j < 4; j++) o[i][j] = 0.f;

    for (int kt = 0; kt < S_/64; kt++) {
        __syncthreads();
        const int key0 = kt * 64;
        // ---- load K tile ----
#pragma unroll
        for (int i = 0; i < 10; i++) {
            int idx4 = tid + i*256;
            int r = idx4 / 40, c4 = idx4 - r*40;
            float4 v = *(const float4*)(kg + (size_t)(key0+r)*DQK + c4*4);
            k_s[r*SKK + c4*4 + 0] = to_tf32(v.x);
            k_s[r*SKK + c4*4 + 1] = to_tf32(v.y);
            k_s[r*SKK + c4*4 + 2] = to_tf32(v.z);
            k_s[r*SKK + c4*4 + 3] = to_tf32(v.w);
        }
        // ---- load V tile ----
#pragma unroll
        for (int i = 0; i < 8; i++) {
            int idx4 = tid + i*256;
            int r = idx4 >> 5, c4 = idx4 & 31;
            float4 v = *(const float4*)(vg + (size_t)(key0+r)*DK + c4*4);
            v_s[r*SV + c4*4 + 0] = to_tf32(v.x);
            v_s[r*SV + c4*4 + 1] = to_tf32(v.y);
            v_s[r*SV + c4*4 + 2] = to_tf32(v.z);
            v_s[r*SV + c4*4 + 3] = to_tf32(v.w);
        }
        __syncthreads();

        // ---- S = Q K^T ----
        float sa[8][4];
#pragma unroll
        for (int n = 0; n < 8; n++)
#pragma unroll
            for (int j = 0; j < 4; j++) sa[n][j] = 0.f;

#pragma unroll
        for (int kb = 0; kb < 20; kb++) {
            const int c0 = kb*8 + tig;
            float a[4];
            a[0] = q_s[ r0     *SQ + c0    ];
            a[1] = q_s[(r0+8)  *SQ + c0    ];
            a[2] = q_s[ r0     *SQ + c0 + 4];
            a[3] = q_s[(r0+8)  *SQ + c0 + 4];
#pragma unroll
            for (int nt = 0; nt < 8; nt++) {
                const int kr = nt*8 + gid;
                float b[2];
                b[0] = k_s[kr*SKK + c0    ];
                b[1] = k_s[kr*SKK + c0 + 4];
                mma_tf32(sa[nt], a, b);
            }
        }

        // ---- online softmax (rows r0 and r0+8) ----
        float mx0 = -1e30f, mx1 = -1e30f;
#pragma unroll
        for (int n = 0; n < 8; n++) {
            mx0 = fmaxf(mx0, fmaxf(sa[n][0], sa[n][1]));
            mx1 = fmaxf(mx1, fmaxf(sa[n][2], sa[n][3]));
        }
        mx0 = fmaxf(mx0, __shfl_xor_sync(0xffffffffu, mx0, 1));
        mx0 = fmaxf(mx0, __shfl_xor_sync(0xffffffffu, mx0, 2));
        mx1 = fmaxf(mx1, __shfl_xor_sync(0xffffffffu, mx1, 1));
        mx1 = fmaxf(mx1, __shfl_xor_sync(0xffffffffu, mx1, 2));

        float nm0 = fmaxf(m0, mx0), nm1 = fmaxf(m1, mx1);
        float al0 = __expf(m0 - nm0), al1 = __expf(m1 - nm1);
        m0 = nm0; m1 = nm1;

        float rs0 = 0.f, rs1 = 0.f;
#pragma unroll
        for (int n = 0; n < 8; n++) {
            float p00 = __expf(sa[n][0] - nm0);
            float p01 = __expf(sa[n][1] - nm0);
            float p10 = __expf(sa[n][2] - nm1);
            float p11 = __expf(sa[n][3] - nm1);
            rs0 += p00 + p01; rs1 += p10 + p11;
            float2 v0 = make_float2(to_tf32(p00), to_tf32(p01));
            float2 v1 = make_float2(to_tf32(p10), to_tf32(p11));
            *(float2*)(p_s +  r0   *SP + n*8 + 2*tig) = v0;
            *(float2*)(p_s + (r0+8)*SP + n*8 + 2*tig) = v1;
        }
        rs0 += __shfl_xor_sync(0xffffffffu, rs0, 1);
        rs0 += __shfl_xor_sync(0xffffffffu, rs0, 2);
        rs1 += __shfl_xor_sync(0xffffffffu, rs1, 1);
        rs1 += __shfl_xor_sync(0xffffffffu, rs1, 2);
        l0 = l0*al0 + rs0; l1 = l1*al1 + rs1;

#pragma unroll
        for (int n = 0; n < 16; n++) {
            o[n][0] *= al0; o[n][1] *= al0;
            o[n][2] *= al1; o[n][3] *= al1;
        }
        __syncwarp();

        // ---- O += P V ----
#pragma unroll
        for (int kb = 0; kb < 8; kb++) {
            const int c0 = kb*8 + tig;
            float a[4];
            a[0] = p_s[ r0    *SP + c0    ];
            a[1] = p_s[(r0+8) *SP + c0    ];
            a[2] = p_s[ r0    *SP + c0 + 4];
            a[3] = p_s[(r0+8) *SP + c0 + 4];
#pragma unroll
            for (int nt = 0; nt < 16; nt++) {
                float b[2];
                b[0] = v_s[(kb*8 + tig    )*SV + nt*8 + gid];
                b[1] = v_s[(kb*8 + tig + 4)*SV + nt*8 + gid];
                mma_tf32(o[nt], a, b);
            }
        }
    }

    // ---- epilogue ----
    const int bb = bh >> 3, hh = bh & 7;
    const float inv0 = 1.f / l0, inv1 = 1.f / l1;
    const int s0 = q0 + r0;
    float* op0 = g_o + ((size_t)(bb*S_ + s0    )*H_ + hh)*DK;
    float* op1 = g_o + ((size_t)(bb*S_ + s0 + 8)*H_ + hh)*DK;
#pragma unroll
    for (int nt = 0; nt < 16; nt++) {
        int col = nt*8 + 2*tig;
        *(float2*)(op0 + col) = make_float2(o[nt][0]*inv0, o[nt][1]*inv0);
        *(float2*)(op1 + col) = make_float2(o[nt][2]*inv1, o[nt][3]*inv1);
    }
}

// ---------------------------------------------------------------------------
// Kernel 4: out = g_o @ W_O + b_O   tf32 mma, 128x128 tiles, k-chunk 32
// ---------------------------------------------------------------------------
#define SA 36    // a_s stride (36 % 32 == 4)
#define SB 136   // b_s stride (136 % 32 == 8)

__global__ void __launch_bounds__(256) out_proj_kernel(
    const float* __restrict__ Wo, const float* __restrict__ bo,
    float* __restrict__ out)
{
    __shared__ float a_s[128*SA];
    __shared__ float b_s[32*SB];
    const int tid  = threadIdx.x;
    const int lane = tid & 31;
    const int warp = tid >> 5;
    const int gid  = lane >> 2, tig = lane & 3;
    const int wm = warp >> 1, wn = warp & 1;     // warp tile: 32 rows x 64 cols
    const int col0 = blockIdx.x * 128;
    const int row0 = blockIdx.y * 128;

    float acc[2][8][4];
#pragma unroll
    for (int im = 0; im < 2; im++)
#pragma unroll
        for (int n = 0; n < 8; n++)
#pragma unroll
            for (int j = 0; j < 4; j++) acc[im][n][j] = 0.f;

    for (int kc = 0; kc < 32; kc++) {
        __syncthreads();
#pragma unroll
        for (int i = 0; i < 4; i++) {
            int idx4 = tid + i*256;
            int r = idx4 >> 3, c4 = idx4 & 7;
            float4 v = *(const float4*)(g_o + (size_t)(row0+r)*DM + kc*32 + c4*4);
            a_s[r*SA + c4*4 + 0] = to_tf32(v.x);
            a_s[r*SA + c4*4 + 1] = to_tf32(v.y);
            a_s[r*SA + c4*4 + 2] = to_tf32(v.z);
            a_s[r*SA + c4*4 + 3] = to_tf32(v.w);
        }
#pragma unroll
        for (int i = 0; i < 4; i++) {
            int idx4 = tid + i*256;
            int r = idx4 >> 5, c4 = idx4 & 31;
            float4 v = *(const float4*)(Wo + (size_t)(kc*32+r)*DM + col0 + c4*4);
            b_s[r*SB + c4*4 + 0] = to_tf32(v.x);
            b_s[r*SB + c4*4 + 1] = to_tf32(v.y);
            b_s[r*SB + c4*4 + 2] = to_tf32(v.z);
            b_s[r*SB + c4*4 + 3] = to_tf32(v.w);
        }
        __syncthreads();

#pragma unroll
        for (int ks = 0; ks < 4; ks++) {
            const int c0 = ks*8 + tig;
            float a0[4], a1[4];
            int ra = wm*32 + gid;
            a0[0] = a_s[ ra      *SA + c0    ];
            a0[1] = a_s[(ra+8)   *SA + c0    ];
            a0[2] = a_s[ ra      *SA + c0 + 4];
            a0[3] = a_s[(ra+8)   *SA + c0 + 4];
            a1[0] = a_s[(ra+16)  *SA + c0    ];
            a1[1] = a_s[(ra+24)  *SA + c0    ];
            a1[2] = a_s[(ra+16)  *SA + c0 + 4];
            a1[3] = a_s[(ra+24)  *SA + c0 + 4];
#pragma unroll
            for (int nt = 0; nt < 8; nt++) {
                float b[2];
                int nb = wn*64 + nt*8 + gid;
                b[0] = b_s[(ks*8 + tig    )*SB + nb];
                b[1] = b_s[(ks*8 + tig + 4)*SB + nb];
                mma_tf32(acc[0][nt], a0, b);
                mma_tf32(acc[1][nt], a1, b);
            }
        }
    }

#pragma unroll
    for (int im = 0; im < 2; im++) {
        int rr = row0 + wm*32 + im*16 + gid;
#pragma unroll
        for (int nt = 0; nt < 8; nt++) {
            int cc = col0 + wn*64 + nt*8 + 2*tig;
            float bx = bo[cc], by = bo[cc+1];
            *(float2*)(out + (size_t)rr*DM + cc) =
                make_float2(acc[im][nt][0] + bx, acc[im][nt][1] + by);
            *(float2*)(out + (size_t)(rr+8)*DM + cc) =
                make_float2(acc[im][nt][2] + bx, acc[im][nt][3] + by);
        }
    }
}

// ---------------------------------------------------------------------------
extern "C" void kernel_launch(void* const* d_in, const int* in_sizes, int n_in,
                              void* d_out, int out_size)
{
    (void)in_sizes; (void)n_in; (void)out_size;
    const float* h    = (const float*)d_in[0];
    const float* Wdq  = (const float*)d_in[1];
    const float* bdq  = (const float*)d_in[2];
    const float* Wuq  = (const float*)d_in[3];
    const float* buq  = (const float*)d_in[4];
    const float* Wdkv = (const float*)d_in[5];
    const float* bdkv = (const float*)d_in[6];
    const float* Wuk  = (const float*)d_in[7];
    const float* buk  = (const float*)d_in[8];
    const float* Wuv  = (const float*)d_in[9];
    const float* buv  = (const float*)d_in[10];
    const float* Wqr  = (const float*)d_in[11];
    const float* bqr  = (const float*)d_in[12];
    const float* Wkr  = (const float*)d_in[13];
    const float* bkr  = (const float*)d_in[14];
    const float* Wo   = (const float*)d_in[15];
    const float* bo   = (const float*)d_in[16];
    float* out = (float*)d_out;

    cudaFuncSetAttribute(attn_kernel, cudaFuncAttributeMaxDynamicSharedMemorySize,
                         ATTN_SMEM_FLOATS * (int)sizeof(float));

    down_proj_kernel<<<BS_/32, 256>>>(h, Wdq, bdq, Wdkv, bdkv, Wkr, bkr);
    up_proj_kernel<<<dim3(14, BS_/64), 256>>>(Wuq, buq, Wuk, buk, Wuv, buv, Wqr, bqr);
    attn_kernel<<<dim3(S_/128, B_*H_), 256, ATTN_SMEM_FLOATS * sizeof(float)>>>();
    out_proj_kernel<<<dim3(DM/128, BS_/128), 256>>>(Wo, bo, out);
}

// round 5
// speedup vs baseline: 3.4810x; 1.1235x over previous
#include <cuda_runtime.h>
#include <math.h>
#include <stdint.h>

#define B_   4
#define S_   2048
#define DM   1024
#define H_   8
#define DK   128
#define DC   32
#define DHR  32
#define DQK  160            // DK + DHR
#define BS_  (B_*S_)        // 8192

// ---------------- scratch (device globals; no allocations allowed) ----------
__device__ float g_cq [BS_*DC];
__device__ float g_ckv[BS_*DC];
__device__ float g_kr [BS_*DC];
__device__ float g_q[(size_t)B_*H_*S_*DQK];   // [B,H,S,160]  (tf32-rounded)
__device__ float g_k[(size_t)B_*H_*S_*DQK];   // [B,H,S,160]  (tf32-rounded)
__device__ float g_v[(size_t)B_*H_*S_*DK];    // [B,H,S,128]  (tf32-rounded)
__device__ float g_o[(size_t)BS_*H_*DK];      // [B,S,H*128]  (tf32-rounded)

// ---------------- helpers ----------------------------------------------------
__device__ __forceinline__ float to_tf32(float x) {
    uint32_t u;
    asm("cvt.rna.tf32.f32 %0, %1;" : "=r"(u) : "f"(x));
    return __uint_as_float(u);
}

__device__ __forceinline__ void mma_tf32(float* d, const float* a, const float* b) {
    asm("mma.sync.aligned.m16n8k8.row.col.f32.tf32.tf32.f32 "
        "{%0,%1,%2,%3}, {%4,%5,%6,%7}, {%8,%9}, {%0,%1,%2,%3};"
        : "+f"(d[0]), "+f"(d[1]), "+f"(d[2]), "+f"(d[3])
        : "r"(__float_as_uint(a[0])), "r"(__float_as_uint(a[1])),
          "r"(__float_as_uint(a[2])), "r"(__float_as_uint(a[3])),
          "r"(__float_as_uint(b[0])), "r"(__float_as_uint(b[1])));
}

__device__ __forceinline__ void cp_async16(uint32_t saddr, const void* gptr) {
    asm volatile("cp.async.cg.shared.global [%0], [%1], 16;"
                 :: "r"(saddr), "l"(gptr));
}
#define CP_COMMIT()  asm volatile("cp.async.commit_group;")
#define CP_WAIT1()   asm volatile("cp.async.wait_group 1;")

// ---------------------------------------------------------------------------
// Kernel 1: down projections
// ---------------------------------------------------------------------------
__global__ void __launch_bounds__(256) down_proj_kernel(
    const float* __restrict__ h,
    const float* __restrict__ Wdq,  const float* __restrict__ bdq,
    const float* __restrict__ Wdkv, const float* __restrict__ bdkv,
    const float* __restrict__ Wkr,  const float* __restrict__ bkr)
{
    __shared__ float h_s[32*64];
    __shared__ float w_s[64*96];
    const int tid  = threadIdx.x;
    const int row0 = blockIdx.x * 32;
    const int ty = tid >> 5, tx = tid & 31;

    float acc[4][3];
#pragma unroll
    for (int i = 0; i < 4; i++)
#pragma unroll
        for (int j = 0; j < 3; j++) acc[i][j] = 0.f;

    for (int kc = 0; kc < 16; kc++) {
        __syncthreads();
#pragma unroll
        for (int i = 0; i < 2; i++) {
            int idx4 = tid + i*256;
            int r = idx4 >> 4, c4 = idx4 & 15;
            float4 v = *(const float4*)(h + (size_t)(row0+r)*DM + kc*64 + c4*4);
            *(float4*)(h_s + r*64 + c4*4) = v;
        }
#pragma unroll
        for (int i = 0; i < 24; i++) {
            int idx = tid + i*256;
            int k = idx / 96, c = idx - k*96;
            int gk = kc*64 + k;
            float w;
            if (c < 32)      w = Wdq [gk*32 + c];
            else if (c < 64) w = Wdkv[gk*32 + (c-32)];
            else             w = Wkr [gk*32 + (c-64)];
            w_s[k*96 + c] = w;
        }
        __syncthreads();
#pragma unroll 8
        for (int kk = 0; kk < 64; kk++) {
            float a0 = h_s[(ty*4+0)*64 + kk];
            float a1 = h_s[(ty*4+1)*64 + kk];
            float a2 = h_s[(ty*4+2)*64 + kk];
            float a3 = h_s[(ty*4+3)*64 + kk];
            float b0 = w_s[kk*96 + tx];
            float b1 = w_s[kk*96 + tx + 32];
            float b2 = w_s[kk*96 + tx + 64];
            acc[0][0] += a0*b0; acc[0][1] += a0*b1; acc[0][2] += a0*b2;
            acc[1][0] += a1*b0; acc[1][1] += a1*b1; acc[1][2] += a1*b2;
            acc[2][0] += a2*b0; acc[2][1] += a2*b1; acc[2][2] += a2*b2;
            acc[3][0] += a3*b0; acc[3][1] += a3*b1; acc[3][2] += a3*b2;
        }
    }
#pragma unroll
    for (int i = 0; i < 4; i++) {
        int row = row0 + ty*4 + i;
        g_cq [row*32 + tx] = acc[i][0] + bdq [tx];
        g_ckv[row*32 + tx] = acc[i][1] + bdkv[tx];
        g_kr [row*32 + tx] = acc[i][2] + bkr [tx];
    }
}

// ---------------------------------------------------------------------------
// Kernel 2: up projections (K=32). Outputs tf32-rounded (rna) for the mma stages.
// ---------------------------------------------------------------------------
__global__ void __launch_bounds__(256) up_proj_kernel(
    const float* __restrict__ Wuq, const float* __restrict__ buq,
    const float* __restrict__ Wuk, const float* __restrict__ buk,
    const float* __restrict__ Wuv, const float* __restrict__ buv,
    const float* __restrict__ Wqr, const float* __restrict__ bqr)
{
    __shared__ float w_s[32*256];
    __shared__ float c_s[64*32];
    __shared__ float bias_s[256];

    const int tid  = threadIdx.x;
    const int ct   = blockIdx.x;
    const int row0 = blockIdx.y * 64;

    if (ct == 13) {
        int hh = tid >> 5, c = tid & 31;
        for (int r = 0; r < 64; r++) {
            int row = row0 + r;
            int bb = row >> 11, ss = row & 2047;
            float v = to_tf32(g_kr[row*32 + c]);          // rna round
            g_k[((size_t)(bb*H_ + hh)*S_ + ss)*DQK + 128 + c] = v;
        }
        return;
    }

    const float *W, *bias, *src;
    int colbase, Wn, dest;
    if (ct < 4)      { W=Wuq; bias=buq; src=g_cq;  colbase=ct*256;     Wn=1024; dest=0; }
    else if (ct==4)  { W=Wqr; bias=bqr; src=g_cq;  colbase=0;          Wn=256;  dest=1; }
    else if (ct < 9) { W=Wuk; bias=buk; src=g_ckv; colbase=(ct-5)*256; Wn=1024; dest=2; }
    else             { W=Wuv; bias=buv; src=g_ckv; colbase=(ct-9)*256; Wn=1024; dest=3; }

#pragma unroll
    for (int k = 0; k < 32; k++) w_s[k*256 + tid] = W[k*Wn + colbase + tid];
    bias_s[tid] = bias[colbase + tid];
#pragma unroll
    for (int i = 0; i < 8; i++) {
        int idx = tid + i*256;
        c_s[idx] = src[row0*32 + idx];
    }
    __syncthreads();

    const int gcol = colbase + tid;
    for (int r = 0; r < 64; r++) {
        float acc = bias_s[tid];
#pragma unroll
        for (int k = 0; k < 32; k++) acc += c_s[r*32 + k] * w_s[k*256 + tid];
        acc = to_tf32(acc);                               // rna round at store
        int row = row0 + r;
        int bb = row >> 11, ss = row & 2047;
        if (dest == 0) {
            int hh = gcol >> 7, d = gcol & 127;
            g_q[((size_t)(bb*H_ + hh)*S_ + ss)*DQK + d] = acc;
        } else if (dest == 1) {
            int hh = gcol >> 5, d = gcol & 31;
            g_q[((size_t)(bb*H_ + hh)*S_ + ss)*DQK + 128 + d] = acc;
        } else if (dest == 2) {
            int hh = gcol >> 7, d = gcol & 127;
            g_k[((size_t)(bb*H_ + hh)*S_ + ss)*DQK + d] = acc;
        } else {
            int hh = gcol >> 7, d = gcol & 127;
            g_v[((size_t)(bb*H_ + hh)*S_ + ss)*DK + d] = acc;
        }
    }
}

// ---------------------------------------------------------------------------
// Kernel 3: flash attention, tf32 mma, cp.async double-buffered K/V,
// Q fragments in registers. K/V arrive pre-rounded from gmem.
// ---------------------------------------------------------------------------
#define SKS 164          // K row stride (164%32==4)
#define SVS 136          // V row stride (136%32==8)
#define SPS 68           // P row stride (68%32==4)
#define KBUF_FL 10496    // 64*164
#define VBUF_FL 8704     // 64*136
#define ATTN_SMEM_FLOATS (2*KBUF_FL + 2*VBUF_FL + 128*SPS)

__global__ void __launch_bounds__(256, 1) attn_kernel()
{
    extern __shared__ float sm[];
    float* kbuf = sm;                         // 2 x 64x164 (Q staging uses both)
    float* vbuf = sm + 2*KBUF_FL;             // 2 x 64x136
    float* p_s  = vbuf + 2*VBUF_FL;           // 128x68
    const uint32_t smb = (uint32_t)__cvta_generic_to_shared(sm);

    const int tid  = threadIdx.x;
    const int lane = tid & 31;
    const int warp = tid >> 5;
    const int gid  = lane >> 2;
    const int tig  = lane & 3;
    const int bh   = blockIdx.y;
    const int q0   = blockIdx.x * 128;

    const float* qg = g_q + ((size_t)bh*S_ + q0)*DQK;
    const float* kg = g_k + (size_t)bh*S_*DQK;
    const float* vg = g_v + (size_t)bh*S_*DK;

    const float scale = 0.07905694150420948f;  // 1/sqrt(160)

    // ---- stage FULL 128-row Q tile (128*164 = 2*KBUF_FL) ----
#pragma unroll
    for (int i = 0; i < 20; i++) {
        int idx4 = tid + i*256;
        int r = idx4 / 40, c4 = idx4 - r*40;
        float4 v = *(const float4*)(qg + (size_t)r*DQK + c4*4);
        *(float4*)(kbuf + r*SKS + c4*4) = v;
    }
    __syncthreads();

    const int r0 = warp*16 + gid;
    float qf[20][4];
#pragma unroll
    for (int kb = 0; kb < 20; kb++) {
        int c0 = kb*8 + tig;
        qf[kb][0] = kbuf[ r0    *SKS + c0    ];
        qf[kb][1] = kbuf[(r0+8) *SKS + c0    ];
        qf[kb][2] = kbuf[ r0    *SKS + c0 + 4];
        qf[kb][3] = kbuf[(r0+8) *SKS + c0 + 4];
    }
    __syncthreads();

    auto issue_kv = [&](int s, int t) {
        const float* ksrc = kg + (size_t)t*64*DQK;
        const float* vsrc = vg + (size_t)t*64*DK;
        const uint32_t kdst0 = smb + (uint32_t)(s*KBUF_FL)*4u;
        const uint32_t vdst0 = smb + (uint32_t)(2*KBUF_FL + s*VBUF_FL)*4u;
#pragma unroll
        for (int i = 0; i < 10; i++) {
            int idx4 = tid + i*256;
            int r = idx4 / 40, c4 = idx4 - r*40;
            cp_async16(kdst0 + (uint32_t)(r*SKS + c4*4)*4u,
                       ksrc + (size_t)r*DQK + c4*4);
        }
#pragma unroll
        for (int i = 0; i < 8; i++) {
            int idx4 = tid + i*256;
            int r = idx4 >> 5, c4 = idx4 & 31;
            cp_async16(vdst0 + (uint32_t)(r*SVS + c4*4)*4u,
                       vsrc + (size_t)r*DK + c4*4);
        }
    };

    issue_kv(0, 0); CP_COMMIT();
    issue_kv(1, 1); CP_COMMIT();

    float m0 = -1e30f, m1 = -1e30f, l0 = 0.f, l1 = 0.f;
    float o[16][4];
#pragma unroll
    for (int i = 0; i < 16; i++)
#pragma unroll
        for (int j = 0; j < 4; j++) o[i][j] = 0.f;

    for (int kt = 0; kt < S_/64; kt++) {
        const int cur = kt & 1;
        CP_WAIT1();
        __syncthreads();
        const float* ks = kbuf + cur*KBUF_FL;
        const float* vs = vbuf + cur*VBUF_FL;

        // ---- S = Q K^T ----
        float sa[8][4];
#pragma unroll
        for (int n = 0; n < 8; n++)
#pragma unroll
            for (int j = 0; j < 4; j++) sa[n][j] = 0.f;

#pragma unroll
        for (int kb = 0; kb < 20; kb++) {
            const int c0 = kb*8 + tig;
#pragma unroll
            for (int nt = 0; nt < 8; nt++) {
                const int kr = nt*8 + gid;
                float b[2];
                b[0] = ks[kr*SKS + c0    ];
                b[1] = ks[kr*SKS + c0 + 4];
                mma_tf32(sa[nt], qf[kb], b);
            }
        }

        // ---- online softmax (scale folded into exp) ----
        float mx0 = -1e30f, mx1 = -1e30f;
#pragma unroll
        for (int n = 0; n < 8; n++) {
            mx0 = fmaxf(mx0, fmaxf(sa[n][0], sa[n][1]));
            mx1 = fmaxf(mx1, fmaxf(sa[n][2], sa[n][3]));
        }
        mx0 = fmaxf(mx0, __shfl_xor_sync(0xffffffffu, mx0, 1));
        mx0 = fmaxf(mx0, __shfl_xor_sync(0xffffffffu, mx0, 2));
        mx1 = fmaxf(mx1, __shfl_xor_sync(0xffffffffu, mx1, 1));
        mx1 = fmaxf(mx1, __shfl_xor_sync(0xffffffffu, mx1, 2));

        float nm0 = fmaxf(m0, mx0), nm1 = fmaxf(m1, mx1);
        float al0 = __expf((m0 - nm0)*scale), al1 = __expf((m1 - nm1)*scale);
        m0 = nm0; m1 = nm1;

        float rs0 = 0.f, rs1 = 0.f;
#pragma unroll
        for (int n = 0; n < 8; n++) {
            float p00 = __expf((sa[n][0] - nm0)*scale);
            float p01 = __expf((sa[n][1] - nm0)*scale);
            float p10 = __expf((sa[n][2] - nm1)*scale);
            float p11 = __expf((sa[n][3] - nm1)*scale);
            rs0 += p00 + p01; rs1 += p10 + p11;
            *(float2*)(p_s +  r0   *SPS + n*8 + 2*tig) =
                make_float2(to_tf32(p00), to_tf32(p01));
            *(float2*)(p_s + (r0+8)*SPS + n*8 + 2*tig) =
                make_float2(to_tf32(p10), to_tf32(p11));
        }
        rs0 += __shfl_xor_sync(0xffffffffu, rs0, 1);
        rs0 += __shfl_xor_sync(0xffffffffu, rs0, 2);
        rs1 += __shfl_xor_sync(0xffffffffu, rs1, 1);
        rs1 += __shfl_xor_sync(0xffffffffu, rs1, 2);
        l0 = l0*al0 + rs0; l1 = l1*al1 + rs1;

#pragma unroll
        for (int n = 0; n < 16; n++) {
            o[n][0] *= al0; o[n][1] *= al0;
            o[n][2] *= al1; o[n][3] *= al1;
        }
        __syncwarp();

        // ---- O += P V ----
#pragma unroll
        for (int kb = 0; kb < 8; kb++) {
            const int c0 = kb*8 + tig;
            float a[4];
            a[0] = p_s[ r0    *SPS + c0    ];
            a[1] = p_s[(r0+8) *SPS + c0    ];
            a[2] = p_s[ r0    *SPS + c0 + 4];
            a[3] = p_s[(r0+8) *SPS + c0 + 4];
#pragma unroll
            for (int nt = 0; nt < 16; nt++) {
                float b[2];
                b[0] = vs[(kb*8 + tig    )*SVS + nt*8 + gid];
                b[1] = vs[(kb*8 + tig + 4)*SVS + nt*8 + gid];
                mma_tf32(o[nt], a, b);
            }
        }
        __syncthreads();

        if (kt + 2 < S_/64) issue_kv(cur, kt + 2);
        CP_COMMIT();
    }

    // ---- epilogue (rna-rounded for the out_proj mma A operand) ----
    const int bb = bh >> 3, hh = bh & 7;
    const float inv0 = 1.f / l0, inv1 = 1.f / l1;
    const int s0 = q0 + r0;
    float* op0 = g_o + ((size_t)(bb*S_ + s0    )*H_ + hh)*DK;
    float* op1 = g_o + ((size_t)(bb*S_ + s0 + 8)*H_ + hh)*DK;
#pragma unroll
    for (int nt = 0; nt < 16; nt++) {
        int col = nt*8 + 2*tig;
        *(float2*)(op0 + col) = make_float2(to_tf32(o[nt][0]*inv0), to_tf32(o[nt][1]*inv0));
        *(float2*)(op1 + col) = make_float2(to_tf32(o[nt][2]*inv1), to_tf32(o[nt][3]*inv1));
    }
}

// ---------------------------------------------------------------------------
// Kernel 4: out = g_o @ W_O + b_O, tf32 mma, cp.async double-buffered.
// A is pre-rounded in gmem; B (Wo) fragments rounded rna in-register.
// ---------------------------------------------------------------------------
#define SA 36     // a stride (36%32==4)
#define SB 136    // b stride (136%32==8)
#define ABUF_FL (128*SA)   // 4608
#define BBUF_FL (32*SB)    // 4352
#define OUT_SMEM_FLOATS (2*ABUF_FL + 2*BBUF_FL)

__global__ void __launch_bounds__(256) out_proj_kernel(
    const float* __restrict__ Wo, const float* __restrict__ bo,
    float* __restrict__ out)
{
    extern __shared__ float sm[];
    float* a_s = sm;
    float* b_s = sm + 2*ABUF_FL;
    const uint32_t smb = (uint32_t)__cvta_generic_to_shared(sm);

    const int tid  = threadIdx.x;
    const int lane = tid & 31;
    const int warp = tid >> 5;
    const int gid  = lane >> 2, tig = lane & 3;
    const int wm = warp >> 1, wn = warp & 1;
    const int col0 = blockIdx.x * 128;
    const int row0 = blockIdx.y * 128;

    auto issue_ab = [&](int s, int kc) {
        const uint32_t adst = smb + (uint32_t)(s*ABUF_FL)*4u;
        const uint32_t bdst = smb + (uint32_t)(2*ABUF_FL + s*BBUF_FL)*4u;
#pragma unroll
        for (int i = 0; i < 4; i++) {
            int idx4 = tid + i*256;
            int r = idx4 >> 3, c4 = idx4 & 7;
            cp_async16(adst + (uint32_t)(r*SA + c4*4)*4u,
                       g_o + (size_t)(row0+r)*DM + kc*32 + c4*4);
        }
#pragma unroll
        for (int i = 0; i < 4; i++) {
            int idx4 = tid + i*256;
            int r = idx4 >> 5, c4 = idx4 & 31;
            cp_async16(bdst + (uint32_t)(r*SB + c4*4)*4u,
                       Wo + (size_t)(kc*32+r)*DM + col0 + c4*4);
        }
    };

    float acc[2][8][4];
#pragma unroll
    for (int im = 0; im < 2; im++)
#pragma unroll
        for (int n = 0; n < 8; n++)
#pragma unroll
            for (int j = 0; j < 4; j++) acc[im][n][j] = 0.f;

    issue_ab(0, 0); CP_COMMIT();
    issue_ab(1, 1); CP_COMMIT();

    for (int kc = 0; kc < 32; kc++) {
        const int cur = kc & 1;
        CP_WAIT1();
        __syncthreads();
        const float* ap = a_s + cur*ABUF_FL;
        const float* bp = b_s + cur*BBUF_FL;

#pragma unroll
        for (int ks = 0; ks < 4; ks++) {
            const int c0 = ks*8 + tig;
            float a0[4], a1[4];
            int ra = wm*32 + gid;
            a0[0] = ap[ ra      *SA + c0    ];
            a0[1] = ap[(ra+8)   *SA + c0    ];
            a0[2] = ap[ ra      *SA + c0 + 4];
            a0[3] = ap[(ra+8)   *SA + c0 + 4];
            a1[0] = ap[(ra+16)  *SA + c0    ];
            a1[1] = ap[(ra+24)  *SA + c0    ];
            a1[2] = ap[(ra+16)  *SA + c0 + 4];
            a1[3] = ap[(ra+24)  *SA + c0 + 4];
#pragma unroll
            for (int nt = 0; nt < 8; nt++) {
                float b[2];
                int nb = wn*64 + nt*8 + gid;
                b[0] = to_tf32(bp[(ks*8 + tig    )*SB + nb]);   // rna round B
                b[1] = to_tf32(bp[(ks*8 + tig + 4)*SB + nb]);
                mma_tf32(acc[0][nt], a0, b);
                mma_tf32(acc[1][nt], a1, b);
            }
        }
        __syncthreads();
        if (kc + 2 < 32) issue_ab(cur, kc + 2);
        CP_COMMIT();
    }

#pragma unroll
    for (int im = 0; im < 2; im++) {
        int rr = row0 + wm*32 + im*16 + gid;
#pragma unroll
        for (int nt = 0; nt < 8; nt++) {
            int cc = col0 + wn*64 + nt*8 + 2*tig;
            float bx = bo[cc], by = bo[cc+1];
            *(float2*)(out + (size_t)rr*DM + cc) =
                make_float2(acc[im][nt][0] + bx, acc[im][nt][1] + by);
            *(float2*)(out + (size_t)(rr+8)*DM + cc) =
                make_float2(acc[im][nt][2] + bx, acc[im][nt][3] + by);
        }
    }
}

// ---------------------------------------------------------------------------
extern "C" void kernel_launch(void* const* d_in, const int* in_sizes, int n_in,
                              void* d_out, int out_size)
{
    (void)in_sizes; (void)n_in; (void)out_size;
    const float* h    = (const float*)d_in[0];
    const float* Wdq  = (const float*)d_in[1];
    const float* bdq  = (const float*)d_in[2];
    const float* Wuq  = (const float*)d_in[3];
    const float* buq  = (const float*)d_in[4];
    const float* Wdkv = (const float*)d_in[5];
    const float* bdkv = (const float*)d_in[6];
    const float* Wuk  = (const float*)d_in[7];
    const float* buk  = (const float*)d_in[8];
    const float* Wuv  = (const float*)d_in[9];
    const float* buv  = (const float*)d_in[10];
    const float* Wqr  = (const float*)d_in[11];
    const float* bqr  = (const float*)d_in[12];
    const float* Wkr  = (const float*)d_in[13];
    const float* bkr  = (const float*)d_in[14];
    const float* Wo   = (const float*)d_in[15];
    const float* bo   = (const float*)d_in[16];
    float* out = (float*)d_out;

    cudaFuncSetAttribute(attn_kernel, cudaFuncAttributeMaxDynamicSharedMemorySize,
                         ATTN_SMEM_FLOATS * (int)sizeof(float));
    cudaFuncSetAttribute(out_proj_kernel, cudaFuncAttributeMaxDynamicSharedMemorySize,
                         OUT_SMEM_FLOATS * (int)sizeof(float));

    down_proj_kernel<<<BS_/32, 256>>>(h, Wdq, bdq, Wdkv, bdkv, Wkr, bkr);
    up_proj_kernel<<<dim3(14, BS_/64), 256>>>(Wuq, buq, Wuk, buk, Wuv, buv, Wqr, bqr);
    attn_kernel<<<dim3(S_/128, B_*H_), 256, ATTN_SMEM_FLOATS * sizeof(float)>>>();
    out_proj_kernel<<<dim3(DM/128, BS_/128), 256, OUT_SMEM_FLOATS * sizeof(float)>>>(Wo, bo, out);
}

// round 8
// speedup vs baseline: 5.4367x; 1.5619x over previous
#include <cuda_runtime.h>
#include <math.h>
#include <stdint.h>

#define B_   4
#define S_   2048
#define DM   1024
#define H_   8
#define DK   128
#define DC   32
#define DHR  32
#define BS_  (B_*S_)        // 8192

// ---------------- scratch (device globals) ----------------------------------
__device__ float g_cq  [BS_*DC];            // fp32
__device__ float g_ckv [BS_*DC];            // tf32-rounded (PV C operand)
__device__ float g_kt  [BS_*64];            // K~ = [ckv|kr], natural order, rounded
__device__ float g_qt  [(size_t)B_*H_*S_*64];  // Q~ = [q~|q_r], natural, rounded
__device__ float g_ot  [(size_t)BS_*H_*32];    // O~ [B,S,H*32], rounded
__device__ float g_M   [H_*DC*DC];          // M_h[c][i] fp32
__device__ float g_m   [H_*DC];             // m_h fp32
__device__ float g_weff[256*DM];            // W_eff [(h*32+i)][j], rounded
__device__ float g_beff[DM];                // fp32

// ---------------- helpers ----------------------------------------------------
__device__ __forceinline__ float to_tf32(float x) {
    uint32_t u;
    asm("cvt.rna.tf32.f32 %0, %1;" : "=r"(u) : "f"(x));
    return __uint_as_float(u);
}
__device__ __forceinline__ void mma_tf32(float* d, const float* a, const float* b) {
    asm("mma.sync.aligned.m16n8k8.row.col.f32.tf32.tf32.f32 "
        "{%0,%1,%2,%3}, {%4,%5,%6,%7}, {%8,%9}, {%0,%1,%2,%3};"
        : "+f"(d[0]), "+f"(d[1]), "+f"(d[2]), "+f"(d[3])
        : "r"(__float_as_uint(a[0])), "r"(__float_as_uint(a[1])),
          "r"(__float_as_uint(a[2])), "r"(__float_as_uint(a[3])),
          "r"(__float_as_uint(b[0])), "r"(__float_as_uint(b[1])));
}
__device__ __forceinline__ void cp_async16(uint32_t saddr, const void* gptr) {
    asm volatile("cp.async.cg.shared.global [%0], [%1], 16;"
                 :: "r"(saddr), "l"(gptr));
}
#define CP_COMMIT()  asm volatile("cp.async.commit_group;")
#define CP_WAIT1()   asm volatile("cp.async.wait_group 1;")

// ---------------------------------------------------------------------------
// Prep A: M_h[c][i] = sum_d W_UQ[c][h*128+d]*W_UK[i][h*128+d];  m_h from b_UQ
// ---------------------------------------------------------------------------
__global__ void __launch_bounds__(256) prep_M_kernel(
    const float* __restrict__ Wuq, const float* __restrict__ buq,
    const float* __restrict__ Wuk)
{
    const int h = blockIdx.x;
    const int tid = threadIdx.x;
    for (int idx = tid; idx < DC*DC; idx += 256) {
        int c = idx >> 5, i = idx & 31;
        float s = 0.f;
        const float* wq = Wuq + c*DM + h*DK;
        const float* wk = Wuk + i*DM + h*DK;
#pragma unroll 8
        for (int d = 0; d < DK; d++) s += wq[d]*wk[d];
        g_M[h*DC*DC + idx] = s;
    }
    if (tid < DC) {
        float s = 0.f;
        const float* wk = Wuk + tid*DM + h*DK;
#pragma unroll 8
        for (int d = 0; d < DK; d++) s += buq[h*DK + d]*wk[d];
        g_m[h*DC + tid] = s;
    }
}

// ---------------------------------------------------------------------------
// Prep B: blocks 0..63: W_eff[(h*32+i)][j] = sum_d W_UV[i][h*128+d]*W_O[h*128+d][j]
//         blocks 64..67: b_eff[j] = b_O[j] + sum_k b_UV[k]*W_O[k][j]
// ---------------------------------------------------------------------------
__global__ void __launch_bounds__(256) prep_weff_kernel(
    const float* __restrict__ Wuv, const float* __restrict__ buv,
    const float* __restrict__ Wo,  const float* __restrict__ bo)
{
    const int tid = threadIdx.x;
    if (blockIdx.x >= 64) {
        int j = (blockIdx.x - 64)*256 + tid;
        float acc = bo[j];
        for (int k = 0; k < DM; k++) acc += buv[k]*Wo[(size_t)k*DM + j];
        g_beff[j] = acc;
        return;
    }
    const int h = blockIdx.x >> 3, jt = blockIdx.x & 7;
    const int i = tid >> 3, jg = tid & 7;
    const int j0 = jt*128 + jg*16;
    float acc[16];
#pragma unroll
    for (int k = 0; k < 16; k++) acc[k] = 0.f;
    for (int d = 0; d < DK; d++) {
        float wuv = Wuv[i*DM + h*DK + d];
        const float* wo = Wo + (size_t)(h*DK + d)*DM + j0;
#pragma unroll
        for (int k = 0; k < 16; k++) acc[k] += wuv*wo[k];
    }
#pragma unroll
    for (int k = 0; k < 16; k++)
        g_weff[(size_t)(h*32 + i)*DM + j0 + k] = to_tf32(acc[k]);
}

// ---------------------------------------------------------------------------
// Kernel 1: down projections -> c_q, c_kv (rounded), K~ (natural, rounded)
// ---------------------------------------------------------------------------
__global__ void __launch_bounds__(256) down_proj_kernel(
    const float* __restrict__ h,
    const float* __restrict__ Wdq,  const float* __restrict__ bdq,
    const float* __restrict__ Wdkv, const float* __restrict__ bdkv,
    const float* __restrict__ Wkr,  const float* __restrict__ bkr)
{
    __shared__ float h_s[32*64];
    __shared__ float w_s[64*96];
    const int tid  = threadIdx.x;
    const int row0 = blockIdx.x * 32;
    const int ty = tid >> 5, tx = tid & 31;

    float acc[4][3];
#pragma unroll
    for (int i = 0; i < 4; i++)
#pragma unroll
        for (int j = 0; j < 3; j++) acc[i][j] = 0.f;

    for (int kc = 0; kc < 16; kc++) {
        __syncthreads();
#pragma unroll
        for (int i = 0; i < 2; i++) {
            int idx4 = tid + i*256;
            int r = idx4 >> 4, c4 = idx4 & 15;
            float4 v = *(const float4*)(h + (size_t)(row0+r)*DM + kc*64 + c4*4);
            *(float4*)(h_s + r*64 + c4*4) = v;
        }
#pragma unroll
        for (int i = 0; i < 24; i++) {
            int idx = tid + i*256;
            int k = idx / 96, c = idx - k*96;
            int gk = kc*64 + k;
            float w;
            if (c < 32)      w = Wdq [gk*32 + c];
            else if (c < 64) w = Wdkv[gk*32 + (c-32)];
            else             w = Wkr [gk*32 + (c-64)];
            w_s[k*96 + c] = w;
        }
        __syncthreads();
#pragma unroll 8
        for (int kk = 0; kk < 64; kk++) {
            float a0 = h_s[(ty*4+0)*64 + kk];
            float a1 = h_s[(ty*4+1)*64 + kk];
            float a2 = h_s[(ty*4+2)*64 + kk];
            float a3 = h_s[(ty*4+3)*64 + kk];
            float b0 = w_s[kk*96 + tx];
            float b1 = w_s[kk*96 + tx + 32];
            float b2 = w_s[kk*96 + tx + 64];
            acc[0][0] += a0*b0; acc[0][1] += a0*b1; acc[0][2] += a0*b2;
            acc[1][0] += a1*b0; acc[1][1] += a1*b1; acc[1][2] += a1*b2;
            acc[2][0] += a2*b0; acc[2][1] += a2*b1; acc[2][2] += a2*b2;
            acc[3][0] += a3*b0; acc[3][1] += a3*b1; acc[3][2] += a3*b2;
        }
    }
#pragma unroll
    for (int i = 0; i < 4; i++) {
        int row = row0 + ty*4 + i;
        float cq  = acc[i][0] + bdq [tx];
        float ckv = to_tf32(acc[i][1] + bdkv[tx]);
        float kr  = to_tf32(acc[i][2] + bkr [tx]);
        g_cq [row*32 + tx] = cq;
        g_ckv[row*32 + tx] = ckv;
        g_kt [row*64 + tx]      = ckv;
        g_kt [row*64 + 32 + tx] = kr;
    }
}

// ---------------------------------------------------------------------------
// Kernel 2: Q~[b,h,s,64] = [c_q@M_h+m_h | c_q@W_QR_h+b_QR_h], natural order
// ---------------------------------------------------------------------------
__global__ void __launch_bounds__(256) q_proj_kernel(
    const float* __restrict__ Wqr, const float* __restrict__ bqr)
{
    __shared__ float w_s[32*64];
    __shared__ float c_s[64*32];
    __shared__ float bias_s[64];

    const int tid  = threadIdx.x;
    const int hh   = blockIdx.y;
    const int row0 = blockIdx.x * 64;

#pragma unroll
    for (int i = 0; i < 8; i++) {
        int idx = tid + i*256;
        int k = idx >> 6, c = idx & 63;
        w_s[idx] = (c < 32) ? g_M[hh*DC*DC + k*32 + c]
                            : Wqr[k*256 + hh*32 + (c-32)];
    }
    if (tid < 64)
        bias_s[tid] = (tid < 32) ? g_m[hh*DC + tid] : bqr[hh*32 + tid - 32];
#pragma unroll
    for (int i = 0; i < 8; i++) {
        int idx = tid + i*256;
        c_s[idx] = g_cq[row0*32 + idx];
    }
    __syncthreads();

    const int col = tid & 63, rg = tid >> 6;
    for (int rr = 0; rr < 16; rr++) {
        int r = rg*16 + rr;
        float acc = bias_s[col];
#pragma unroll
        for (int k = 0; k < 32; k++) acc += c_s[r*32 + k]*w_s[k*64 + col];
        int row = row0 + r;
        int bb = row >> 11, ss = row & 2047;
        g_qt[((size_t)(bb*H_ + hh)*S_ + ss)*64 + col] = to_tf32(acc);
    }
}

// ---------------------------------------------------------------------------
// Kernel 3: absorbed flash attention. Q~ 128x64, K~ 64x64 (head-shared),
// C = c_kv 64x32. tf32 mma, cp.async double buffer, full tile fill (FIXED).
// ---------------------------------------------------------------------------
#define SKT 68            // K~ stride (68%32==4); 68*4=272 bytes, 16B-multiple
#define SCT 40            // C stride  (40%32==8); 160 bytes, 16B-multiple
#define SPT 68            // P / Q-staging stride
#define KT_FL (64*SKT)    // 4352
#define CT_FL (64*SCT)    // 2560
#define ATTN_SMEM_FLOATS (2*KT_FL + 2*CT_FL + 128*SPT)   // 22528 fl = 90112 B

__global__ void __launch_bounds__(256, 2) attn_kernel()
{
    extern __shared__ float sm[];
    float* kbuf = sm;                     // 2 x 64x68
    float* cbuf = sm + 2*KT_FL;           // 2 x 64x40
    float* p_s  = cbuf + 2*CT_FL;         // 128x68  (also Q staging)
    const uint32_t smb = (uint32_t)__cvta_generic_to_shared(sm);

    const int tid  = threadIdx.x;
    const int lane = tid & 31;
    const int warp = tid >> 5;
    const int gid  = lane >> 2;
    const int tig  = lane & 3;
    const int bh   = blockIdx.y;          // b*8+h
    const int bb   = bh >> 3, hh = bh & 7;
    const int q0   = blockIdx.x * 128;

    const float* qg = g_qt + ((size_t)bh*S_ + q0)*64;
    const float* kg = g_kt + (size_t)bb*S_*64;
    const float* cg = g_ckv + (size_t)bb*S_*32;

    const float scale = 0.07905694150420948f;  // 1/sqrt(160)

    // ---- stage Q~ (128x64) into p_s, lift fragments ----
#pragma unroll
    for (int i = 0; i < 8; i++) {
        int idx4 = tid + i*256;
        int r = idx4 >> 4, c4 = idx4 & 15;
        float4 v = *(const float4*)(qg + (size_t)r*64 + c4*4);
        *(float4*)(p_s + r*SPT + c4*4) = v;
    }
    __syncthreads();

    const int r0 = warp*16 + gid;
    float qf[8][4];
#pragma unroll
    for (int kb = 0; kb < 8; kb++) {
        int c0 = kb*8 + tig;
        qf[kb][0] = p_s[ r0    *SPT + c0    ];
        qf[kb][1] = p_s[(r0+8) *SPT + c0    ];
        qf[kb][2] = p_s[ r0    *SPT + c0 + 4];
        qf[kb][3] = p_s[(r0+8) *SPT + c0 + 4];
    }

    auto issue_kv = [&](int s, int t) {
        const float* ksrc = kg + (size_t)t*64*64;
        const float* csrc = cg + (size_t)t*64*32;
        const uint32_t kdst = smb + (uint32_t)(s*KT_FL)*4u;
        const uint32_t cdst = smb + (uint32_t)(2*KT_FL + s*CT_FL)*4u;
        // K~: 64 rows x 16 float4 = 1024 chunks -> 4 per thread  (FIX)
#pragma unroll
        for (int i = 0; i < 4; i++) {
            int idx4 = tid + i*256;
            int r = idx4 >> 4, c4 = idx4 & 15;
            cp_async16(kdst + (uint32_t)(r*SKT + c4*4)*4u, ksrc + r*64 + c4*4);
        }
        // C: 64 rows x 8 float4 = 512 chunks -> 2 per thread     (FIX)
#pragma unroll
        for (int i = 0; i < 2; i++) {
            int idx4 = tid + i*256;
            int r = idx4 >> 3, c4 = idx4 & 7;
            cp_async16(cdst + (uint32_t)(r*SCT + c4*4)*4u, csrc + r*32 + c4*4);
        }
    };

    issue_kv(0, 0); CP_COMMIT();
    issue_kv(1, 1); CP_COMMIT();

    float m0 = -1e30f, m1 = -1e30f, l0 = 0.f, l1 = 0.f;
    float o[4][4];
#pragma unroll
    for (int i = 0; i < 4; i++)
#pragma unroll
        for (int j = 0; j < 4; j++) o[i][j] = 0.f;

    for (int kt = 0; kt < S_/64; kt++) {
        const int cur = kt & 1;
        CP_WAIT1();
        __syncthreads();            // orders qf-lift reads before P stores too
        const float* ks = kbuf + cur*KT_FL;
        const float* cs = cbuf + cur*CT_FL;

        // ---- S = Q~ K~^T (64-dim contraction) ----
        float sa[8][4];
#pragma unroll
        for (int n = 0; n < 8; n++)
#pragma unroll
            for (int j = 0; j < 4; j++) sa[n][j] = 0.f;

#pragma unroll
        for (int kb = 0; kb < 8; kb++) {
            const int c0 = kb*8 + tig;
#pragma unroll
            for (int nt = 0; nt < 8; nt++) {
                const int kr = nt*8 + gid;
                float b[2];
                b[0] = ks[kr*SKT + c0    ];
                b[1] = ks[kr*SKT + c0 + 4];
                mma_tf32(sa[nt], qf[kb], b);
            }
        }

        // ---- online softmax ----
        float mx0 = -1e30f, mx1 = -1e30f;
#pragma unroll
        for (int n = 0; n < 8; n++) {
            mx0 = fmaxf(mx0, fmaxf(sa[n][0], sa[n][1]));
            mx1 = fmaxf(mx1, fmaxf(sa[n][2], sa[n][3]));
        }
        mx0 = fmaxf(mx0, __shfl_xor_sync(0xffffffffu, mx0, 1));
        mx0 = fmaxf(mx0, __shfl_xor_sync(0xffffffffu, mx0, 2));
        mx1 = fmaxf(mx1, __shfl_xor_sync(0xffffffffu, mx1, 1));
        mx1 = fmaxf(mx1, __shfl_xor_sync(0xffffffffu, mx1, 2));

        float nm0 = fmaxf(m0, mx0), nm1 = fmaxf(m1, mx1);
        float al0 = __expf((m0 - nm0)*scale), al1 = __expf((m1 - nm1)*scale);
        m0 = nm0; m1 = nm1;

        float rs0 = 0.f, rs1 = 0.f;
#pragma unroll
        for (int n = 0; n < 8; n++) {
            float p00 = __expf((sa[n][0] - nm0)*scale);
            float p01 = __expf((sa[n][1] - nm0)*scale);
            float p10 = __expf((sa[n][2] - nm1)*scale);
            float p11 = __expf((sa[n][3] - nm1)*scale);
            rs0 += p00 + p01; rs1 += p10 + p11;
            *(float2*)(p_s +  r0   *SPT + n*8 + 2*tig) =
                make_float2(to_tf32(p00), to_tf32(p01));
            *(float2*)(p_s + (r0+8)*SPT + n*8 + 2*tig) =
                make_float2(to_tf32(p10), to_tf32(p11));
        }
        rs0 += __shfl_xor_sync(0xffffffffu, rs0, 1);
        rs0 += __shfl_xor_sync(0xffffffffu, rs0, 2);
        rs1 += __shfl_xor_sync(0xffffffffu, rs1, 1);
        rs1 += __shfl_xor_sync(0xffffffffu, rs1, 2);
        l0 = l0*al0 + rs0; l1 = l1*al1 + rs1;

#pragma unroll
        for (int n = 0; n < 4; n++) {
            o[n][0] *= al0; o[n][1] *= al0;
            o[n][2] *= al1; o[n][3] *= al1;
        }
        __syncwarp();

        // ---- O~ += P @ C (32-dim output) ----
#pragma unroll
        for (int kb = 0; kb < 8; kb++) {
            const int c0 = kb*8 + tig;
            float a[4];
            a[0] = p_s[ r0    *SPT + c0    ];
            a[1] = p_s[(r0+8) *SPT + c0    ];
            a[2] = p_s[ r0    *SPT + c0 + 4];
            a[3] = p_s[(r0+8) *SPT + c0 + 4];
#pragma unroll
            for (int nt = 0; nt < 4; nt++) {
                float b[2];
                b[0] = cs[(kb*8 + tig    )*SCT + nt*8 + gid];
                b[1] = cs[(kb*8 + tig + 4)*SCT + nt*8 + gid];
                mma_tf32(o[nt], a, b);
            }
        }
        __syncthreads();

        if (kt + 2 < S_/64) issue_kv(cur, kt + 2);
        CP_COMMIT();
    }

    // ---- epilogue: O~ [B,S,H*32], rounded for out_proj ----
    const float inv0 = 1.f / l0, inv1 = 1.f / l1;
    const int s0 = q0 + r0;
    float* op0 = g_ot + ((size_t)(bb*S_ + s0    )*H_ + hh)*32;
    float* op1 = g_ot + ((size_t)(bb*S_ + s0 + 8)*H_ + hh)*32;
#pragma unroll
    for (int nt = 0; nt < 4; nt++) {
        int col = nt*8 + 2*tig;
        *(float2*)(op0 + col) = make_float2(to_tf32(o[nt][0]*inv0), to_tf32(o[nt][1]*inv0));
        *(float2*)(op1 + col) = make_float2(to_tf32(o[nt][2]*inv1), to_tf32(o[nt][3]*inv1));
    }
}

// ---------------------------------------------------------------------------
// Kernel 4: out = O~[8192x256] @ W_eff[256x1024] + b_eff. K-chunks of 32 (x8).
// ---------------------------------------------------------------------------
#define SA 36
#define SB 136
#define ABUF_FL (128*SA)
#define BBUF_FL (32*SB)
#define OUT_SMEM_FLOATS (2*ABUF_FL + 2*BBUF_FL)

__global__ void __launch_bounds__(256) out_proj_kernel(float* __restrict__ out)
{
    extern __shared__ float sm[];
    float* a_s = sm;
    float* b_s = sm + 2*ABUF_FL;
    const uint32_t smb = (uint32_t)__cvta_generic_to_shared(sm);

    const int tid  = threadIdx.x;
    const int lane = tid & 31;
    const int warp = tid >> 5;
    const int gid  = lane >> 2, tig = lane & 3;
    const int wm = warp >> 1, wn = warp & 1;
    const int col0 = blockIdx.x * 128;
    const int row0 = blockIdx.y * 128;

    auto issue_ab = [&](int s, int kc) {
        const uint32_t adst = smb + (uint32_t)(s*ABUF_FL)*4u;
        const uint32_t bdst = smb + (uint32_t)(2*ABUF_FL + s*BBUF_FL)*4u;
#pragma unroll
        for (int i = 0; i < 4; i++) {
            int idx4 = tid + i*256;
            int r = idx4 >> 3, c4 = idx4 & 7;
            cp_async16(adst + (uint32_t)(r*SA + c4*4)*4u,
                       g_ot + (size_t)(row0+r)*256 + kc*32 + c4*4);
        }
#pragma unroll
        for (int i = 0; i < 4; i++) {
            int idx4 = tid + i*256;
            int r = idx4 >> 5, c4 = idx4 & 31;
            cp_async16(bdst + (uint32_t)(r*SB + c4*4)*4u,
                       g_weff + (size_t)(kc*32+r)*DM + col0 + c4*4);
        }
    };

    float acc[2][8][4];
#pragma unroll
    for (int im = 0; im < 2; im++)
#pragma unroll
        for (int n = 0; n < 8; n++)
#pragma unroll
            for (int j = 0; j < 4; j++) acc[im][n][j] = 0.f;

    issue_ab(0, 0); CP_COMMIT();
    issue_ab(1, 1); CP_COMMIT();

    for (int kc = 0; kc < 8; kc++) {
        const int cur = kc & 1;
        CP_WAIT1();
        __syncthreads();
        const float* ap = a_s + cur*ABUF_FL;
        const float* bp = b_s + cur*BBUF_FL;

#pragma unroll
        for (int ks = 0; ks < 4; ks++) {
            const int c0 = ks*8 + tig;
            float a0[4], a1[4];
            int ra = wm*32 + gid;
            a0[0] = ap[ ra      *SA + c0    ];
            a0[1] = ap[(ra+8)   *SA + c0    ];
            a0[2] = ap[ ra      *SA + c0 + 4];
            a0[3] = ap[(ra+8)   *SA + c0 + 4];
            a1[0] = ap[(ra+16)  *SA + c0    ];
            a1[1] = ap[(ra+24)  *SA + c0    ];
            a1[2] = ap[(ra+16)  *SA + c0 + 4];
            a1[3] = ap[(ra+24)  *SA + c0 + 4];
#pragma unroll
            for (int nt = 0; nt < 8; nt++) {
                float b[2];
                int nb = wn*64 + nt*8 + gid;
                b[0] = bp[(ks*8 + tig    )*SB + nb];
                b[1] = bp[(ks*8 + tig + 4)*SB + nb];
                mma_tf32(acc[0][nt], a0, b);
                mma_tf32(acc[1][nt], a1, b);
            }
        }
        __syncthreads();
        if (kc + 2 < 8) issue_ab(cur, kc + 2);
        CP_COMMIT();
    }

#pragma unroll
    for (int im = 0; im < 2; im++) {
        int rr = row0 + wm*32 + im*16 + gid;
#pragma unroll
        for (int nt = 0; nt < 8; nt++) {
            int cc = col0 + wn*64 + nt*8 + 2*tig;
            float bx = g_beff[cc], by = g_beff[cc+1];
            *(float2*)(out + (size_t)rr*DM + cc) =
                make_float2(acc[im][nt][0] + bx, acc[im][nt][1] + by);
            *(float2*)(out + (size_t)(rr+8)*DM + cc) =
                make_float2(acc[im][nt][2] + bx, acc[im][nt][3] + by);
        }
    }
}

// ---------------------------------------------------------------------------
extern "C" void kernel_launch(void* const* d_in, const int* in_sizes, int n_in,
                              void* d_out, int out_size)
{
    (void)in_sizes; (void)n_in; (void)out_size;
    const float* h    = (const float*)d_in[0];
    const float* Wdq  = (const float*)d_in[1];
    const float* bdq  = (const float*)d_in[2];
    const float* Wuq  = (const float*)d_in[3];
    const float* buq  = (const float*)d_in[4];
    const float* Wdkv = (const float*)d_in[5];
    const float* bdkv = (const float*)d_in[6];
    const float* Wuk  = (const float*)d_in[7];
    const float* buk  = (const float*)d_in[8];   (void)buk; // cancels in softmax
    const float* Wuv  = (const float*)d_in[9];
    const float* buv  = (const float*)d_in[10];
    const float* Wqr  = (const float*)d_in[11];
    const float* bqr  = (const float*)d_in[12];
    const float* Wkr  = (const float*)d_in[13];
    const float* bkr  = (const float*)d_in[14];
    const float* Wo   = (const float*)d_in[15];
    const float* bo   = (const float*)d_in[16];
    float* out = (float*)d_out;

    cudaFuncSetAttribute(attn_kernel, cudaFuncAttributeMaxDynamicSharedMemorySize,
                         ATTN_SMEM_FLOATS * (int)sizeof(float));
    cudaFuncSetAttribute(out_proj_kernel, cudaFuncAttributeMaxDynamicSharedMemorySize,
                         OUT_SMEM_FLOATS * (int)sizeof(float));

    prep_M_kernel<<<H_, 256>>>(Wuq, buq, Wuk);
    prep_weff_kernel<<<68, 256>>>(Wuv, buv, Wo, bo);
    down_proj_kernel<<<BS_/32, 256>>>(h, Wdq, bdq, Wdkv, bdkv, Wkr, bkr);
    q_proj_kernel<<<dim3(BS_/64, H_), 256>>>(Wqr, bqr);
    attn_kernel<<<dim3(S_/128, B_*H_), 256, ATTN_SMEM_FLOATS * sizeof(float)>>>();
    out_proj_kernel<<<dim3(DM/128, BS_/128), 256, OUT_SMEM_FLOATS * sizeof(float)>>>(out);
}

// round 9
// speedup vs baseline: 7.4099x; 1.3629x over previous
#include <cuda_runtime.h>
#include <math.h>
#include <stdint.h>

#define B_   4
#define S_   2048
#define DM   1024
#define H_   8
#define DK   128
#define DC   32
#define DHR  32
#define BS_  (B_*S_)        // 8192

// ---------------- scratch (device globals) ----------------------------------
__device__ float g_cq  [BS_*DC];            // fp32 (tf32-grade accuracy)
__device__ float g_ckv [BS_*DC];            // tf32-rounded (PV C operand)
__device__ float g_kt  [BS_*64];            // K~ = [ckv|kr], rounded
__device__ float g_qt  [(size_t)B_*H_*S_*64];  // Q~, rounded
__device__ float g_ot  [(size_t)BS_*H_*32];    // O~ [B,S,H*32], rounded
__device__ float g_M   [H_*DC*DC];          // M_h[c][i] fp32
__device__ float g_m   [H_*DC];             // m_h fp32
__device__ float g_weff[256*DM];            // W_eff rounded
__device__ float g_beff[DM];                // fp32
__device__ float g_wdown[1024*96];          // [Wdq|Wdkv|Wkr] interleaved, rounded

// ---------------- helpers ----------------------------------------------------
__device__ __forceinline__ float to_tf32(float x) {
    uint32_t u;
    asm("cvt.rna.tf32.f32 %0, %1;" : "=r"(u) : "f"(x));
    return __uint_as_float(u);
}
__device__ __forceinline__ void mma_tf32(float* d, const float* a, const float* b) {
    asm("mma.sync.aligned.m16n8k8.row.col.f32.tf32.tf32.f32 "
        "{%0,%1,%2,%3}, {%4,%5,%6,%7}, {%8,%9}, {%0,%1,%2,%3};"
        : "+f"(d[0]), "+f"(d[1]), "+f"(d[2]), "+f"(d[3])
        : "r"(__float_as_uint(a[0])), "r"(__float_as_uint(a[1])),
          "r"(__float_as_uint(a[2])), "r"(__float_as_uint(a[3])),
          "r"(__float_as_uint(b[0])), "r"(__float_as_uint(b[1])));
}
__device__ __forceinline__ void cp_async16(uint32_t saddr, const void* gptr) {
    asm volatile("cp.async.cg.shared.global [%0], [%1], 16;"
                 :: "r"(saddr), "l"(gptr));
}
#define CP_COMMIT()  asm volatile("cp.async.commit_group;")
#define CP_WAIT1()   asm volatile("cp.async.wait_group 1;")

// ---------------------------------------------------------------------------
// Prep A (launch 1): blocks 0..7: M_h, m_h.  blocks 8..19: round down-weights
// into g_wdown[k][0:32=dq | 32:64=dkv | 64:96=kr].
// ---------------------------------------------------------------------------
__global__ void __launch_bounds__(256) prep_M_kernel(
    const float* __restrict__ Wuq, const float* __restrict__ buq,
    const float* __restrict__ Wuk,
    const float* __restrict__ Wdq, const float* __restrict__ Wdkv,
    const float* __restrict__ Wkr)
{
    const int tid = threadIdx.x;
    if (blockIdx.x >= 8) {
        int base = (blockIdx.x - 8)*8192 + tid;
#pragma unroll
        for (int i = 0; i < 32; i++) {
            int idx = base + i*256;
            int k = idx / 96, c = idx - 96*k;
            float v;
            if (c < 32)      v = Wdq [k*32 + c];
            else if (c < 64) v = Wdkv[k*32 + (c-32)];
            else             v = Wkr [k*32 + (c-64)];
            g_wdown[idx] = to_tf32(v);
        }
        return;
    }
    const int h = blockIdx.x;
    for (int idx = tid; idx < DC*DC; idx += 256) {
        int c = idx >> 5, i = idx & 31;
        float s = 0.f;
        const float* wq = Wuq + c*DM + h*DK;
        const float* wk = Wuk + i*DM + h*DK;
#pragma unroll 8
        for (int d = 0; d < DK; d++) s += wq[d]*wk[d];
        g_M[h*DC*DC + idx] = s;
    }
    if (tid < DC) {
        float s = 0.f;
        const float* wk = Wuk + tid*DM + h*DK;
#pragma unroll 8
        for (int d = 0; d < DK; d++) s += buq[h*DK + d]*wk[d];
        g_m[h*DC + tid] = s;
    }
}

// ---------------------------------------------------------------------------
// Prep B (launch 5, before out_proj): W_eff and b_eff.
// ---------------------------------------------------------------------------
__global__ void __launch_bounds__(256) prep_weff_kernel(
    const float* __restrict__ Wuv, const float* __restrict__ buv,
    const float* __restrict__ Wo,  const float* __restrict__ bo)
{
    const int tid = threadIdx.x;
    if (blockIdx.x >= 64) {
        int j = (blockIdx.x - 64)*256 + tid;
        float acc = bo[j];
        for (int k = 0; k < DM; k++) acc += buv[k]*Wo[(size_t)k*DM + j];
        g_beff[j] = acc;
        return;
    }
    const int h = blockIdx.x >> 3, jt = blockIdx.x & 7;
    const int i = tid >> 3, jg = tid & 7;
    const int j0 = jt*128 + jg*16;
    float acc[16];
#pragma unroll
    for (int k = 0; k < 16; k++) acc[k] = 0.f;
    for (int d = 0; d < DK; d++) {
        float wuv = Wuv[i*DM + h*DK + d];
        const float* wo = Wo + (size_t)(h*DK + d)*DM + j0;
#pragma unroll
        for (int k = 0; k < 16; k++) acc[k] += wuv*wo[k];
    }
#pragma unroll
    for (int k = 0; k < 16; k++)
        g_weff[(size_t)(h*32 + i)*DM + j0 + k] = to_tf32(acc[k]);
}

// ---------------------------------------------------------------------------
// Kernel (launch 2): down projections via tf32 mma, cp.async pipelined.
// out[8192x96] = h[8192x1024] @ g_wdown[1024x96]; tile 128x96, K-chunk 32.
// ---------------------------------------------------------------------------
#define DSA 36             // A stride (36%32==4)
#define DSB 104            // B stride (104%32==8)
#define DABUF (128*DSA)    // 4608
#define DBBUF (32*DSB)     // 3328
#define DOWN_SMEM_FLOATS (2*DABUF + 2*DBBUF)   // 15872 fl = 63.5 KB

__global__ void __launch_bounds__(256) down_proj_kernel(
    const float* __restrict__ h,
    const float* __restrict__ bdq, const float* __restrict__ bdkv,
    const float* __restrict__ bkr)
{
    extern __shared__ float sm[];
    float* a_s = sm;
    float* b_s = sm + 2*DABUF;
    const uint32_t smb = (uint32_t)__cvta_generic_to_shared(sm);

    const int tid  = threadIdx.x;
    const int lane = tid & 31;
    const int warp = tid >> 5;
    const int gid  = lane >> 2, tig = lane & 3;
    const int wm = warp >> 1, wn = warp & 1;   // wm: 32-row band, wn: 48-col band
    const int row0 = blockIdx.x * 128;

    auto issue_ab = [&](int s, int kc) {
        const uint32_t adst = smb + (uint32_t)(s*DABUF)*4u;
        const uint32_t bdst = smb + (uint32_t)(2*DABUF + s*DBBUF)*4u;
        // A: 128 rows x 8 float4 = 1024 chunks -> 4/thread
#pragma unroll
        for (int i = 0; i < 4; i++) {
            int idx4 = tid + i*256;
            int r = idx4 >> 3, c4 = idx4 & 7;
            cp_async16(adst + (uint32_t)(r*DSA + c4*4)*4u,
                       h + (size_t)(row0+r)*DM + kc*32 + c4*4);
        }
        // B: 32 rows x 24 float4 = 768 chunks -> 3/thread
#pragma unroll
        for (int i = 0; i < 3; i++) {
            int idx4 = tid + i*256;
            int r = idx4 / 24, cc = idx4 - 24*r;
            cp_async16(bdst + (uint32_t)(r*DSB + cc*4)*4u,
                       g_wdown + (size_t)(kc*32+r)*96 + cc*4);
        }
    };

    float acc[2][6][4];
#pragma unroll
    for (int im = 0; im < 2; im++)
#pragma unroll
        for (int n = 0; n < 6; n++)
#pragma unroll
            for (int j = 0; j < 4; j++) acc[im][n][j] = 0.f;

    issue_ab(0, 0); CP_COMMIT();
    issue_ab(1, 1); CP_COMMIT();

    for (int kc = 0; kc < 32; kc++) {
        const int cur = kc & 1;
        CP_WAIT1();
        __syncthreads();
        const float* ap = a_s + cur*DABUF;
        const float* bp = b_s + cur*DBBUF;

#pragma unroll
        for (int ks = 0; ks < 4; ks++) {
            const int c0 = ks*8 + tig;
            float a0[4], a1[4];
            int ra = wm*32 + gid;
            a0[0] = ap[ ra      *DSA + c0    ];
            a0[1] = ap[(ra+8)   *DSA + c0    ];
            a0[2] = ap[ ra      *DSA + c0 + 4];
            a0[3] = ap[(ra+8)   *DSA + c0 + 4];
            a1[0] = ap[(ra+16)  *DSA + c0    ];
            a1[1] = ap[(ra+24)  *DSA + c0    ];
            a1[2] = ap[(ra+16)  *DSA + c0 + 4];
            a1[3] = ap[(ra+24)  *DSA + c0 + 4];
#pragma unroll
            for (int nt = 0; nt < 6; nt++) {
                float b[2];
                int nb = wn*48 + nt*8 + gid;
                b[0] = bp[(ks*8 + tig    )*DSB + nb];
                b[1] = bp[(ks*8 + tig + 4)*DSB + nb];
                mma_tf32(acc[0][nt], a0, b);
                mma_tf32(acc[1][nt], a1, b);
            }
        }
        __syncthreads();
        if (kc + 2 < 32) issue_ab(cur, kc + 2);
        CP_COMMIT();
    }

    // epilogue: scatter to g_cq / g_ckv / g_kt with bias, rounding where needed
#pragma unroll
    for (int im = 0; im < 2; im++) {
        int rbase = row0 + wm*32 + im*16 + gid;
#pragma unroll
        for (int nt = 0; nt < 6; nt++) {
            int cc = wn*48 + nt*8 + 2*tig;
#pragma unroll
            for (int half = 0; half < 2; half++) {
                int rr = rbase + half*8;
                float v0 = acc[im][nt][half*2 + 0];
                float v1 = acc[im][nt][half*2 + 1];
#pragma unroll
                for (int e = 0; e < 2; e++) {
                    int col = cc + e;
                    float v = e ? v1 : v0;
                    if (col < 32) {
                        g_cq[rr*32 + col] = v + bdq[col];
                    } else if (col < 64) {
                        float cv = to_tf32(v + bdkv[col-32]);
                        g_ckv[rr*32 + (col-32)] = cv;
                        g_kt [rr*64 + (col-32)] = cv;
                    } else {
                        g_kt[rr*64 + 32 + (col-64)] = to_tf32(v + bkr[col-64]);
                    }
                }
            }
        }
    }
}

// ---------------------------------------------------------------------------
// Kernel (launch 3): Q~[b,h,s,64] = [c_q@M_h+m_h | c_q@W_QR_h+b_QR_h]
// ---------------------------------------------------------------------------
__global__ void __launch_bounds__(256) q_proj_kernel(
    const float* __restrict__ Wqr, const float* __restrict__ bqr)
{
    __shared__ float w_s[32*64];
    __shared__ float c_s[64*32];
    __shared__ float bias_s[64];

    const int tid  = threadIdx.x;
    const int hh   = blockIdx.y;
    const int row0 = blockIdx.x * 64;

#pragma unroll
    for (int i = 0; i < 8; i++) {
        int idx = tid + i*256;
        int k = idx >> 6, c = idx & 63;
        w_s[idx] = (c < 32) ? g_M[hh*DC*DC + k*32 + c]
                            : Wqr[k*256 + hh*32 + (c-32)];
    }
    if (tid < 64)
        bias_s[tid] = (tid < 32) ? g_m[hh*DC + tid] : bqr[hh*32 + tid - 32];
#pragma unroll
    for (int i = 0; i < 8; i++) {
        int idx = tid + i*256;
        c_s[idx] = g_cq[row0*32 + idx];
    }
    __syncthreads();

    const int col = tid & 63, rg = tid >> 6;
    for (int rr = 0; rr < 16; rr++) {
        int r = rg*16 + rr;
        float acc = bias_s[col];
#pragma unroll
        for (int k = 0; k < 32; k++) acc += c_s[r*32 + k]*w_s[k*64 + col];
        int row = row0 + r;
        int bb = row >> 11, ss = row & 2047;
        g_qt[((size_t)(bb*H_ + hh)*S_ + ss)*64 + col] = to_tf32(acc);
    }
}

// ---------------------------------------------------------------------------
// Kernel (launch 4 -> gets PROFILED): absorbed flash attention (as R8).
// ---------------------------------------------------------------------------
#define SKT 68
#define SCT 40
#define SPT 68
#define KT_FL (64*SKT)
#define CT_FL (64*SCT)
#define ATTN_SMEM_FLOATS (2*KT_FL + 2*CT_FL + 128*SPT)

__global__ void __launch_bounds__(256, 2) attn_kernel()
{
    extern __shared__ float sm[];
    float* kbuf = sm;
    float* cbuf = sm + 2*KT_FL;
    float* p_s  = cbuf + 2*CT_FL;
    const uint32_t smb = (uint32_t)__cvta_generic_to_shared(sm);

    const int tid  = threadIdx.x;
    const int lane = tid & 31;
    const int warp = tid >> 5;
    const int gid  = lane >> 2;
    const int tig  = lane & 3;
    const int bh   = blockIdx.y;
    const int bb   = bh >> 3, hh = bh & 7;
    const int q0   = blockIdx.x * 128;

    const float* qg = g_qt + ((size_t)bh*S_ + q0)*64;
    const float* kg = g_kt + (size_t)bb*S_*64;
    const float* cg = g_ckv + (size_t)bb*S_*32;

    const float scale = 0.07905694150420948f;

#pragma unroll
    for (int i = 0; i < 8; i++) {
        int idx4 = tid + i*256;
        int r = idx4 >> 4, c4 = idx4 & 15;
        float4 v = *(const float4*)(qg + (size_t)r*64 + c4*4);
        *(float4*)(p_s + r*SPT + c4*4) = v;
    }
    __syncthreads();

    const int r0 = warp*16 + gid;
    float qf[8][4];
#pragma unroll
    for (int kb = 0; kb < 8; kb++) {
        int c0 = kb*8 + tig;
        qf[kb][0] = p_s[ r0    *SPT + c0    ];
        qf[kb][1] = p_s[(r0+8) *SPT + c0    ];
        qf[kb][2] = p_s[ r0    *SPT + c0 + 4];
        qf[kb][3] = p_s[(r0+8) *SPT + c0 + 4];
    }

    auto issue_kv = [&](int s, int t) {
        const float* ksrc = kg + (size_t)t*64*64;
        const float* csrc = cg + (size_t)t*64*32;
        const uint32_t kdst = smb + (uint32_t)(s*KT_FL)*4u;
        const uint32_t cdst = smb + (uint32_t)(2*KT_FL + s*CT_FL)*4u;
#pragma unroll
        for (int i = 0; i < 4; i++) {
            int idx4 = tid + i*256;
            int r = idx4 >> 4, c4 = idx4 & 15;
            cp_async16(kdst + (uint32_t)(r*SKT + c4*4)*4u, ksrc + r*64 + c4*4);
        }
#pragma unroll
        for (int i = 0; i < 2; i++) {
            int idx4 = tid + i*256;
            int r = idx4 >> 3, c4 = idx4 & 7;
            cp_async16(cdst + (uint32_t)(r*SCT + c4*4)*4u, csrc + r*32 + c4*4);
        }
    };

    issue_kv(0, 0); CP_COMMIT();
    issue_kv(1, 1); CP_COMMIT();

    float m0 = -1e30f, m1 = -1e30f, l0 = 0.f, l1 = 0.f;
    float o[4][4];
#pragma unroll
    for (int i = 0; i < 4; i++)
#pragma unroll
        for (int j = 0; j < 4; j++) o[i][j] = 0.f;

    for (int kt = 0; kt < S_/64; kt++) {
        const int cur = kt & 1;
        CP_WAIT1();
        __syncthreads();
        const float* ks = kbuf + cur*KT_FL;
        const float* cs = cbuf + cur*CT_FL;

        float sa[8][4];
#pragma unroll
        for (int n = 0; n < 8; n++)
#pragma unroll
            for (int j = 0; j < 4; j++) sa[n][j] = 0.f;

#pragma unroll
        for (int kb = 0; kb < 8; kb++) {
            const int c0 = kb*8 + tig;
#pragma unroll
            for (int nt = 0; nt < 8; nt++) {
                const int kr = nt*8 + gid;
                float b[2];
                b[0] = ks[kr*SKT + c0    ];
                b[1] = ks[kr*SKT + c0 + 4];
                mma_tf32(sa[nt], qf[kb], b);
            }
        }

        float mx0 = -1e30f, mx1 = -1e30f;
#pragma unroll
        for (int n = 0; n < 8; n++) {
            mx0 = fmaxf(mx0, fmaxf(sa[n][0], sa[n][1]));
            mx1 = fmaxf(mx1, fmaxf(sa[n][2], sa[n][3]));
        }
        mx0 = fmaxf(mx0, __shfl_xor_sync(0xffffffffu, mx0, 1));
        mx0 = fmaxf(mx0, __shfl_xor_sync(0xffffffffu, mx0, 2));
        mx1 = fmaxf(mx1, __shfl_xor_sync(0xffffffffu, mx1, 1));
        mx1 = fmaxf(mx1, __shfl_xor_sync(0xffffffffu, mx1, 2));

        float nm0 = fmaxf(m0, mx0), nm1 = fmaxf(m1, mx1);
        float al0 = __expf((m0 - nm0)*scale), al1 = __expf((m1 - nm1)*scale);
        m0 = nm0; m1 = nm1;

        float rs0 = 0.f, rs1 = 0.f;
#pragma unroll
        for (int n = 0; n < 8; n++) {
            float p00 = __expf((sa[n][0] - nm0)*scale);
            float p01 = __expf((sa[n][1] - nm0)*scale);
            float p10 = __expf((sa[n][2] - nm1)*scale);
            float p11 = __expf((sa[n][3] - nm1)*scale);
            rs0 += p00 + p01; rs1 += p10 + p11;
            *(float2*)(p_s +  r0   *SPT + n*8 + 2*tig) =
                make_float2(to_tf32(p00), to_tf32(p01));
            *(float2*)(p_s + (r0+8)*SPT + n*8 + 2*tig) =
                make_float2(to_tf32(p10), to_tf32(p11));
        }
        rs0 += __shfl_xor_sync(0xffffffffu, rs0, 1);
        rs0 += __shfl_xor_sync(0xffffffffu, rs0, 2);
        rs1 += __shfl_xor_sync(0xffffffffu, rs1, 1);
        rs1 += __shfl_xor_sync(0xffffffffu, rs1, 2);
        l0 = l0*al0 + rs0; l1 = l1*al1 + rs1;

#pragma unroll
        for (int n = 0; n < 4; n++) {
            o[n][0] *= al0; o[n][1] *= al0;
            o[n][2] *= al1; o[n][3] *= al1;
        }
        __syncwarp();

#pragma unroll
        for (int kb = 0; kb < 8; kb++) {
            const int c0 = kb*8 + tig;
            float a[4];
            a[0] = p_s[ r0    *SPT + c0    ];
            a[1] = p_s[(r0+8) *SPT + c0    ];
            a[2] = p_s[ r0    *SPT + c0 + 4];
            a[3] = p_s[(r0+8) *SPT + c0 + 4];
#pragma unroll
            for (int nt = 0; nt < 4; nt++) {
                float b[2];
                b[0] = cs[(kb*8 + tig    )*SCT + nt*8 + gid];
                b[1] = cs[(kb*8 + tig + 4)*SCT + nt*8 + gid];
                mma_tf32(o[nt], a, b);
            }
        }
        __syncthreads();

        if (kt + 2 < S_/64) issue_kv(cur, kt + 2);
        CP_COMMIT();
    }

    const float inv0 = 1.f / l0, inv1 = 1.f / l1;
    const int s0 = q0 + r0;
    float* op0 = g_ot + ((size_t)(bb*S_ + s0    )*H_ + hh)*32;
    float* op1 = g_ot + ((size_t)(bb*S_ + s0 + 8)*H_ + hh)*32;
#pragma unroll
    for (int nt = 0; nt < 4; nt++) {
        int col = nt*8 + 2*tig;
        *(float2*)(op0 + col) = make_float2(to_tf32(o[nt][0]*inv0), to_tf32(o[nt][1]*inv0));
        *(float2*)(op1 + col) = make_float2(to_tf32(o[nt][2]*inv1), to_tf32(o[nt][3]*inv1));
    }
}

// ---------------------------------------------------------------------------
// Kernel (launch 6): out = O~[8192x256] @ W_eff[256x1024] + b_eff
// ---------------------------------------------------------------------------
#define SA 36
#define SB 136
#define ABUF_FL (128*SA)
#define BBUF_FL (32*SB)
#define OUT_SMEM_FLOATS (2*ABUF_FL + 2*BBUF_FL)

__global__ void __launch_bounds__(256) out_proj_kernel(float* __restrict__ out)
{
    extern __shared__ float sm[];
    float* a_s = sm;
    float* b_s = sm + 2*ABUF_FL;
    const uint32_t smb = (uint32_t)__cvta_generic_to_shared(sm);

    const int tid  = threadIdx.x;
    const int lane = tid & 31;
    const int warp = tid >> 5;
    const int gid  = lane >> 2, tig = lane & 3;
    const int wm = warp >> 1, wn = warp & 1;
    const int col0 = blockIdx.x * 128;
    const int row0 = blockIdx.y * 128;

    auto issue_ab = [&](int s, int kc) {
        const uint32_t adst = smb + (uint32_t)(s*ABUF_FL)*4u;
        const uint32_t bdst = smb + (uint32_t)(2*ABUF_FL + s*BBUF_FL)*4u;
#pragma unroll
        for (int i = 0; i < 4; i++) {
            int idx4 = tid + i*256;
            int r = idx4 >> 3, c4 = idx4 & 7;
            cp_async16(adst + (uint32_t)(r*SA + c4*4)*4u,
                       g_ot + (size_t)(row0+r)*256 + kc*32 + c4*4);
        }
#pragma unroll
        for (int i = 0; i < 4; i++) {
            int idx4 = tid + i*256;
            int r = idx4 >> 5, c4 = idx4 & 31;
            cp_async16(bdst + (uint32_t)(r*SB + c4*4)*4u,
                       g_weff + (size_t)(kc*32+r)*DM + col0 + c4*4);
        }
    };

    float acc[2][8][4];
#pragma unroll
    for (int im = 0; im < 2; im++)
#pragma unroll
        for (int n = 0; n < 8; n++)
#pragma unroll
            for (int j = 0; j < 4; j++) acc[im][n][j] = 0.f;

    issue_ab(0, 0); CP_COMMIT();
    issue_ab(1, 1); CP_COMMIT();

    for (int kc = 0; kc < 8; kc++) {
        const int cur = kc & 1;
        CP_WAIT1();
        __syncthreads();
        const float* ap = a_s + cur*ABUF_FL;
        const float* bp = b_s + cur*BBUF_FL;

#pragma unroll
        for (int ks = 0; ks < 4; ks++) {
            const int c0 = ks*8 + tig;
            float a0[4], a1[4];
            int ra = wm*32 + gid;
            a0[0] = ap[ ra      *SA + c0    ];
            a0[1] = ap[(ra+8)   *SA + c0    ];
            a0[2] = ap[ ra      *SA + c0 + 4];
            a0[3] = ap[(ra+8)   *SA + c0 + 4];
            a1[0] = ap[(ra+16)  *SA + c0    ];
            a1[1] = ap[(ra+24)  *SA + c0    ];
            a1[2] = ap[(ra+16)  *SA + c0 + 4];
            a1[3] = ap[(ra+24)  *SA + c0 + 4];
#pragma unroll
            for (int nt = 0; nt < 8; nt++) {
                float b[2];
                int nb = wn*64 + nt*8 + gid;
                b[0] = bp[(ks*8 + tig    )*SB + nb];
                b[1] = bp[(ks*8 + tig + 4)*SB + nb];
                mma_tf32(acc[0][nt], a0, b);
                mma_tf32(acc[1][nt], a1, b);
            }
        }
        __syncthreads();
        if (kc + 2 < 8) issue_ab(cur, kc + 2);
        CP_COMMIT();
    }

#pragma unroll
    for (int im = 0; im < 2; im++) {
        int rr = row0 + wm*32 + im*16 + gid;
#pragma unroll
        for (int nt = 0; nt < 8; nt++) {
            int cc = col0 + wn*64 + nt*8 + 2*tig;
            float bx = g_beff[cc], by = g_beff[cc+1];
            *(float2*)(out + (size_t)rr*DM + cc) =
                make_float2(acc[im][nt][0] + bx, acc[im][nt][1] + by);
            *(float2*)(out + (size_t)(rr+8)*DM + cc) =
                make_float2(acc[im][nt][2] + bx, acc[im][nt][3] + by);
        }
    }
}

// ---------------------------------------------------------------------------
extern "C" void kernel_launch(void* const* d_in, const int* in_sizes, int n_in,
                              void* d_out, int out_size)
{
    (void)in_sizes; (void)n_in; (void)out_size;
    const float* h    = (const float*)d_in[0];
    const float* Wdq  = (const float*)d_in[1];
    const float* bdq  = (const float*)d_in[2];
    const float* Wuq  = (const float*)d_in[3];
    const float* buq  = (const float*)d_in[4];
    const float* Wdkv = (const float*)d_in[5];
    const float* bdkv = (const float*)d_in[6];
    const float* Wuk  = (const float*)d_in[7];
    const float* buk  = (const float*)d_in[8];   (void)buk; // cancels in softmax
    const float* Wuv  = (const float*)d_in[9];
    const float* buv  = (const float*)d_in[10];
    const float* Wqr  = (const float*)d_in[11];
    const float* bqr  = (const float*)d_in[12];
    const float* Wkr  = (const float*)d_in[13];
    const float* bkr  = (const float*)d_in[14];
    const float* Wo   = (const float*)d_in[15];
    const float* bo   = (const float*)d_in[16];
    float* out = (float*)d_out;

    cudaFuncSetAttribute(attn_kernel, cudaFuncAttributeMaxDynamicSharedMemorySize,
                         ATTN_SMEM_FLOATS * (int)sizeof(float));
    cudaFuncSetAttribute(out_proj_kernel, cudaFuncAttributeMaxDynamicSharedMemorySize,
                         OUT_SMEM_FLOATS * (int)sizeof(float));
    cudaFuncSetAttribute(down_proj_kernel, cudaFuncAttributeMaxDynamicSharedMemorySize,
                         DOWN_SMEM_FLOATS * (int)sizeof(float));

    // launch order chosen so attn is the 4th launch (ncu capture window)
    prep_M_kernel<<<20, 256>>>(Wuq, buq, Wuk, Wdq, Wdkv, Wkr);
    down_proj_kernel<<<BS_/128, 256, DOWN_SMEM_FLOATS * sizeof(float)>>>(h, bdq, bdkv, bkr);
    q_proj_kernel<<<dim3(BS_/64, H_), 256>>>(Wqr, bqr);
    attn_kernel<<<dim3(S_/128, B_*H_), 256, ATTN_SMEM_FLOATS * sizeof(float)>>>();
    prep_weff_kernel<<<68, 256>>>(Wuv, buv, Wo, bo);
    out_proj_kernel<<<dim3(DM/128, BS_/128), 256, OUT_SMEM_FLOATS * sizeof(float)>>>(out);
}

// round 11
// speedup vs baseline: 8.7968x; 1.1872x over previous
#include <cuda_runtime.h>
#include <math.h>
#include <stdint.h>

#define B_   4
#define S_   2048
#define DM   1024
#define H_   8
#define DK   128
#define DC   32
#define DHR  32
#define BS_  (B_*S_)        // 8192

// ---------------- scratch (device globals) ----------------------------------
__device__ float g_cq  [BS_*DC];               // fp32
__device__ float g_kt  [BS_*64];               // K~ pair-permuted cols, rounded
__device__ float g_cvT [BS_*DC];               // C^T tiles [tile][col][64 rows perm]
__device__ float g_qt  [(size_t)B_*H_*S_*64];  // Q~ pair-permuted cols, rounded
__device__ float g_ot  [(size_t)BS_*H_*32];    // O~ [B,S,H*32], rounded
__device__ float g_M   [H_*DC*DC];
__device__ float g_m   [H_*DC];
__device__ float g_weff[256*DM];               // rounded
__device__ float g_beff[DM];
__device__ float g_wdown[1024*96];             // [Wdq|Wdkv|Wkr], rounded

// ---------------- helpers ----------------------------------------------------
__device__ __forceinline__ float to_tf32(float x) {
    uint32_t u;
    asm("cvt.rna.tf32.f32 %0, %1;" : "=r"(u) : "f"(x));
    return __uint_as_float(u);
}
__device__ __forceinline__ int perm8(int c) {   // (c,c+4) pairs -> adjacent
    return ((c & 3) << 1) | ((c >> 2) & 1);
}
__device__ __forceinline__ int ppos(int c) {    // permute within 8-group
    return (c & ~7) | perm8(c & 7);
}
__device__ __forceinline__ void mma_tf32(float* d, const float* a, const float* b) {
    asm("mma.sync.aligned.m16n8k8.row.col.f32.tf32.tf32.f32 "
        "{%0,%1,%2,%3}, {%4,%5,%6,%7}, {%8,%9}, {%0,%1,%2,%3};"
        : "+f"(d[0]), "+f"(d[1]), "+f"(d[2]), "+f"(d[3])
        : "r"(__float_as_uint(a[0])), "r"(__float_as_uint(a[1])),
          "r"(__float_as_uint(a[2])), "r"(__float_as_uint(a[3])),
          "r"(__float_as_uint(b[0])), "r"(__float_as_uint(b[1])));
}
__device__ __forceinline__ void cp_async16(uint32_t saddr, const void* gptr) {
    asm volatile("cp.async.cg.shared.global [%0], [%1], 16;"
                 :: "r"(saddr), "l"(gptr));
}
#define CP_COMMIT()  asm volatile("cp.async.commit_group;")
#define CP_WAIT1()   asm volatile("cp.async.wait_group 1;")

// ---------------------------------------------------------------------------
// Launch 1: merged prep. blocks 0..7: M_h,m_h; 8..19: wdown rounding;
// 20..83: W_eff; 84..87: b_eff.
// ---------------------------------------------------------------------------
__global__ void __launch_bounds__(256) prep_kernel(
    const float* __restrict__ Wuq, const float* __restrict__ buq,
    const float* __restrict__ Wuk,
    const float* __restrict__ Wdq, const float* __restrict__ Wdkv,
    const float* __restrict__ Wkr,
    const float* __restrict__ Wuv, const float* __restrict__ buv,
    const float* __restrict__ Wo,  const float* __restrict__ bo)
{
    const int tid = threadIdx.x;
    const int bx  = blockIdx.x;
    if (bx < 8) {
        const int h = bx;
        for (int idx = tid; idx < DC*DC; idx += 256) {
            int c = idx >> 5, i = idx & 31;
            float s = 0.f;
            const float* wq = Wuq + c*DM + h*DK;
            const float* wk = Wuk + i*DM + h*DK;
#pragma unroll 8
            for (int d = 0; d < DK; d++) s += wq[d]*wk[d];
            g_M[h*DC*DC + idx] = s;
        }
        if (tid < DC) {
            float s = 0.f;
            const float* wk = Wuk + tid*DM + h*DK;
#pragma unroll 8
            for (int d = 0; d < DK; d++) s += buq[h*DK + d]*wk[d];
            g_m[h*DC + tid] = s;
        }
    } else if (bx < 20) {
        int base = (bx - 8)*8192 + tid;
#pragma unroll
        for (int i = 0; i < 32; i++) {
            int idx = base + i*256;
            int k = idx / 96, c = idx - 96*k;
            float v;
            if (c < 32)      v = Wdq [k*32 + c];
            else if (c < 64) v = Wdkv[k*32 + (c-32)];
            else             v = Wkr [k*32 + (c-64)];
            g_wdown[idx] = to_tf32(v);
        }
    } else if (bx < 84) {
        const int h = (bx-20) >> 3, jt = (bx-20) & 7;
        const int i = tid >> 3, jg = tid & 7;
        const int j0 = jt*128 + jg*16;
        float acc[16];
#pragma unroll
        for (int k = 0; k < 16; k++) acc[k] = 0.f;
        for (int d = 0; d < DK; d++) {
            float wuv = Wuv[i*DM + h*DK + d];
            const float* wo = Wo + (size_t)(h*DK + d)*DM + j0;
#pragma unroll
            for (int k = 0; k < 16; k++) acc[k] += wuv*wo[k];
        }
#pragma unroll
        for (int k = 0; k < 16; k++)
            g_weff[(size_t)(h*32 + i)*DM + j0 + k] = to_tf32(acc[k]);
    } else {
        int j = (bx - 84)*256 + tid;
        float acc = bo[j];
        for (int k = 0; k < DM; k++) acc += buv[k]*Wo[(size_t)k*DM + j];
        g_beff[j] = acc;
    }
}

// ---------------------------------------------------------------------------
// Launch 2: down projections via tf32 mma (tile 128x96, K-chunk 32).
// Epilogue scatters: g_cq natural, g_kt permuted (FIXED bases), g_cvT.
// ---------------------------------------------------------------------------
#define DSA 36
#define DSB 104
#define DABUF (128*DSA)
#define DBBUF (32*DSB)
#define DOWN_SMEM_FLOATS (2*DABUF + 2*DBBUF)

__global__ void __launch_bounds__(256) down_proj_kernel(
    const float* __restrict__ h,
    const float* __restrict__ bdq, const float* __restrict__ bdkv,
    const float* __restrict__ bkr)
{
    extern __shared__ float sm[];
    float* a_s = sm;
    float* b_s = sm + 2*DABUF;
    const uint32_t smb = (uint32_t)__cvta_generic_to_shared(sm);

    const int tid  = threadIdx.x;
    const int lane = tid & 31;
    const int warp = tid >> 5;
    const int gid  = lane >> 2, tig = lane & 3;
    const int wm = warp >> 1, wn = warp & 1;
    const int row0 = blockIdx.x * 128;

    auto issue_ab = [&](int s, int kc) {
        const uint32_t adst = smb + (uint32_t)(s*DABUF)*4u;
        const uint32_t bdst = smb + (uint32_t)(2*DABUF + s*DBBUF)*4u;
#pragma unroll
        for (int i = 0; i < 4; i++) {
            int idx4 = tid + i*256;
            int r = idx4 >> 3, c4 = idx4 & 7;
            cp_async16(adst + (uint32_t)(r*DSA + c4*4)*4u,
                       h + (size_t)(row0+r)*DM + kc*32 + c4*4);
        }
#pragma unroll
        for (int i = 0; i < 3; i++) {
            int idx4 = tid + i*256;
            int r = idx4 / 24, cc = idx4 - 24*r;
            cp_async16(bdst + (uint32_t)(r*DSB + cc*4)*4u,
                       g_wdown + (size_t)(kc*32+r)*96 + cc*4);
        }
    };

    float acc[2][6][4];
#pragma unroll
    for (int im = 0; im < 2; im++)
#pragma unroll
        for (int n = 0; n < 6; n++)
#pragma unroll
            for (int j = 0; j < 4; j++) acc[im][n][j] = 0.f;

    issue_ab(0, 0); CP_COMMIT();
    issue_ab(1, 1); CP_COMMIT();

    for (int kc = 0; kc < 32; kc++) {
        const int cur = kc & 1;
        CP_WAIT1();
        __syncthreads();
        const float* ap = a_s + cur*DABUF;
        const float* bp = b_s + cur*DBBUF;

#pragma unroll
        for (int ks = 0; ks < 4; ks++) {
            const int c0 = ks*8 + tig;
            float a0[4], a1[4];
            int ra = wm*32 + gid;
            a0[0] = ap[ ra      *DSA + c0    ];
            a0[1] = ap[(ra+8)   *DSA + c0    ];
            a0[2] = ap[ ra      *DSA + c0 + 4];
            a0[3] = ap[(ra+8)   *DSA + c0 + 4];
            a1[0] = ap[(ra+16)  *DSA + c0    ];
            a1[1] = ap[(ra+24)  *DSA + c0    ];
            a1[2] = ap[(ra+16)  *DSA + c0 + 4];
            a1[3] = ap[(ra+24)  *DSA + c0 + 4];
#pragma unroll
            for (int nt = 0; nt < 6; nt++) {
                float b[2];
                int nb = wn*48 + nt*8 + gid;
                b[0] = bp[(ks*8 + tig    )*DSB + nb];
                b[1] = bp[(ks*8 + tig + 4)*DSB + nb];
                mma_tf32(acc[0][nt], a0, b);
                mma_tf32(acc[1][nt], a1, b);
            }
        }
        __syncthreads();
        if (kc + 2 < 32) issue_ab(cur, kc + 2);
        CP_COMMIT();
    }

#pragma unroll
    for (int im = 0; im < 2; im++) {
        int rbase = row0 + wm*32 + im*16 + gid;
#pragma unroll
        for (int nt = 0; nt < 6; nt++) {
            int cc = wn*48 + nt*8 + 2*tig;
#pragma unroll
            for (int half = 0; half < 2; half++) {
                int rr = rbase + half*8;
#pragma unroll
                for (int e = 0; e < 2; e++) {
                    int col = cc + e;
                    float v = acc[im][nt][half*2 + e];
                    if (col < 32) {
                        g_cq[rr*32 + col] = v + bdq[col];
                    } else if (col < 64) {
                        float cv = to_tf32(v + bdkv[col-32]);
                        g_kt[rr*64 + ppos(col-32)] = cv;            // FIX: base 0
                        int t = rr >> 6, lr = rr & 63;
                        g_cvT[((size_t)t*32 + (col-32))*64 + ppos(lr)] = cv;
                    } else {
                        g_kt[rr*64 + 32 + ppos(col-64)] =           // FIX: base 32
                            to_tf32(v + bkr[col-64]);
                    }
                }
            }
        }
    }
}

// ---------------------------------------------------------------------------
// Launch 3: Q~[b,h,s,64] = [c_q@M_h+m_h | c_q@W_QR_h+b_QR_h], pair-permuted
// ---------------------------------------------------------------------------
__global__ void __launch_bounds__(256) q_proj_kernel(
    const float* __restrict__ Wqr, const float* __restrict__ bqr)
{
    __shared__ float w_s[32*64];
    __shared__ float c_s[64*32];
    __shared__ float bias_s[64];

    const int tid  = threadIdx.x;
    const int hh   = blockIdx.y;
    const int row0 = blockIdx.x * 64;

#pragma unroll
    for (int i = 0; i < 8; i++) {
        int idx = tid + i*256;
        int k = idx >> 6, c = idx & 63;
        w_s[idx] = (c < 32) ? g_M[hh*DC*DC + k*32 + c]
                            : Wqr[k*256 + hh*32 + (c-32)];
    }
    if (tid < 64)
        bias_s[tid] = (tid < 32) ? g_m[hh*DC + tid] : bqr[hh*32 + tid - 32];
#pragma unroll
    for (int i = 0; i < 8; i++) {
        int idx = tid + i*256;
        c_s[idx] = g_cq[row0*32 + idx];
    }
    __syncthreads();

    const int col = tid & 63, rg = tid >> 6;
    const int pcol = ppos(col);
    for (int rr = 0; rr < 16; rr++) {
        int r = rg*16 + rr;
        float acc = bias_s[col];
#pragma unroll
        for (int k = 0; k < 32; k++) acc += c_s[r*32 + k]*w_s[k*64 + col];
        int row = row0 + r;
        int bb = row >> 11, ss = row & 2047;
        g_qt[((size_t)(bb*H_ + hh)*S_ + ss)*64 + pcol] = to_tf32(acc);
    }
}

// ---------------------------------------------------------------------------
// Launch 4 (PROFILED): absorbed flash attention, float2 b-fragments.
// ---------------------------------------------------------------------------
#define SKT 72
#define SCT 72
#define SPT 72
#define KT_FL (64*SKT)
#define CT_FL (32*SCT)
#define ATTN_SMEM_FLOATS (2*KT_FL + 2*CT_FL + 128*SPT)

__global__ void __launch_bounds__(256, 2) attn_kernel()
{
    extern __shared__ float sm[];
    float* kbuf = sm;
    float* cbuf = sm + 2*KT_FL;
    float* p_s  = cbuf + 2*CT_FL;
    const uint32_t smb = (uint32_t)__cvta_generic_to_shared(sm);

    const int tid  = threadIdx.x;
    const int lane = tid & 31;
    const int warp = tid >> 5;
    const int gid  = lane >> 2;
    const int tig  = lane & 3;
    const int bh   = blockIdx.y;
    const int bb   = bh >> 3, hh = bh & 7;
    const int q0   = blockIdx.x * 128;

    const float* qg = g_qt + ((size_t)bh*S_ + q0)*64;
    const float* kg = g_kt + (size_t)bb*S_*64;
    const float* cg = g_cvT + (size_t)bb*(S_/64)*2048;

    const float scale = 0.07905694150420948f;

#pragma unroll
    for (int i = 0; i < 8; i++) {
        int idx4 = tid + i*256;
        int r = idx4 >> 4, c4 = idx4 & 15;
        float4 v = *(const float4*)(qg + (size_t)r*64 + c4*4);
        *(float4*)(p_s + r*SPT + c4*4) = v;
    }
    __syncthreads();

    const int r0 = warp*16 + gid;
    float qf[8][4];
#pragma unroll
    for (int kb = 0; kb < 8; kb++) {
        float2 f0 = *(const float2*)(p_s +  r0   *SPT + kb*8 + 2*tig);
        float2 f1 = *(const float2*)(p_s + (r0+8)*SPT + kb*8 + 2*tig);
        qf[kb][0] = f0.x; qf[kb][1] = f1.x; qf[kb][2] = f0.y; qf[kb][3] = f1.y;
    }

    auto issue_kv = [&](int s, int t) {
        const float* ksrc = kg + (size_t)t*64*64;
        const float* csrc = cg + (size_t)t*2048;
        const uint32_t kdst = smb + (uint32_t)(s*KT_FL)*4u;
        const uint32_t cdst = smb + (uint32_t)(2*KT_FL + s*CT_FL)*4u;
#pragma unroll
        for (int i = 0; i < 4; i++) {
            int idx4 = tid + i*256;
            int r = idx4 >> 4, c4 = idx4 & 15;
            cp_async16(kdst + (uint32_t)(r*SKT + c4*4)*4u, ksrc + r*64 + c4*4);
        }
#pragma unroll
        for (int i = 0; i < 2; i++) {
            int idx4 = tid + i*256;
            int c = idx4 >> 4, rg = idx4 & 15;
            cp_async16(cdst + (uint32_t)(c*SCT + rg*4)*4u, csrc + c*64 + rg*4);
        }
    };

    issue_kv(0, 0); CP_COMMIT();
    issue_kv(1, 1); CP_COMMIT();

    float m0 = -1e30f, m1 = -1e30f, l0 = 0.f, l1 = 0.f;
    float o[4][4];
#pragma unroll
    for (int i = 0; i < 4; i++)
#pragma unroll
        for (int j = 0; j < 4; j++) o[i][j] = 0.f;

    for (int kt = 0; kt < S_/64; kt++) {
        const int cur = kt & 1;
        CP_WAIT1();
        __syncthreads();
        const float* ks = kbuf + cur*KT_FL;
        const float* cs = cbuf + cur*CT_FL;

        float sa[8][4];
#pragma unroll
        for (int n = 0; n < 8; n++)
#pragma unroll
            for (int j = 0; j < 4; j++) sa[n][j] = 0.f;

#pragma unroll
        for (int kb = 0; kb < 8; kb++) {
#pragma unroll
            for (int nt = 0; nt < 8; nt++) {
                float2 bv = *(const float2*)(ks + (nt*8+gid)*SKT + kb*8 + 2*tig);
                float b[2] = {bv.x, bv.y};
                mma_tf32(sa[nt], qf[kb], b);
            }
        }

        float mx0 = -1e30f, mx1 = -1e30f;
#pragma unroll
        for (int n = 0; n < 8; n++) {
            mx0 = fmaxf(mx0, fmaxf(sa[n][0], sa[n][1]));
            mx1 = fmaxf(mx1, fmaxf(sa[n][2], sa[n][3]));
        }
        mx0 = fmaxf(mx0, __shfl_xor_sync(0xffffffffu, mx0, 1));
        mx0 = fmaxf(mx0, __shfl_xor_sync(0xffffffffu, mx0, 2));
        mx1 = fmaxf(mx1, __shfl_xor_sync(0xffffffffu, mx1, 1));
        mx1 = fmaxf(mx1, __shfl_xor_sync(0xffffffffu, mx1, 2));

        float nm0 = fmaxf(m0, mx0), nm1 = fmaxf(m1, mx1);
        float al0 = __expf((m0 - nm0)*scale), al1 = __expf((m1 - nm1)*scale);
        m0 = nm0; m1 = nm1;

        float rs0 = 0.f, rs1 = 0.f;
#pragma unroll
        for (int n = 0; n < 8; n++) {
            float p00 = __expf((sa[n][0] - nm0)*scale);
            float p01 = __expf((sa[n][1] - nm0)*scale);
            float p10 = __expf((sa[n][2] - nm1)*scale);
            float p11 = __expf((sa[n][3] - nm1)*scale);
            rs0 += p00 + p01; rs1 += p10 + p11;
            *(float2*)(p_s +  r0   *SPT + n*8 + 2*tig) =
                make_float2(to_tf32(p00), to_tf32(p01));
            *(float2*)(p_s + (r0+8)*SPT + n*8 + 2*tig) =
                make_float2(to_tf32(p10), to_tf32(p11));
        }
        rs0 += __shfl_xor_sync(0xffffffffu, rs0, 1);
        rs0 += __shfl_xor_sync(0xffffffffu, rs0, 2);
        rs1 += __shfl_xor_sync(0xffffffffu, rs1, 1);
        rs1 += __shfl_xor_sync(0xffffffffu, rs1, 2);
        l0 = l0*al0 + rs0; l1 = l1*al1 + rs1;

#pragma unroll
        for (int n = 0; n < 4; n++) {
            o[n][0] *= al0; o[n][1] *= al0;
            o[n][2] *= al1; o[n][3] *= al1;
        }
        __syncwarp();

        // O~ += P @ C : P fragments scalar; C^T float2 (key pairs adjacent)
#pragma unroll
        for (int kb = 0; kb < 8; kb++) {
            const int c0 = kb*8 + tig;
            float a[4];
            a[0] = p_s[ r0    *SPT + c0    ];
            a[1] = p_s[(r0+8) *SPT + c0    ];
            a[2] = p_s[ r0    *SPT + c0 + 4];
            a[3] = p_s[(r0+8) *SPT + c0 + 4];
#pragma unroll
            for (int nt = 0; nt < 4; nt++) {
                float2 bv = *(const float2*)(cs + (nt*8+gid)*SCT + kb*8 + 2*tig);
                float b[2] = {bv.x, bv.y};
                mma_tf32(o[nt], a, b);
            }
        }
        __syncthreads();

        if (kt + 2 < S_/64) issue_kv(cur, kt + 2);
        CP_COMMIT();
    }

    const float inv0 = 1.f / l0, inv1 = 1.f / l1;
    const int s0 = q0 + r0;
    float* op0 = g_ot + ((size_t)(bb*S_ + s0    )*H_ + hh)*32;
    float* op1 = g_ot + ((size_t)(bb*S_ + s0 + 8)*H_ + hh)*32;
#pragma unroll
    for (int nt = 0; nt < 4; nt++) {
        int col = nt*8 + 2*tig;
        *(float2*)(op0 + col) = make_float2(to_tf32(o[nt][0]*inv0), to_tf32(o[nt][1]*inv0));
        *(float2*)(op1 + col) = make_float2(to_tf32(o[nt][2]*inv1), to_tf32(o[nt][3]*inv1));
    }
}

// ---------------------------------------------------------------------------
// Launch 5: out = O~[8192x256] @ W_eff[256x1024] + b_eff
// ---------------------------------------------------------------------------
#define SA 36
#define SB 136
#define ABUF_FL (128*SA)
#define BBUF_FL (32*SB)
#define OUT_SMEM_FLOATS (2*ABUF_FL + 2*BBUF_FL)

__global__ void __launch_bounds__(256) out_proj_kernel(float* __restrict__ out)
{
    extern __shared__ float sm[];
    float* a_s = sm;
    float* b_s = sm + 2*ABUF_FL;
    const uint32_t smb = (uint32_t)__cvta_generic_to_shared(sm);

    const int tid  = threadIdx.x;
    const int lane = tid & 31;
    const int warp = tid >> 5;
    const int gid  = lane >> 2, tig = lane & 3;
    const int wm = warp >> 1, wn = warp & 1;
    const int col0 = blockIdx.x * 128;
    const int row0 = blockIdx.y * 128;

    auto issue_ab = [&](int s, int kc) {
        const uint32_t adst = smb + (uint32_t)(s*ABUF_FL)*4u;
        const uint32_t bdst = smb + (uint32_t)(2*ABUF_FL + s*BBUF_FL)*4u;
#pragma unroll
        for (int i = 0; i < 4; i++) {
            int idx4 = tid + i*256;
            int r = idx4 >> 3, c4 = idx4 & 7;
            cp_async16(adst + (uint32_t)(r*SA + c4*4)*4u,
                       g_ot + (size_t)(row0+r)*256 + kc*32 + c4*4);
        }
#pragma unroll
        for (int i = 0; i < 4; i++) {
            int idx4 = tid + i*256;
            int r = idx4 >> 5, c4 = idx4 & 31;
            cp_async16(bdst + (uint32_t)(r*SB + c4*4)*4u,
                       g_weff + (size_t)(kc*32+r)*DM + col0 + c4*4);
        }
    };

    float acc[2][8][4];
#pragma unroll
    for (int im = 0; im < 2; im++)
#pragma unroll
        for (int n = 0; n < 8; n++)
#pragma unroll
            for (int j = 0; j < 4; j++) acc[im][n][j] = 0.f;

    issue_ab(0, 0); CP_COMMIT();
    issue_ab(1, 1); CP_COMMIT();

    for (int kc = 0; kc < 8; kc++) {
        const int cur = kc & 1;
        CP_WAIT1();
        __syncthreads();
        const float* ap = a_s + cur*ABUF_FL;
        const float* bp = b_s + cur*BBUF_FL;

#pragma unroll
        for (int ks = 0; ks < 4; ks++) {
            const int c0 = ks*8 + tig;
            float a0[4], a1[4];
            int ra = wm*32 + gid;
            a0[0] = ap[ ra      *SA + c0    ];
            a0[1] = ap[(ra+8)   *SA + c0    ];
            a0[2] = ap[ ra      *SA + c0 + 4];
            a0[3] = ap[(ra+8)   *SA + c0 + 4];
            a1[0] = ap[(ra+16)  *SA + c0    ];
            a1[1] = ap[(ra+24)  *SA + c0    ];
            a1[2] = ap[(ra+16)  *SA + c0 + 4];
            a1[3] = ap[(ra+24)  *SA + c0 + 4];
#pragma unroll
            for (int nt = 0; nt < 8; nt++) {
                float b[2];
                int nb = wn*64 + nt*8 + gid;
                b[0] = bp[(ks*8 + tig    )*SB + nb];
                b[1] = bp[(ks*8 + tig + 4)*SB + nb];
                mma_tf32(acc[0][nt], a0, b);
                mma_tf32(acc[1][nt], a1, b);
            }
        }
        __syncthreads();
        if (kc + 2 < 8) issue_ab(cur, kc + 2);
        CP_COMMIT();
    }

#pragma unroll
    for (int im = 0; im < 2; im++) {
        int rr = row0 + wm*32 + im*16 + gid;
#pragma unroll
        for (int nt = 0; nt < 8; nt++) {
            int cc = col0 + wn*64 + nt*8 + 2*tig;
            float bx = g_beff[cc], by = g_beff[cc+1];
            *(float2*)(out + (size_t)rr*DM + cc) =
                make_float2(acc[im][nt][0] + bx, acc[im][nt][1] + by);
            *(float2*)(out + (size_t)(rr+8)*DM + cc) =
                make_float2(acc[im][nt][2] + bx, acc[im][nt][3] + by);
        }
    }
}

// ---------------------------------------------------------------------------
extern "C" void kernel_launch(void* const* d_in, const int* in_sizes, int n_in,
                              void* d_out, int out_size)
{
    (void)in_sizes; (void)n_in; (void)out_size;
    const float* h    = (const float*)d_in[0];
    const float* Wdq  = (const float*)d_in[1];
    const float* bdq  = (const float*)d_in[2];
    const float* Wuq  = (const float*)d_in[3];
    const float* buq  = (const float*)d_in[4];
    const float* Wdkv = (const float*)d_in[5];
    const float* bdkv = (const float*)d_in[6];
    const float* Wuk  = (const float*)d_in[7];
    const float* buk  = (const float*)d_in[8];   (void)buk; // cancels in softmax
    const float* Wuv  = (const float*)d_in[9];
    const float* buv  = (const float*)d_in[10];
    const float* Wqr  = (const float*)d_in[11];
    const float* bqr  = (const float*)d_in[12];
    const float* Wkr  = (const float*)d_in[13];
    const float* bkr  = (const float*)d_in[14];
    const float* Wo   = (const float*)d_in[15];
    const float* bo   = (const float*)d_in[16];
    float* out = (float*)d_out;

    cudaFuncSetAttribute(attn_kernel, cudaFuncAttributeMaxDynamicSharedMemorySize,
                         ATTN_SMEM_FLOATS * (int)sizeof(float));
    cudaFuncSetAttribute(out_proj_kernel, cudaFuncAttributeMaxDynamicSharedMemorySize,
                         OUT_SMEM_FLOATS * (int)sizeof(float));
    cudaFuncSetAttribute(down_proj_kernel, cudaFuncAttributeMaxDynamicSharedMemorySize,
                         DOWN_SMEM_FLOATS * (int)sizeof(float));

    // attn is the 4th launch (ncu capture window)
    prep_kernel<<<88, 256>>>(Wuq, buq, Wuk, Wdq, Wdkv, Wkr, Wuv, buv, Wo, bo);
    down_proj_kernel<<<BS_/128, 256, DOWN_SMEM_FLOATS * sizeof(float)>>>(h, bdq, bdkv, bkr);
    q_proj_kernel<<<dim3(BS_/64, H_), 256>>>(Wqr, bqr);
    attn_kernel<<<dim3(S_/128, B_*H_), 256, ATTN_SMEM_FLOATS * sizeof(float)>>>();
    out_proj_kernel<<<dim3(DM/128, BS_/128), 256, OUT_SMEM_FLOATS * sizeof(float)>>>(out);
}

// round 12
// speedup vs baseline: 9.2052x; 1.0464x over previous
#include <cuda_runtime.h>
#include <math.h>
#include <stdint.h>

#define B_   4
#define S_   2048
#define DM   1024
#define H_   8
#define DK   128
#define DC   32
#define DHR  32
#define BS_  (B_*S_)        // 8192

// ---------------- scratch (device globals) ----------------------------------
__device__ float g_cq  [BS_*DC];               // fp32
__device__ float g_kt  [BS_*64];               // K~ pair-permuted cols, rounded
__device__ float g_cvT [BS_*DC];               // C^T tiles [tile][col][64 rows perm]
__device__ float g_qt  [(size_t)B_*H_*S_*64];  // Q~ pair-permuted cols, rounded
__device__ float g_ot  [(size_t)BS_*H_*32];    // O~ [B,S,H*32], rounded
__device__ float g_M   [H_*DC*DC];
__device__ float g_m   [H_*DC];
__device__ float g_weff[256*DM];               // rounded
__device__ float g_beff[DM];
__device__ float g_wdown[1024*96];             // [Wdq|Wdkv|Wkr], rounded

// ---------------- helpers ----------------------------------------------------
__device__ __forceinline__ float to_tf32(float x) {
    uint32_t u;
    asm("cvt.rna.tf32.f32 %0, %1;" : "=r"(u) : "f"(x));
    return __uint_as_float(u);
}
__device__ __forceinline__ int perm8(int c) {   // (c,c+4) pairs -> adjacent
    return ((c & 3) << 1) | ((c >> 2) & 1);
}
__device__ __forceinline__ int ppos(int c) {    // permute within 8-group
    return (c & ~7) | perm8(c & 7);
}
__device__ __forceinline__ void mma_tf32(float* d, const float* a, const float* b) {
    asm("mma.sync.aligned.m16n8k8.row.col.f32.tf32.tf32.f32 "
        "{%0,%1,%2,%3}, {%4,%5,%6,%7}, {%8,%9}, {%0,%1,%2,%3};"
        : "+f"(d[0]), "+f"(d[1]), "+f"(d[2]), "+f"(d[3])
        : "r"(__float_as_uint(a[0])), "r"(__float_as_uint(a[1])),
          "r"(__float_as_uint(a[2])), "r"(__float_as_uint(a[3])),
          "r"(__float_as_uint(b[0])), "r"(__float_as_uint(b[1])));
}
__device__ __forceinline__ void cp_async16(uint32_t saddr, const void* gptr) {
    asm volatile("cp.async.cg.shared.global [%0], [%1], 16;"
                 :: "r"(saddr), "l"(gptr));
}
#define CP_COMMIT()  asm volatile("cp.async.commit_group;")
#define CP_WAIT1()   asm volatile("cp.async.wait_group 1;")

// ---------------------------------------------------------------------------
// Launch 1: merged prep. blocks 0..7: M_h,m_h; 8..19: wdown rounding;
// 20..83: W_eff; 84..87: b_eff.
// ---------------------------------------------------------------------------
__global__ void __launch_bounds__(256) prep_kernel(
    const float* __restrict__ Wuq, const float* __restrict__ buq,
    const float* __restrict__ Wuk,
    const float* __restrict__ Wdq, const float* __restrict__ Wdkv,
    const float* __restrict__ Wkr,
    const float* __restrict__ Wuv, const float* __restrict__ buv,
    const float* __restrict__ Wo,  const float* __restrict__ bo)
{
    const int tid = threadIdx.x;
    const int bx  = blockIdx.x;
    if (bx < 8) {
        const int h = bx;
        for (int idx = tid; idx < DC*DC; idx += 256) {
            int c = idx >> 5, i = idx & 31;
            float s = 0.f;
            const float* wq = Wuq + c*DM + h*DK;
            const float* wk = Wuk + i*DM + h*DK;
#pragma unroll 8
            for (int d = 0; d < DK; d++) s += wq[d]*wk[d];
            g_M[h*DC*DC + idx] = s;
        }
        if (tid < DC) {
            float s = 0.f;
            const float* wk = Wuk + tid*DM + h*DK;
#pragma unroll 8
            for (int d = 0; d < DK; d++) s += buq[h*DK + d]*wk[d];
            g_m[h*DC + tid] = s;
        }
    } else if (bx < 20) {
        int base = (bx - 8)*8192 + tid;
#pragma unroll
        for (int i = 0; i < 32; i++) {
            int idx = base + i*256;
            int k = idx / 96, c = idx - 96*k;
            float v;
            if (c < 32)      v = Wdq [k*32 + c];
            else if (c < 64) v = Wdkv[k*32 + (c-32)];
            else             v = Wkr [k*32 + (c-64)];
            g_wdown[idx] = to_tf32(v);
        }
    } else if (bx < 84) {
        const int h = (bx-20) >> 3, jt = (bx-20) & 7;
        const int i = tid >> 3, jg = tid & 7;
        const int j0 = jt*128 + jg*16;
        float acc[16];
#pragma unroll
        for (int k = 0; k < 16; k++) acc[k] = 0.f;
        for (int d = 0; d < DK; d++) {
            float wuv = Wuv[i*DM + h*DK + d];
            const float* wo = Wo + (size_t)(h*DK + d)*DM + j0;
#pragma unroll
            for (int k = 0; k < 16; k++) acc[k] += wuv*wo[k];
        }
#pragma unroll
        for (int k = 0; k < 16; k++)
            g_weff[(size_t)(h*32 + i)*DM + j0 + k] = to_tf32(acc[k]);
    } else {
        int j = (bx - 84)*256 + tid;
        float acc = bo[j];
        for (int k = 0; k < DM; k++) acc += buv[k]*Wo[(size_t)k*DM + j];
        g_beff[j] = acc;
    }
}

// ---------------------------------------------------------------------------
// Launch 2: down projections via tf32 mma (tile 128x96, K-chunk 32).
// ---------------------------------------------------------------------------
#define DSA 36
#define DSB 104
#define DABUF (128*DSA)
#define DBBUF (32*DSB)
#define DOWN_SMEM_FLOATS (2*DABUF + 2*DBBUF)

__global__ void __launch_bounds__(256) down_proj_kernel(
    const float* __restrict__ h,
    const float* __restrict__ bdq, const float* __restrict__ bdkv,
    const float* __restrict__ bkr)
{
    extern __shared__ float sm[];
    float* a_s = sm;
    float* b_s = sm + 2*DABUF;
    const uint32_t smb = (uint32_t)__cvta_generic_to_shared(sm);

    const int tid  = threadIdx.x;
    const int lane = tid & 31;
    const int warp = tid >> 5;
    const int gid  = lane >> 2, tig = lane & 3;
    const int wm = warp >> 1, wn = warp & 1;
    const int row0 = blockIdx.x * 128;

    auto issue_ab = [&](int s, int kc) {
        const uint32_t adst = smb + (uint32_t)(s*DABUF)*4u;
        const uint32_t bdst = smb + (uint32_t)(2*DABUF + s*DBBUF)*4u;
#pragma unroll
        for (int i = 0; i < 4; i++) {
            int idx4 = tid + i*256;
            int r = idx4 >> 3, c4 = idx4 & 7;
            cp_async16(adst + (uint32_t)(r*DSA + c4*4)*4u,
                       h + (size_t)(row0+r)*DM + kc*32 + c4*4);
        }
#pragma unroll
        for (int i = 0; i < 3; i++) {
            int idx4 = tid + i*256;
            int r = idx4 / 24, cc = idx4 - 24*r;
            cp_async16(bdst + (uint32_t)(r*DSB + cc*4)*4u,
                       g_wdown + (size_t)(kc*32+r)*96 + cc*4);
        }
    };

    float acc[2][6][4];
#pragma unroll
    for (int im = 0; im < 2; im++)
#pragma unroll
        for (int n = 0; n < 6; n++)
#pragma unroll
            for (int j = 0; j < 4; j++) acc[im][n][j] = 0.f;

    issue_ab(0, 0); CP_COMMIT();
    issue_ab(1, 1); CP_COMMIT();

    for (int kc = 0; kc < 32; kc++) {
        const int cur = kc & 1;
        CP_WAIT1();
        __syncthreads();
        const float* ap = a_s + cur*DABUF;
        const float* bp = b_s + cur*DBBUF;

#pragma unroll
        for (int ks = 0; ks < 4; ks++) {
            const int c0 = ks*8 + tig;
            float a0[4], a1[4];
            int ra = wm*32 + gid;
            a0[0] = ap[ ra      *DSA + c0    ];
            a0[1] = ap[(ra+8)   *DSA + c0    ];
            a0[2] = ap[ ra      *DSA + c0 + 4];
            a0[3] = ap[(ra+8)   *DSA + c0 + 4];
            a1[0] = ap[(ra+16)  *DSA + c0    ];
            a1[1] = ap[(ra+24)  *DSA + c0    ];
            a1[2] = ap[(ra+16)  *DSA + c0 + 4];
            a1[3] = ap[(ra+24)  *DSA + c0 + 4];
#pragma unroll
            for (int nt = 0; nt < 6; nt++) {
                float b[2];
                int nb = wn*48 + nt*8 + gid;
                b[0] = bp[(ks*8 + tig    )*DSB + nb];
                b[1] = bp[(ks*8 + tig + 4)*DSB + nb];
                mma_tf32(acc[0][nt], a0, b);
                mma_tf32(acc[1][nt], a1, b);
            }
        }
        __syncthreads();
        if (kc + 2 < 32) issue_ab(cur, kc + 2);
        CP_COMMIT();
    }

#pragma unroll
    for (int im = 0; im < 2; im++) {
        int rbase = row0 + wm*32 + im*16 + gid;
#pragma unroll
        for (int nt = 0; nt < 6; nt++) {
            int cc = wn*48 + nt*8 + 2*tig;
#pragma unroll
            for (int half = 0; half < 2; half++) {
                int rr = rbase + half*8;
#pragma unroll
                for (int e = 0; e < 2; e++) {
                    int col = cc + e;
                    float v = acc[im][nt][half*2 + e];
                    if (col < 32) {
                        g_cq[rr*32 + col] = v + bdq[col];
                    } else if (col < 64) {
                        float cv = to_tf32(v + bdkv[col-32]);
                        g_kt[rr*64 + ppos(col-32)] = cv;
                        int t = rr >> 6, lr = rr & 63;
                        g_cvT[((size_t)t*32 + (col-32))*64 + ppos(lr)] = cv;
                    } else {
                        g_kt[rr*64 + 32 + ppos(col-64)] =
                            to_tf32(v + bkr[col-64]);
                    }
                }
            }
        }
    }
}

// ---------------------------------------------------------------------------
// Launch 3: Q~[b,h,s,64] = [c_q@M_h+m_h | c_q@W_QR_h+b_QR_h], pair-permuted
// ---------------------------------------------------------------------------
__global__ void __launch_bounds__(256) q_proj_kernel(
    const float* __restrict__ Wqr, const float* __restrict__ bqr)
{
    __shared__ float w_s[32*64];
    __shared__ float c_s[64*32];
    __shared__ float bias_s[64];

    const int tid  = threadIdx.x;
    const int hh   = blockIdx.y;
    const int row0 = blockIdx.x * 64;

#pragma unroll
    for (int i = 0; i < 8; i++) {
        int idx = tid + i*256;
        int k = idx >> 6, c = idx & 63;
        w_s[idx] = (c < 32) ? g_M[hh*DC*DC + k*32 + c]
                            : Wqr[k*256 + hh*32 + (c-32)];
    }
    if (tid < 64)
        bias_s[tid] = (tid < 32) ? g_m[hh*DC + tid] : bqr[hh*32 + tid - 32];
#pragma unroll
    for (int i = 0; i < 8; i++) {
        int idx = tid + i*256;
        c_s[idx] = g_cq[row0*32 + idx];
    }
    __syncthreads();

    const int col = tid & 63, rg = tid >> 6;
    const int pcol = ppos(col);
    for (int rr = 0; rr < 16; rr++) {
        int r = rg*16 + rr;
        float acc = bias_s[col];
#pragma unroll
        for (int k = 0; k < 32; k++) acc += c_s[r*32 + k]*w_s[k*64 + col];
        int row = row0 + r;
        int bb = row >> 11, ss = row & 2047;
        g_qt[((size_t)(bb*H_ + hh)*S_ + ss)*64 + pcol] = to_tf32(acc);
    }
}

// ---------------------------------------------------------------------------
// Launch 4 (PROFILED): absorbed flash attention. P kept in registers and
// converted to PV a-fragments via intra-quad shuffles (no P smem round-trip).
// ---------------------------------------------------------------------------
#define SKT 72
#define SCT 72
#define KT_FL (64*SKT)
#define CT_FL (32*SCT)
#define ATTN_SMEM_FLOATS (2*KT_FL + 2*CT_FL)   // 13824 fl = 55296 B

__global__ void __launch_bounds__(256, 2) attn_kernel()
{
    extern __shared__ float sm[];
    float* kbuf = sm;                   // 2 x 64x72 (Q staging = both, 128x72)
    float* cbuf = sm + 2*KT_FL;         // 2 x 32x72
    const uint32_t smb = (uint32_t)__cvta_generic_to_shared(sm);

    const int tid  = threadIdx.x;
    const int lane = tid & 31;
    const int warp = tid >> 5;
    const int gid  = lane >> 2;
    const int tig  = lane & 3;
    const int bh   = blockIdx.y;
    const int bb   = bh >> 3, hh = bh & 7;
    const int q0   = blockIdx.x * 128;

    const float* qg = g_qt + ((size_t)bh*S_ + q0)*64;
    const float* kg = g_kt + (size_t)bb*S_*64;
    const float* cg = g_cvT + (size_t)bb*(S_/64)*2048;

    const float scale = 0.07905694150420948f;

    // ---- stage permuted Q~ (128x72 spans both K buffers), lift fragments ----
#pragma unroll
    for (int i = 0; i < 8; i++) {
        int idx4 = tid + i*256;
        int r = idx4 >> 4, c4 = idx4 & 15;
        float4 v = *(const float4*)(qg + (size_t)r*64 + c4*4);
        *(float4*)(kbuf + r*SKT + c4*4) = v;
    }
    __syncthreads();

    const int r0 = warp*16 + gid;
    float qf[8][4];
#pragma unroll
    for (int kb = 0; kb < 8; kb++) {
        float2 f0 = *(const float2*)(kbuf +  r0   *SKT + kb*8 + 2*tig);
        float2 f1 = *(const float2*)(kbuf + (r0+8)*SKT + kb*8 + 2*tig);
        qf[kb][0] = f0.x; qf[kb][1] = f1.x; qf[kb][2] = f0.y; qf[kb][3] = f1.y;
    }
    __syncthreads();

    auto issue_kv = [&](int s, int t) {
        const float* ksrc = kg + (size_t)t*64*64;
        const float* csrc = cg + (size_t)t*2048;
        const uint32_t kdst = smb + (uint32_t)(s*KT_FL)*4u;
        const uint32_t cdst = smb + (uint32_t)(2*KT_FL + s*CT_FL)*4u;
#pragma unroll
        for (int i = 0; i < 4; i++) {
            int idx4 = tid + i*256;
            int r = idx4 >> 4, c4 = idx4 & 15;
            cp_async16(kdst + (uint32_t)(r*SKT + c4*4)*4u, ksrc + r*64 + c4*4);
        }
#pragma unroll
        for (int i = 0; i < 2; i++) {
            int idx4 = tid + i*256;
            int c = idx4 >> 4, rg = idx4 & 15;
            cp_async16(cdst + (uint32_t)(c*SCT + rg*4)*4u, csrc + c*64 + rg*4);
        }
    };

    issue_kv(0, 0); CP_COMMIT();
    issue_kv(1, 1); CP_COMMIT();

    float m0 = -1e30f, m1 = -1e30f, l0 = 0.f, l1 = 0.f;
    float o[4][4];
#pragma unroll
    for (int i = 0; i < 4; i++)
#pragma unroll
        for (int j = 0; j < 4; j++) o[i][j] = 0.f;

    const int srcA = (lane & ~3) + (tig >> 1);   // quad lane holding col tig
    const int srcB = srcA + 2;                   // quad lane holding col tig+4
    const bool odd = (tig & 1);

    for (int kt = 0; kt < S_/64; kt++) {
        const int cur = kt & 1;
        CP_WAIT1();
        __syncthreads();
        const float* ks = kbuf + cur*KT_FL;
        const float* cs = cbuf + cur*CT_FL;

        // ---- S = Q~ K~^T ----
        float sa[8][4];
#pragma unroll
        for (int n = 0; n < 8; n++)
#pragma unroll
            for (int j = 0; j < 4; j++) sa[n][j] = 0.f;

#pragma unroll
        for (int kb = 0; kb < 8; kb++) {
#pragma unroll
            for (int nt = 0; nt < 8; nt++) {
                float2 bv = *(const float2*)(ks + (nt*8+gid)*SKT + kb*8 + 2*tig);
                float b[2] = {bv.x, bv.y};
                mma_tf32(sa[nt], qf[kb], b);
            }
        }

        // ---- online softmax ----
        float mx0 = -1e30f, mx1 = -1e30f;
#pragma unroll
        for (int n = 0; n < 8; n++) {
            mx0 = fmaxf(mx0, fmaxf(sa[n][0], sa[n][1]));
            mx1 = fmaxf(mx1, fmaxf(sa[n][2], sa[n][3]));
        }
        mx0 = fmaxf(mx0, __shfl_xor_sync(0xffffffffu, mx0, 1));
        mx0 = fmaxf(mx0, __shfl_xor_sync(0xffffffffu, mx0, 2));
        mx1 = fmaxf(mx1, __shfl_xor_sync(0xffffffffu, mx1, 1));
        mx1 = fmaxf(mx1, __shfl_xor_sync(0xffffffffu, mx1, 2));

        float nm0 = fmaxf(m0, mx0), nm1 = fmaxf(m1, mx1);
        float al0 = __expf((m0 - nm0)*scale), al1 = __expf((m1 - nm1)*scale);
        m0 = nm0; m1 = nm1;

#pragma unroll
        for (int n = 0; n < 4; n++) {
            o[n][0] *= al0; o[n][1] *= al0;
            o[n][2] *= al1; o[n][3] *= al1;
        }

        // ---- P (registers) -> PV, a-fragments via intra-quad shuffles ----
        float rs0 = 0.f, rs1 = 0.f;
#pragma unroll
        for (int kb = 0; kb < 8; kb++) {
            float p00 = __expf((sa[kb][0] - nm0)*scale);
            float p01 = __expf((sa[kb][1] - nm0)*scale);
            float p10 = __expf((sa[kb][2] - nm1)*scale);
            float p11 = __expf((sa[kb][3] - nm1)*scale);
            rs0 += p00 + p01; rs1 += p10 + p11;

            float q00A = __shfl_sync(0xffffffffu, p00, srcA);
            float q01A = __shfl_sync(0xffffffffu, p01, srcA);
            float q00B = __shfl_sync(0xffffffffu, p00, srcB);
            float q01B = __shfl_sync(0xffffffffu, p01, srcB);
            float q10A = __shfl_sync(0xffffffffu, p10, srcA);
            float q11A = __shfl_sync(0xffffffffu, p11, srcA);
            float q10B = __shfl_sync(0xffffffffu, p10, srcB);
            float q11B = __shfl_sync(0xffffffffu, p11, srcB);

            float a[4];
            a[0] = to_tf32(odd ? q01A : q00A);   // row r0,   key kb*8+tig
            a[1] = to_tf32(odd ? q11A : q10A);   // row r0+8, key kb*8+tig
            a[2] = to_tf32(odd ? q01B : q00B);   // row r0,   key kb*8+tig+4
            a[3] = to_tf32(odd ? q11B : q10B);   // row r0+8, key kb*8+tig+4
#pragma unroll
            for (int nt = 0; nt < 4; nt++) {
                float2 bv = *(const float2*)(cs + (nt*8+gid)*SCT + kb*8 + 2*tig);
                float b[2] = {bv.x, bv.y};
                mma_tf32(o[nt], a, b);
            }
        }
        rs0 += __shfl_xor_sync(0xffffffffu, rs0, 1);
        rs0 += __shfl_xor_sync(0xffffffffu, rs0, 2);
        rs1 += __shfl_xor_sync(0xffffffffu, rs1, 1);
        rs1 += __shfl_xor_sync(0xffffffffu, rs1, 2);
        l0 = l0*al0 + rs0; l1 = l1*al1 + rs1;

        __syncthreads();
        if (kt + 2 < S_/64) issue_kv(cur, kt + 2);
        CP_COMMIT();
    }

    const float inv0 = 1.f / l0, inv1 = 1.f / l1;
    const int s0 = q0 + r0;
    float* op0 = g_ot + ((size_t)(bb*S_ + s0    )*H_ + hh)*32;
    float* op1 = g_ot + ((size_t)(bb*S_ + s0 + 8)*H_ + hh)*32;
#pragma unroll
    for (int nt = 0; nt < 4; nt++) {
        int col = nt*8 + 2*tig;
        *(float2*)(op0 + col) = make_float2(to_tf32(o[nt][0]*inv0), to_tf32(o[nt][1]*inv0));
        *(float2*)(op1 + col) = make_float2(to_tf32(o[nt][2]*inv1), to_tf32(o[nt][3]*inv1));
    }
}

// ---------------------------------------------------------------------------
// Launch 5: out = O~[8192x256] @ W_eff[256x1024] + b_eff
// ---------------------------------------------------------------------------
#define SA 36
#define SB 136
#define ABUF_FL (128*SA)
#define BBUF_FL (32*SB)
#define OUT_SMEM_FLOATS (2*ABUF_FL + 2*BBUF_FL)

__global__ void __launch_bounds__(256) out_proj_kernel(float* __restrict__ out)
{
    extern __shared__ float sm[];
    float* a_s = sm;
    float* b_s = sm + 2*ABUF_FL;
    const uint32_t smb = (uint32_t)__cvta_generic_to_shared(sm);

    const int tid  = threadIdx.x;
    const int lane = tid & 31;
    const int warp = tid >> 5;
    const int gid  = lane >> 2, tig = lane & 3;
    const int wm = warp >> 1, wn = warp & 1;
    const int col0 = blockIdx.x * 128;
    const int row0 = blockIdx.y * 128;

    auto issue_ab = [&](int s, int kc) {
        const uint32_t adst = smb + (uint32_t)(s*ABUF_FL)*4u;
        const uint32_t bdst = smb + (uint32_t)(2*ABUF_FL + s*BBUF_FL)*4u;
#pragma unroll
        for (int i = 0; i < 4; i++) {
            int idx4 = tid + i*256;
            int r = idx4 >> 3, c4 = idx4 & 7;
            cp_async16(adst + (uint32_t)(r*SA + c4*4)*4u,
                       g_ot + (size_t)(row0+r)*256 + kc*32 + c4*4);
        }
#pragma unroll
        for (int i = 0; i < 4; i++) {
            int idx4 = tid + i*256;
            int r = idx4 >> 5, c4 = idx4 & 31;
            cp_async16(bdst + (uint32_t)(r*SB + c4*4)*4u,
                       g_weff + (size_t)(kc*32+r)*DM + col0 + c4*4);
        }
    };

    float acc[2][8][4];
#pragma unroll
    for (int im = 0; im < 2; im++)
#pragma unroll
        for (int n = 0; n < 8; n++)
#pragma unroll
            for (int j = 0; j < 4; j++) acc[im][n][j] = 0.f;

    issue_ab(0, 0); CP_COMMIT();
    issue_ab(1, 1); CP_COMMIT();

    for (int kc = 0; kc < 8; kc++) {
        const int cur = kc & 1;
        CP_WAIT1();
        __syncthreads();
        const float* ap = a_s + cur*ABUF_FL;
        const float* bp = b_s + cur*BBUF_FL;

#pragma unroll
        for (int ks = 0; ks < 4; ks++) {
            const int c0 = ks*8 + tig;
            float a0[4], a1[4];
            int ra = wm*32 + gid;
            a0[0] = ap[ ra      *SA + c0    ];
            a0[1] = ap[(ra+8)   *SA + c0    ];
            a0[2] = ap[ ra      *SA + c0 + 4];
            a0[3] = ap[(ra+8)   *SA + c0 + 4];
            a1[0] = ap[(ra+16)  *SA + c0    ];
            a1[1] = ap[(ra+24)  *SA + c0    ];
            a1[2] = ap[(ra+16)  *SA + c0 + 4];
            a1[3] = ap[(ra+24)  *SA + c0 + 4];
#pragma unroll
            for (int nt = 0; nt < 8; nt++) {
                float b[2];
                int nb = wn*64 + nt*8 + gid;
                b[0] = bp[(ks*8 + tig    )*SB + nb];
                b[1] = bp[(ks*8 + tig + 4)*SB + nb];
                mma_tf32(acc[0][nt], a0, b);
                mma_tf32(acc[1][nt], a1, b);
            }
        }
        __syncthreads();
        if (kc + 2 < 8) issue_ab(cur, kc + 2);
        CP_COMMIT();
    }

#pragma unroll
    for (int im = 0; im < 2; im++) {
        int rr = row0 + wm*32 + im*16 + gid;
#pragma unroll
        for (int nt = 0; nt < 8; nt++) {
            int cc = col0 + wn*64 + nt*8 + 2*tig;
            float bx = g_beff[cc], by = g_beff[cc+1];
            *(float2*)(out + (size_t)rr*DM + cc) =
                make_float2(acc[im][nt][0] + bx, acc[im][nt][1] + by);
            *(float2*)(out + (size_t)(rr+8)*DM + cc) =
                make_float2(acc[im][nt][2] + bx, acc[im][nt][3] + by);
        }
    }
}

// ---------------------------------------------------------------------------
extern "C" void kernel_launch(void* const* d_in, const int* in_sizes, int n_in,
                              void* d_out, int out_size)
{
    (void)in_sizes; (void)n_in; (void)out_size;
    const float* h    = (const float*)d_in[0];
    const float* Wdq  = (const float*)d_in[1];
    const float* bdq  = (const float*)d_in[2];
    const float* Wuq  = (const float*)d_in[3];
    const float* buq  = (const float*)d_in[4];
    const float* Wdkv = (const float*)d_in[5];
    const float* bdkv = (const float*)d_in[6];
    const float* Wuk  = (const float*)d_in[7];
    const float* buk  = (const float*)d_in[8];   (void)buk; // cancels in softmax
    const float* Wuv  = (const float*)d_in[9];
    const float* buv  = (const float*)d_in[10];
    const float* Wqr  = (const float*)d_in[11];
    const float* bqr  = (const float*)d_in[12];
    const float* Wkr  = (const float*)d_in[13];
    const float* bkr  = (const float*)d_in[14];
    const float* Wo   = (const float*)d_in[15];
    const float* bo   = (const float*)d_in[16];
    float* out = (float*)d_out;

    cudaFuncSetAttribute(attn_kernel, cudaFuncAttributeMaxDynamicSharedMemorySize,
                         ATTN_SMEM_FLOATS * (int)sizeof(float));
    cudaFuncSetAttribute(out_proj_kernel, cudaFuncAttributeMaxDynamicSharedMemorySize,
                         OUT_SMEM_FLOATS * (int)sizeof(float));
    cudaFuncSetAttribute(down_proj_kernel, cudaFuncAttributeMaxDynamicSharedMemorySize,
                         DOWN_SMEM_FLOATS * (int)sizeof(float));

    // attn is the 4th launch (ncu capture window)
    prep_kernel<<<88, 256>>>(Wuq, buq, Wuk, Wdq, Wdkv, Wkr, Wuv, buv, Wo, bo);
    down_proj_kernel<<<BS_/128, 256, DOWN_SMEM_FLOATS * sizeof(float)>>>(h, bdq, bdkv, bkr);
    q_proj_kernel<<<dim3(BS_/64, H_), 256>>>(Wqr, bqr);
    attn_kernel<<<dim3(S_/128, B_*H_), 256, ATTN_SMEM_FLOATS * sizeof(float)>>>();
    out_proj_kernel<<<dim3(DM/128, BS_/128), 256, OUT_SMEM_FLOATS * sizeof(float)>>>(out);
}

// round 13
// speedup vs baseline: 9.4737x; 1.0292x over previous
#include <cuda_runtime.h>
#include <math.h>
#include <stdint.h>

#define B_   4
#define S_   2048
#define DM   1024
#define H_   8
#define DK   128
#define DC   32
#define DHR  32
#define BS_  (B_*S_)        // 8192

// ---------------- scratch (device globals) ----------------------------------
__device__ float g_cq  [BS_*DC];               // fp32
__device__ float g_kt  [BS_*64];               // K~ pair-permuted cols, rounded
__device__ float g_cvT [BS_*DC];               // C^T tiles [tile][col][64 rows perm]
__device__ float g_qt  [(size_t)B_*H_*S_*64];  // Q~ pair-permuted, PRE-SCALED, rounded
__device__ float g_ot  [(size_t)BS_*H_*32];    // O~ [B,S,H*32], rounded
__device__ float g_M   [H_*DC*DC];
__device__ float g_m   [H_*DC];
__device__ float g_weff[256*DM];               // rounded
__device__ float g_beff[DM];
__device__ float g_wdown[1024*96];             // [Wdq|Wdkv|Wkr], rounded

// ---------------- helpers ----------------------------------------------------
__device__ __forceinline__ float to_tf32(float x) {
    uint32_t u;
    asm("cvt.rna.tf32.f32 %0, %1;" : "=r"(u) : "f"(x));
    return __uint_as_float(u);
}
__device__ __forceinline__ int perm8(int c) {
    return ((c & 3) << 1) | ((c >> 2) & 1);
}
__device__ __forceinline__ int ppos(int c) {
    return (c & ~7) | perm8(c & 7);
}
__device__ __forceinline__ void mma_tf32(float* d, const float* a, const float* b) {
    asm("mma.sync.aligned.m16n8k8.row.col.f32.tf32.tf32.f32 "
        "{%0,%1,%2,%3}, {%4,%5,%6,%7}, {%8,%9}, {%0,%1,%2,%3};"
        : "+f"(d[0]), "+f"(d[1]), "+f"(d[2]), "+f"(d[3])
        : "r"(__float_as_uint(a[0])), "r"(__float_as_uint(a[1])),
          "r"(__float_as_uint(a[2])), "r"(__float_as_uint(a[3])),
          "r"(__float_as_uint(b[0])), "r"(__float_as_uint(b[1])));
}
__device__ __forceinline__ void cp_async16(uint32_t saddr, const void* gptr) {
    asm volatile("cp.async.cg.shared.global [%0], [%1], 16;"
                 :: "r"(saddr), "l"(gptr));
}
#define CP_COMMIT()  asm volatile("cp.async.commit_group;")
#define CP_WAIT1()   asm volatile("cp.async.wait_group 1;")

// ---------------------------------------------------------------------------
// Launch 1: merged prep. blocks 0..7: M_h,m_h; 8..19: wdown rounding;
// 20..83: W_eff; 84..115: b_eff (32 j-blocks, 8-way k-split each).
// ---------------------------------------------------------------------------
__global__ void __launch_bounds__(256) prep_kernel(
    const float* __restrict__ Wuq, const float* __restrict__ buq,
    const float* __restrict__ Wuk,
    const float* __restrict__ Wdq, const float* __restrict__ Wdkv,
    const float* __restrict__ Wkr,
    const float* __restrict__ Wuv, const float* __restrict__ buv,
    const float* __restrict__ Wo,  const float* __restrict__ bo)
{
    const int tid = threadIdx.x;
    const int bx  = blockIdx.x;
    if (bx < 8) {
        const int h = bx;
        for (int idx = tid; idx < DC*DC; idx += 256) {
            int c = idx >> 5, i = idx & 31;
            float s = 0.f;
            const float* wq = Wuq + c*DM + h*DK;
            const float* wk = Wuk + i*DM + h*DK;
#pragma unroll 8
            for (int d = 0; d < DK; d++) s += wq[d]*wk[d];
            g_M[h*DC*DC + idx] = s;
        }
        if (tid < DC) {
            float s = 0.f;
            const float* wk = Wuk + tid*DM + h*DK;
#pragma unroll 8
            for (int d = 0; d < DK; d++) s += buq[h*DK + d]*wk[d];
            g_m[h*DC + tid] = s;
        }
    } else if (bx < 20) {
        int base = (bx - 8)*8192 + tid;
#pragma unroll
        for (int i = 0; i < 32; i++) {
            int idx = base + i*256;
            int k = idx / 96, c = idx - 96*k;
            float v;
            if (c < 32)      v = Wdq [k*32 + c];
            else if (c < 64) v = Wdkv[k*32 + (c-32)];
            else             v = Wkr [k*32 + (c-64)];
            g_wdown[idx] = to_tf32(v);
        }
    } else if (bx < 84) {
        const int h = (bx-20) >> 3, jt = (bx-20) & 7;
        const int i = tid >> 3, jg = tid & 7;
        const int j0 = jt*128 + jg*16;
        float acc[16];
#pragma unroll
        for (int k = 0; k < 16; k++) acc[k] = 0.f;
        for (int d = 0; d < DK; d++) {
            float wuv = Wuv[i*DM + h*DK + d];
            const float* wo = Wo + (size_t)(h*DK + d)*DM + j0;
#pragma unroll
            for (int k = 0; k < 16; k++) acc[k] += wuv*wo[k];
        }
#pragma unroll
        for (int k = 0; k < 16; k++)
            g_weff[(size_t)(h*32 + i)*DM + j0 + k] = to_tf32(acc[k]);
    } else {
        // b_eff: 32 blocks, each 32 j-cols, 8-way k-split + smem reduce
        __shared__ float red[8][32];
        const int j0 = (bx - 84)*32;
        const int jj = tid & 31, ks = tid >> 5;   // ks 0..7
        float s = 0.f;
        const int k0 = ks*128;
        for (int k = 0; k < 128; k++)
            s += buv[k0 + k]*Wo[(size_t)(k0 + k)*DM + j0 + jj];
        red[ks][jj] = s;
        __syncthreads();
        if (ks == 0) {
            float acc = bo[j0 + jj];
#pragma unroll
            for (int r = 0; r < 8; r++) acc += red[r][jj];
            g_beff[j0 + jj] = acc;
        }
    }
}

// ---------------------------------------------------------------------------
// Launch 2: down projections via tf32 mma (tile 128x96, K-chunk 32).
// ---------------------------------------------------------------------------
#define DSA 36
#define DSB 104
#define DABUF (128*DSA)
#define DBBUF (32*DSB)
#define DOWN_SMEM_FLOATS (2*DABUF + 2*DBBUF)

__global__ void __launch_bounds__(256) down_proj_kernel(
    const float* __restrict__ h,
    const float* __restrict__ bdq, const float* __restrict__ bdkv,
    const float* __restrict__ bkr)
{
    extern __shared__ float sm[];
    float* a_s = sm;
    float* b_s = sm + 2*DABUF;
    const uint32_t smb = (uint32_t)__cvta_generic_to_shared(sm);

    const int tid  = threadIdx.x;
    const int lane = tid & 31;
    const int warp = tid >> 5;
    const int gid  = lane >> 2, tig = lane & 3;
    const int wm = warp >> 1, wn = warp & 1;
    const int row0 = blockIdx.x * 128;

    auto issue_ab = [&](int s, int kc) {
        const uint32_t adst = smb + (uint32_t)(s*DABUF)*4u;
        const uint32_t bdst = smb + (uint32_t)(2*DABUF + s*DBBUF)*4u;
#pragma unroll
        for (int i = 0; i < 4; i++) {
            int idx4 = tid + i*256;
            int r = idx4 >> 3, c4 = idx4 & 7;
            cp_async16(adst + (uint32_t)(r*DSA + c4*4)*4u,
                       h + (size_t)(row0+r)*DM + kc*32 + c4*4);
        }
#pragma unroll
        for (int i = 0; i < 3; i++) {
            int idx4 = tid + i*256;
            int r = idx4 / 24, cc = idx4 - 24*r;
            cp_async16(bdst + (uint32_t)(r*DSB + cc*4)*4u,
                       g_wdown + (size_t)(kc*32+r)*96 + cc*4);
        }
    };

    float acc[2][6][4];
#pragma unroll
    for (int im = 0; im < 2; im++)
#pragma unroll
        for (int n = 0; n < 6; n++)
#pragma unroll
            for (int j = 0; j < 4; j++) acc[im][n][j] = 0.f;

    issue_ab(0, 0); CP_COMMIT();
    issue_ab(1, 1); CP_COMMIT();

    for (int kc = 0; kc < 32; kc++) {
        const int cur = kc & 1;
        CP_WAIT1();
        __syncthreads();
        const float* ap = a_s + cur*DABUF;
        const float* bp = b_s + cur*DBBUF;

#pragma unroll
        for (int ks = 0; ks < 4; ks++) {
            const int c0 = ks*8 + tig;
            float a0[4], a1[4];
            int ra = wm*32 + gid;
            a0[0] = ap[ ra      *DSA + c0    ];
            a0[1] = ap[(ra+8)   *DSA + c0    ];
            a0[2] = ap[ ra      *DSA + c0 + 4];
            a0[3] = ap[(ra+8)   *DSA + c0 + 4];
            a1[0] = ap[(ra+16)  *DSA + c0    ];
            a1[1] = ap[(ra+24)  *DSA + c0    ];
            a1[2] = ap[(ra+16)  *DSA + c0 + 4];
            a1[3] = ap[(ra+24)  *DSA + c0 + 4];
#pragma unroll
            for (int nt = 0; nt < 6; nt++) {
                float b[2];
                int nb = wn*48 + nt*8 + gid;
                b[0] = bp[(ks*8 + tig    )*DSB + nb];
                b[1] = bp[(ks*8 + tig + 4)*DSB + nb];
                mma_tf32(acc[0][nt], a0, b);
                mma_tf32(acc[1][nt], a1, b);
            }
        }
        __syncthreads();
        if (kc + 2 < 32) issue_ab(cur, kc + 2);
        CP_COMMIT();
    }

#pragma unroll
    for (int im = 0; im < 2; im++) {
        int rbase = row0 + wm*32 + im*16 + gid;
#pragma unroll
        for (int nt = 0; nt < 6; nt++) {
            int cc = wn*48 + nt*8 + 2*tig;
#pragma unroll
            for (int half = 0; half < 2; half++) {
                int rr = rbase + half*8;
#pragma unroll
                for (int e = 0; e < 2; e++) {
                    int col = cc + e;
                    float v = acc[im][nt][half*2 + e];
                    if (col < 32) {
                        g_cq[rr*32 + col] = v + bdq[col];
                    } else if (col < 64) {
                        float cv = to_tf32(v + bdkv[col-32]);
                        g_kt[rr*64 + ppos(col-32)] = cv;
                        int t = rr >> 6, lr = rr & 63;
                        g_cvT[((size_t)t*32 + (col-32))*64 + ppos(lr)] = cv;
                    } else {
                        g_kt[rr*64 + 32 + ppos(col-64)] =
                            to_tf32(v + bkr[col-64]);
                    }
                }
            }
        }
    }
}

// ---------------------------------------------------------------------------
// Launch 3: Q~ = scale * [c_q@M_h+m_h | c_q@W_QR_h+b_QR_h], pair-permuted
// ---------------------------------------------------------------------------
__global__ void __launch_bounds__(256) q_proj_kernel(
    const float* __restrict__ Wqr, const float* __restrict__ bqr)
{
    __shared__ float w_s[32*64];
    __shared__ float c_s[64*32];
    __shared__ float bias_s[64];

    const int tid  = threadIdx.x;
    const int hh   = blockIdx.y;
    const int row0 = blockIdx.x * 64;
    const float scale = 0.07905694150420948f;   // 1/sqrt(160)

#pragma unroll
    for (int i = 0; i < 8; i++) {
        int idx = tid + i*256;
        int k = idx >> 6, c = idx & 63;
        w_s[idx] = (c < 32) ? g_M[hh*DC*DC + k*32 + c]
                            : Wqr[k*256 + hh*32 + (c-32)];
    }
    if (tid < 64)
        bias_s[tid] = (tid < 32) ? g_m[hh*DC + tid] : bqr[hh*32 + tid - 32];
#pragma unroll
    for (int i = 0; i < 8; i++) {
        int idx = tid + i*256;
        c_s[idx] = g_cq[row0*32 + idx];
    }
    __syncthreads();

    const int col = tid & 63, rg = tid >> 6;
    const int pcol = ppos(col);
    for (int rr = 0; rr < 16; rr++) {
        int r = rg*16 + rr;
        float acc = bias_s[col];
#pragma unroll
        for (int k = 0; k < 32; k++) acc += c_s[r*32 + k]*w_s[k*64 + col];
        int row = row0 + r;
        int bb = row >> 11, ss = row & 2047;
        g_qt[((size_t)(bb*H_ + hh)*S_ + ss)*64 + pcol] = to_tf32(acc * scale);
    }
}

// ---------------------------------------------------------------------------
// Launch 4 (PROFILED): absorbed flash attention. 512 threads, q-tile 256,
// dedicated Q smem region, P via intra-quad shuffles. Q pre-scaled.
// ---------------------------------------------------------------------------
#define SKT 72
#define SCT 72
#define KT_FL (64*SKT)       // 4608
#define CT_FL (32*SCT)       // 2304
#define QBUF_FL (256*SKT)    // 18432
#define ATTN_SMEM_FLOATS (QBUF_FL + 2*KT_FL + 2*CT_FL)   // 32256 fl = 129024 B

__global__ void __launch_bounds__(512, 1) attn_kernel()
{
    extern __shared__ float sm[];
    float* qbuf = sm;                        // 256 x 72
    float* kbuf = sm + QBUF_FL;              // 2 x 64x72
    float* cbuf = kbuf + 2*KT_FL;            // 2 x 32x72
    const uint32_t smb = (uint32_t)__cvta_generic_to_shared(sm);

    const int tid  = threadIdx.x;
    const int lane = tid & 31;
    const int warp = tid >> 5;               // 0..15
    const int gid  = lane >> 2;
    const int tig  = lane & 3;
    const int bh   = blockIdx.y;
    const int bb   = bh >> 3, hh = bh & 7;
    const int q0   = blockIdx.x * 256;

    const float* qg = g_qt + ((size_t)bh*S_ + q0)*64;
    const float* kg = g_kt + (size_t)bb*S_*64;
    const float* cg = g_cvT + (size_t)bb*(S_/64)*2048;

    // ---- stage Q~ (256x64) into qbuf, lift fragments ----
#pragma unroll
    for (int i = 0; i < 8; i++) {
        int idx4 = tid + i*512;
        int r = idx4 >> 4, c4 = idx4 & 15;
        float4 v = *(const float4*)(qg + (size_t)r*64 + c4*4);
        *(float4*)(qbuf + r*SKT + c4*4) = v;
    }
    __syncthreads();

    const int r0 = warp*16 + gid;
    float qf[8][4];
#pragma unroll
    for (int kb = 0; kb < 8; kb++) {
        float2 f0 = *(const float2*)(qbuf +  r0   *SKT + kb*8 + 2*tig);
        float2 f1 = *(const float2*)(qbuf + (r0+8)*SKT + kb*8 + 2*tig);
        qf[kb][0] = f0.x; qf[kb][1] = f1.x; qf[kb][2] = f0.y; qf[kb][3] = f1.y;
    }

    auto issue_kv = [&](int s, int t) {
        const float* ksrc = kg + (size_t)t*64*64;
        const float* csrc = cg + (size_t)t*2048;
        const uint32_t kdst = smb + (uint32_t)(QBUF_FL + s*KT_FL)*4u;
        const uint32_t cdst = smb + (uint32_t)(QBUF_FL + 2*KT_FL + s*CT_FL)*4u;
        // K~: 1024 float4 -> 2/thread
#pragma unroll
        for (int i = 0; i < 2; i++) {
            int idx4 = tid + i*512;
            int r = idx4 >> 4, c4 = idx4 & 15;
            cp_async16(kdst + (uint32_t)(r*SKT + c4*4)*4u, ksrc + r*64 + c4*4);
        }
        // C^T: 512 float4 -> 1/thread
        {
            int c = tid >> 4, rg = tid & 15;
            cp_async16(cdst + (uint32_t)(c*SCT + rg*4)*4u, csrc + c*64 + rg*4);
        }
    };

    issue_kv(0, 0); CP_COMMIT();
    issue_kv(1, 1); CP_COMMIT();

    float m0 = -1e30f, m1 = -1e30f, l0 = 0.f, l1 = 0.f;
    float o[4][4];
#pragma unroll
    for (int i = 0; i < 4; i++)
#pragma unroll
        for (int j = 0; j < 4; j++) o[i][j] = 0.f;

    const int srcA = (lane & ~3) + (tig >> 1);
    const int srcB = srcA + 2;
    const bool odd = (tig & 1);

    for (int kt = 0; kt < S_/64; kt++) {
        const int cur = kt & 1;
        CP_WAIT1();
        __syncthreads();
        const float* ks = kbuf + cur*KT_FL;
        const float* cs = cbuf + cur*CT_FL;

        // ---- S = Q~ K~^T (scores already scaled via Q) ----
        float sa[8][4];
#pragma unroll
        for (int n = 0; n < 8; n++)
#pragma unroll
            for (int j = 0; j < 4; j++) sa[n][j] = 0.f;

#pragma unroll
        for (int kb = 0; kb < 8; kb++) {
#pragma unroll
            for (int nt = 0; nt < 8; nt++) {
                float2 bv = *(const float2*)(ks + (nt*8+gid)*SKT + kb*8 + 2*tig);
                float b[2] = {bv.x, bv.y};
                mma_tf32(sa[nt], qf[kb], b);
            }
        }

        // ---- online softmax ----
        float mx0 = -1e30f, mx1 = -1e30f;
#pragma unroll
        for (int n = 0; n < 8; n++) {
            mx0 = fmaxf(mx0, fmaxf(sa[n][0], sa[n][1]));
            mx1 = fmaxf(mx1, fmaxf(sa[n][2], sa[n][3]));
        }
        mx0 = fmaxf(mx0, __shfl_xor_sync(0xffffffffu, mx0, 1));
        mx0 = fmaxf(mx0, __shfl_xor_sync(0xffffffffu, mx0, 2));
        mx1 = fmaxf(mx1, __shfl_xor_sync(0xffffffffu, mx1, 1));
        mx1 = fmaxf(mx1, __shfl_xor_sync(0xffffffffu, mx1, 2));

        float nm0 = fmaxf(m0, mx0), nm1 = fmaxf(m1, mx1);
        float al0 = __expf(m0 - nm0), al1 = __expf(m1 - nm1);
        m0 = nm0; m1 = nm1;

#pragma unroll
        for (int n = 0; n < 4; n++) {
            o[n][0] *= al0; o[n][1] *= al0;
            o[n][2] *= al1; o[n][3] *= al1;
        }

        // ---- P (registers) -> PV via intra-quad shuffles ----
        float rs0 = 0.f, rs1 = 0.f;
#pragma unroll
        for (int kb = 0; kb < 8; kb++) {
            float p00 = __expf(sa[kb][0] - nm0);
            float p01 = __expf(sa[kb][1] - nm0);
            float p10 = __expf(sa[kb][2] - nm1);
            float p11 = __expf(sa[kb][3] - nm1);
            rs0 += p00 + p01; rs1 += p10 + p11;

            float q00A = __shfl_sync(0xffffffffu, p00, srcA);
            float q01A = __shfl_sync(0xffffffffu, p01, srcA);
            float q00B = __shfl_sync(0xffffffffu, p00, srcB);
            float q01B = __shfl_sync(0xffffffffu, p01, srcB);
            float q10A = __shfl_sync(0xffffffffu, p10, srcA);
            float q11A = __shfl_sync(0xffffffffu, p11, srcA);
            float q10B = __shfl_sync(0xffffffffu, p10, srcB);
            float q11B = __shfl_sync(0xffffffffu, p11, srcB);

            float a[4];
            a[0] = to_tf32(odd ? q01A : q00A);
            a[1] = to_tf32(odd ? q11A : q10A);
            a[2] = to_tf32(odd ? q01B : q00B);
            a[3] = to_tf32(odd ? q11B : q10B);
#pragma unroll
            for (int nt = 0; nt < 4; nt++) {
                float2 bv = *(const float2*)(cs + (nt*8+gid)*SCT + kb*8 + 2*tig);
                float b[2] = {bv.x, bv.y};
                mma_tf32(o[nt], a, b);
            }
        }
        rs0 += __shfl_xor_sync(0xffffffffu, rs0, 1);
        rs0 += __shfl_xor_sync(0xffffffffu, rs0, 2);
        rs1 += __shfl_xor_sync(0xffffffffu, rs1, 1);
        rs1 += __shfl_xor_sync(0xffffffffu, rs1, 2);
        l0 = l0*al0 + rs0; l1 = l1*al1 + rs1;

        __syncthreads();
        if (kt + 2 < S_/64) issue_kv(cur, kt + 2);
        CP_COMMIT();
    }

    const float inv0 = 1.f / l0, inv1 = 1.f / l1;
    const int s0 = q0 + r0;
    float* op0 = g_ot + ((size_t)(bb*S_ + s0    )*H_ + hh)*32;
    float* op1 = g_ot + ((size_t)(bb*S_ + s0 + 8)*H_ + hh)*32;
#pragma unroll
    for (int nt = 0; nt < 4; nt++) {
        int col = nt*8 + 2*tig;
        *(float2*)(op0 + col) = make_float2(to_tf32(o[nt][0]*inv0), to_tf32(o[nt][1]*inv0));
        *(float2*)(op1 + col) = make_float2(to_tf32(o[nt][2]*inv1), to_tf32(o[nt][3]*inv1));
    }
}

// ---------------------------------------------------------------------------
// Launch 5: out = O~[8192x256] @ W_eff[256x1024] + b_eff
// ---------------------------------------------------------------------------
#define SA 36
#define SB 136
#define ABUF_FL (128*SA)
#define BBUF_FL (32*SB)
#define OUT_SMEM_FLOATS (2*ABUF_FL + 2*BBUF_FL)

__global__ void __launch_bounds__(256) out_proj_kernel(float* __restrict__ out)
{
    extern __shared__ float sm[];
    float* a_s = sm;
    float* b_s = sm + 2*ABUF_FL;
    const uint32_t smb = (uint32_t)__cvta_generic_to_shared(sm);

    const int tid  = threadIdx.x;
    const int lane = tid & 31;
    const int warp = tid >> 5;
    const int gid  = lane >> 2, tig = lane & 3;
    const int wm = warp >> 1, wn = warp & 1;
    const int col0 = blockIdx.x * 128;
    const int row0 = blockIdx.y * 128;

    auto issue_ab = [&](int s, int kc) {
        const uint32_t adst = smb + (uint32_t)(s*ABUF_FL)*4u;
        const uint32_t bdst = smb + (uint32_t)(2*ABUF_FL + s*BBUF_FL)*4u;
#pragma unroll
        for (int i = 0; i < 4; i++) {
            int idx4 = tid + i*256;
            int r = idx4 >> 3, c4 = idx4 & 7;
            cp_async16(adst + (uint32_t)(r*SA + c4*4)*4u,
                       g_ot + (size_t)(row0+r)*256 + kc*32 + c4*4);
        }
#pragma unroll
        for (int i = 0; i < 4; i++) {
            int idx4 = tid + i*256;
            int r = idx4 >> 5, c4 = idx4 & 31;
            cp_async16(bdst + (uint32_t)(r*SB + c4*4)*4u,
                       g_weff + (size_t)(kc*32+r)*DM + col0 + c4*4);
        }
    };

    float acc[2][8][4];
#pragma unroll
    for (int im = 0; im < 2; im++)
#pragma unroll
        for (int n = 0; n < 8; n++)
#pragma unroll
            for (int j = 0; j < 4; j++) acc[im][n][j] = 0.f;

    issue_ab(0, 0); CP_COMMIT();
    issue_ab(1, 1); CP_COMMIT();

    for (int kc = 0; kc < 8; kc++) {
        const int cur = kc & 1;
        CP_WAIT1();
        __syncthreads();
        const float* ap = a_s + cur*ABUF_FL;
        const float* bp = b_s + cur*BBUF_FL;

#pragma unroll
        for (int ks = 0; ks < 4; ks++) {
            const int c0 = ks*8 + tig;
            float a0[4], a1[4];
            int ra = wm*32 + gid;
            a0[0] = ap[ ra      *SA + c0    ];
            a0[1] = ap[(ra+8)   *SA + c0    ];
            a0[2] = ap[ ra      *SA + c0 + 4];
            a0[3] = ap[(ra+8)   *SA + c0 + 4];
            a1[0] = ap[(ra+16)  *SA + c0    ];
            a1[1] = ap[(ra+24)  *SA + c0    ];
            a1[2] = ap[(ra+16)  *SA + c0 + 4];
            a1[3] = ap[(ra+24)  *SA + c0 + 4];
#pragma unroll
            for (int nt = 0; nt < 8; nt++) {
                float b[2];
                int nb = wn*64 + nt*8 + gid;
                b[0] = bp[(ks*8 + tig    )*SB + nb];
                b[1] = bp[(ks*8 + tig + 4)*SB + nb];
                mma_tf32(acc[0][nt], a0, b);
                mma_tf32(acc[1][nt], a1, b);
            }
        }
        __syncthreads();
        if (kc + 2 < 8) issue_ab(cur, kc + 2);
        CP_COMMIT();
    }

#pragma unroll
    for (int im = 0; im < 2; im++) {
        int rr = row0 + wm*32 + im*16 + gid;
#pragma unroll
        for (int nt = 0; nt < 8; nt++) {
            int cc = col0 + wn*64 + nt*8 + 2*tig;
            float bx = g_beff[cc], by = g_beff[cc+1];
            *(float2*)(out + (size_t)rr*DM + cc) =
                make_float2(acc[im][nt][0] + bx, acc[im][nt][1] + by);
            *(float2*)(out + (size_t)(rr+8)*DM + cc) =
                make_float2(acc[im][nt][2] + bx, acc[im][nt][3] + by);
        }
    }
}

// ---------------------------------------------------------------------------
extern "C" void kernel_launch(void* const* d_in, const int* in_sizes, int n_in,
                              void* d_out, int out_size)
{
    (void)in_sizes; (void)n_in; (void)out_size;
    const float* h    = (const float*)d_in[0];
    const float* Wdq  = (const float*)d_in[1];
    const float* bdq  = (const float*)d_in[2];
    const float* Wuq  = (const float*)d_in[3];
    const float* buq  = (const float*)d_in[4];
    const float* Wdkv = (const float*)d_in[5];
    const float* bdkv = (const float*)d_in[6];
    const float* Wuk  = (const float*)d_in[7];
    const float* buk  = (const float*)d_in[8];   (void)buk; // cancels in softmax
    const float* Wuv  = (const float*)d_in[9];
    const float* buv  = (const float*)d_in[10];
    const float* Wqr  = (const float*)d_in[11];
    const float* bqr  = (const float*)d_in[12];
    const float* Wkr  = (const float*)d_in[13];
    const float* bkr  = (const float*)d_in[14];
    const float* Wo   = (const float*)d_in[15];
    const float* bo   = (const float*)d_in[16];
    float* out = (float*)d_out;

    cudaFuncSetAttribute(attn_kernel, cudaFuncAttributeMaxDynamicSharedMemorySize,
                         ATTN_SMEM_FLOATS * (int)sizeof(float));
    cudaFuncSetAttribute(out_proj_kernel, cudaFuncAttributeMaxDynamicSharedMemorySize,
                         OUT_SMEM_FLOATS * (int)sizeof(float));
    cudaFuncSetAttribute(down_proj_kernel, cudaFuncAttributeMaxDynamicSharedMemorySize,
                         DOWN_SMEM_FLOATS * (int)sizeof(float));

    // attn is the 4th launch (ncu capture window)
    prep_kernel<<<116, 256>>>(Wuq, buq, Wuk, Wdq, Wdkv, Wkr, Wuv, buv, Wo, bo);
    down_proj_kernel<<<BS_/128, 256, DOWN_SMEM_FLOATS * sizeof(float)>>>(h, bdq, bdkv, bkr);
    q_proj_kernel<<<dim3(BS_/64, H_), 256>>>(Wqr, bqr);
    attn_kernel<<<dim3(S_/256, B_*H_), 512, ATTN_SMEM_FLOATS * sizeof(float)>>>();
    out_proj_kernel<<<dim3(DM/128, BS_/128), 256, OUT_SMEM_FLOATS * sizeof(float)>>>(out);
}

// round 14
// speedup vs baseline: 9.5818x; 1.0114x over previous
#include <cuda_runtime.h>
#include <math.h>
#include <stdint.h>

#define B_   4
#define S_   2048
#define DM   1024
#define H_   8
#define DK   128
#define DC   32
#define DHR  32
#define BS_  (B_*S_)        // 8192

// ---------------- scratch (device globals) ----------------------------------
__device__ float g_cq  [BS_*DC];               // fp32
__device__ float g_kt  [BS_*64];               // K~ pair-permuted cols, rounded
__device__ float g_cvT [BS_*DC];               // C^T tiles [tile][col][64 rows perm]
__device__ float g_qt  [(size_t)B_*H_*S_*64];  // Q~ pair-permuted, PRE-SCALED, rounded
__device__ float g_ot  [(size_t)BS_*H_*32];    // O~ [B,S,H*32], rounded
__device__ float g_M   [H_*DC*DC];
__device__ float g_m   [H_*DC];
__device__ float g_weff[256*DM];               // rounded
__device__ float g_beff[DM];
__device__ float g_wdown[1024*96];             // [Wdq|Wdkv|Wkr], rounded

// ---------------- helpers ----------------------------------------------------
__device__ __forceinline__ float to_tf32(float x) {
    uint32_t u;
    asm("cvt.rna.tf32.f32 %0, %1;" : "=r"(u) : "f"(x));
    return __uint_as_float(u);
}
__device__ __forceinline__ int perm8(int c) {
    return ((c & 3) << 1) | ((c >> 2) & 1);
}
__device__ __forceinline__ int ppos(int c) {
    return (c & ~7) | perm8(c & 7);
}
__device__ __forceinline__ void mma_tf32(float* d, const float* a, const float* b) {
    asm("mma.sync.aligned.m16n8k8.row.col.f32.tf32.tf32.f32 "
        "{%0,%1,%2,%3}, {%4,%5,%6,%7}, {%8,%9}, {%0,%1,%2,%3};"
        : "+f"(d[0]), "+f"(d[1]), "+f"(d[2]), "+f"(d[3])
        : "r"(__float_as_uint(a[0])), "r"(__float_as_uint(a[1])),
          "r"(__float_as_uint(a[2])), "r"(__float_as_uint(a[3])),
          "r"(__float_as_uint(b[0])), "r"(__float_as_uint(b[1])));
}
__device__ __forceinline__ void cp_async16(uint32_t saddr, const void* gptr) {
    asm volatile("cp.async.cg.shared.global [%0], [%1], 16;"
                 :: "r"(saddr), "l"(gptr));
}
#define CP_COMMIT()  asm volatile("cp.async.commit_group;")
#define CP_WAIT1()   asm volatile("cp.async.wait_group 1;")

// ---------------------------------------------------------------------------
// Launch 1: merged prep. blocks 0..7: M_h,m_h; 8..19: wdown rounding;
// 20..83: W_eff; 84..115: b_eff (32 j-blocks, 8-way k-split each).
// ---------------------------------------------------------------------------
__global__ void __launch_bounds__(256) prep_kernel(
    const float* __restrict__ Wuq, const float* __restrict__ buq,
    const float* __restrict__ Wuk,
    const float* __restrict__ Wdq, const float* __restrict__ Wdkv,
    const float* __restrict__ Wkr,
    const float* __restrict__ Wuv, const float* __restrict__ buv,
    const float* __restrict__ Wo,  const float* __restrict__ bo)
{
    const int tid = threadIdx.x;
    const int bx  = blockIdx.x;
    if (bx < 8) {
        const int h = bx;
        for (int idx = tid; idx < DC*DC; idx += 256) {
            int c = idx >> 5, i = idx & 31;
            float s = 0.f;
            const float* wq = Wuq + c*DM + h*DK;
            const float* wk = Wuk + i*DM + h*DK;
#pragma unroll 8
            for (int d = 0; d < DK; d++) s += wq[d]*wk[d];
            g_M[h*DC*DC + idx] = s;
        }
        if (tid < DC) {
            float s = 0.f;
            const float* wk = Wuk + tid*DM + h*DK;
#pragma unroll 8
            for (int d = 0; d < DK; d++) s += buq[h*DK + d]*wk[d];
            g_m[h*DC + tid] = s;
        }
    } else if (bx < 20) {
        int base = (bx - 8)*8192 + tid;
#pragma unroll
        for (int i = 0; i < 32; i++) {
            int idx = base + i*256;
            int k = idx / 96, c = idx - 96*k;
            float v;
            if (c < 32)      v = Wdq [k*32 + c];
            else if (c < 64) v = Wdkv[k*32 + (c-32)];
            else             v = Wkr [k*32 + (c-64)];
            g_wdown[idx] = to_tf32(v);
        }
    } else if (bx < 84) {
        const int h = (bx-20) >> 3, jt = (bx-20) & 7;
        const int i = tid >> 3, jg = tid & 7;
        const int j0 = jt*128 + jg*16;
        float acc[16];
#pragma unroll
        for (int k = 0; k < 16; k++) acc[k] = 0.f;
        for (int d = 0; d < DK; d++) {
            float wuv = Wuv[i*DM + h*DK + d];
            const float* wo = Wo + (size_t)(h*DK + d)*DM + j0;
#pragma unroll
            for (int k = 0; k < 16; k++) acc[k] += wuv*wo[k];
        }
#pragma unroll
        for (int k = 0; k < 16; k++)
            g_weff[(size_t)(h*32 + i)*DM + j0 + k] = to_tf32(acc[k]);
    } else {
        __shared__ float red[8][32];
        const int j0 = (bx - 84)*32;
        const int jj = tid & 31, ks = tid >> 5;
        float s = 0.f;
        const int k0 = ks*128;
        for (int k = 0; k < 128; k++)
            s += buv[k0 + k]*Wo[(size_t)(k0 + k)*DM + j0 + jj];
        red[ks][jj] = s;
        __syncthreads();
        if (ks == 0) {
            float acc = bo[j0 + jj];
#pragma unroll
            for (int r = 0; r < 8; r++) acc += red[r][jj];
            g_beff[j0 + jj] = acc;
        }
    }
}

// ---------------------------------------------------------------------------
// Launch 2: down projections via tf32 mma, 3-stage single-barrier pipeline.
// ---------------------------------------------------------------------------
#define DSA 36
#define DSB 104
#define DABUF (128*DSA)
#define DBBUF (32*DSB)
#define DOWN_SMEM_FLOATS (3*DABUF + 3*DBBUF)   // 23808 fl = 95232 B

__global__ void __launch_bounds__(256) down_proj_kernel(
    const float* __restrict__ h,
    const float* __restrict__ bdq, const float* __restrict__ bdkv,
    const float* __restrict__ bkr)
{
    extern __shared__ float sm[];
    float* a_s = sm;
    float* b_s = sm + 3*DABUF;
    const uint32_t smb = (uint32_t)__cvta_generic_to_shared(sm);

    const int tid  = threadIdx.x;
    const int lane = tid & 31;
    const int warp = tid >> 5;
    const int gid  = lane >> 2, tig = lane & 3;
    const int wm = warp >> 1, wn = warp & 1;
    const int row0 = blockIdx.x * 128;

    auto issue_ab = [&](int s, int kc) {
        const uint32_t adst = smb + (uint32_t)(s*DABUF)*4u;
        const uint32_t bdst = smb + (uint32_t)(3*DABUF + s*DBBUF)*4u;
#pragma unroll
        for (int i = 0; i < 4; i++) {
            int idx4 = tid + i*256;
            int r = idx4 >> 3, c4 = idx4 & 7;
            cp_async16(adst + (uint32_t)(r*DSA + c4*4)*4u,
                       h + (size_t)(row0+r)*DM + kc*32 + c4*4);
        }
#pragma unroll
        for (int i = 0; i < 3; i++) {
            int idx4 = tid + i*256;
            int r = idx4 / 24, cc = idx4 - 24*r;
            cp_async16(bdst + (uint32_t)(r*DSB + cc*4)*4u,
                       g_wdown + (size_t)(kc*32+r)*96 + cc*4);
        }
    };

    float acc[2][6][4];
#pragma unroll
    for (int im = 0; im < 2; im++)
#pragma unroll
        for (int n = 0; n < 6; n++)
#pragma unroll
            for (int j = 0; j < 4; j++) acc[im][n][j] = 0.f;

    issue_ab(0, 0); CP_COMMIT();
    issue_ab(1, 1); CP_COMMIT();

    for (int kc = 0; kc < 32; kc++) {
        CP_WAIT1();
        __syncthreads();
        if (kc + 2 < 32) issue_ab((kc + 2) % 3, kc + 2);
        CP_COMMIT();
        const float* ap = a_s + (kc % 3)*DABUF;
        const float* bp = b_s + (kc % 3)*DBBUF;

#pragma unroll
        for (int ks = 0; ks < 4; ks++) {
            const int c0 = ks*8 + tig;
            float a0[4], a1[4];
            int ra = wm*32 + gid;
            a0[0] = ap[ ra      *DSA + c0    ];
            a0[1] = ap[(ra+8)   *DSA + c0    ];
            a0[2] = ap[ ra      *DSA + c0 + 4];
            a0[3] = ap[(ra+8)   *DSA + c0 + 4];
            a1[0] = ap[(ra+16)  *DSA + c0    ];
            a1[1] = ap[(ra+24)  *DSA + c0    ];
            a1[2] = ap[(ra+16)  *DSA + c0 + 4];
            a1[3] = ap[(ra+24)  *DSA + c0 + 4];
#pragma unroll
            for (int nt = 0; nt < 6; nt++) {
                float b[2];
                int nb = wn*48 + nt*8 + gid;
                b[0] = bp[(ks*8 + tig    )*DSB + nb];
                b[1] = bp[(ks*8 + tig + 4)*DSB + nb];
                mma_tf32(acc[0][nt], a0, b);
                mma_tf32(acc[1][nt], a1, b);
            }
        }
    }

#pragma unroll
    for (int im = 0; im < 2; im++) {
        int rbase = row0 + wm*32 + im*16 + gid;
#pragma unroll
        for (int nt = 0; nt < 6; nt++) {
            int cc = wn*48 + nt*8 + 2*tig;
#pragma unroll
            for (int half = 0; half < 2; half++) {
                int rr = rbase + half*8;
#pragma unroll
                for (int e = 0; e < 2; e++) {
                    int col = cc + e;
                    float v = acc[im][nt][half*2 + e];
                    if (col < 32) {
                        g_cq[rr*32 + col] = v + bdq[col];
                    } else if (col < 64) {
                        float cv = to_tf32(v + bdkv[col-32]);
                        g_kt[rr*64 + ppos(col-32)] = cv;
                        int t = rr >> 6, lr = rr & 63;
                        g_cvT[((size_t)t*32 + (col-32))*64 + ppos(lr)] = cv;
                    } else {
                        g_kt[rr*64 + 32 + ppos(col-64)] =
                            to_tf32(v + bkr[col-64]);
                    }
                }
            }
        }
    }
}

// ---------------------------------------------------------------------------
// Launch 3: Q~ = scale * [c_q@M_h+m_h | c_q@W_QR_h+b_QR_h], pair-permuted
// ---------------------------------------------------------------------------
__global__ void __launch_bounds__(256) q_proj_kernel(
    const float* __restrict__ Wqr, const float* __restrict__ bqr)
{
    __shared__ float w_s[32*64];
    __shared__ float c_s[64*32];
    __shared__ float bias_s[64];

    const int tid  = threadIdx.x;
    const int hh   = blockIdx.y;
    const int row0 = blockIdx.x * 64;
    const float scale = 0.07905694150420948f;

#pragma unroll
    for (int i = 0; i < 8; i++) {
        int idx = tid + i*256;
        int k = idx >> 6, c = idx & 63;
        w_s[idx] = (c < 32) ? g_M[hh*DC*DC + k*32 + c]
                            : Wqr[k*256 + hh*32 + (c-32)];
    }
    if (tid < 64)
        bias_s[tid] = (tid < 32) ? g_m[hh*DC + tid] : bqr[hh*32 + tid - 32];
#pragma unroll
    for (int i = 0; i < 8; i++) {
        int idx = tid + i*256;
        c_s[idx] = g_cq[row0*32 + idx];
    }
    __syncthreads();

    const int col = tid & 63, rg = tid >> 6;
    const int pcol = ppos(col);
    for (int rr = 0; rr < 16; rr++) {
        int r = rg*16 + rr;
        float acc = bias_s[col];
#pragma unroll
        for (int k = 0; k < 32; k++) acc += c_s[r*32 + k]*w_s[k*64 + col];
        int row = row0 + r;
        int bb = row >> 11, ss = row & 2047;
        g_qt[((size_t)(bb*H_ + hh)*S_ + ss)*64 + pcol] = to_tf32(acc * scale);
    }
}

// ---------------------------------------------------------------------------
// Launch 4 (PROFILED): absorbed flash attention. 512 threads, q-tile 256,
// 3-stage single-barrier pipeline, P via intra-quad shuffles.
// ---------------------------------------------------------------------------
#define SKT 72
#define SCT 72
#define KT_FL (64*SKT)       // 4608
#define CT_FL (32*SCT)       // 2304
#define QBUF_FL (256*SKT)    // 18432
#define ATTN_SMEM_FLOATS (QBUF_FL + 3*KT_FL + 3*CT_FL)   // 39168 fl = 156672 B

__global__ void __launch_bounds__(512, 1) attn_kernel()
{
    extern __shared__ float sm[];
    float* qbuf = sm;                        // 256 x 72
    float* kbuf = sm + QBUF_FL;              // 3 x 64x72
    float* cbuf = kbuf + 3*KT_FL;            // 3 x 32x72
    const uint32_t smb = (uint32_t)__cvta_generic_to_shared(sm);

    const int tid  = threadIdx.x;
    const int lane = tid & 31;
    const int warp = tid >> 5;
    const int gid  = lane >> 2;
    const int tig  = lane & 3;
    const int bh   = blockIdx.y;
    const int bb   = bh >> 3, hh = bh & 7;
    const int q0   = blockIdx.x * 256;

    const float* qg = g_qt + ((size_t)bh*S_ + q0)*64;
    const float* kg = g_kt + (size_t)bb*S_*64;
    const float* cg = g_cvT + (size_t)bb*(S_/64)*2048;

    // ---- stage Q~ (256x64) into qbuf, lift fragments ----
#pragma unroll
    for (int i = 0; i < 8; i++) {
        int idx4 = tid + i*512;
        int r = idx4 >> 4, c4 = idx4 & 15;
        float4 v = *(const float4*)(qg + (size_t)r*64 + c4*4);
        *(float4*)(qbuf + r*SKT + c4*4) = v;
    }
    __syncthreads();

    const int r0 = warp*16 + gid;
    float qf[8][4];
#pragma unroll
    for (int kb = 0; kb < 8; kb++) {
        float2 f0 = *(const float2*)(qbuf +  r0   *SKT + kb*8 + 2*tig);
        float2 f1 = *(const float2*)(qbuf + (r0+8)*SKT + kb*8 + 2*tig);
        qf[kb][0] = f0.x; qf[kb][1] = f1.x; qf[kb][2] = f0.y; qf[kb][3] = f1.y;
    }

    auto issue_kv = [&](int s, int t) {
        const float* ksrc = kg + (size_t)t*64*64;
        const float* csrc = cg + (size_t)t*2048;
        const uint32_t kdst = smb + (uint32_t)(QBUF_FL + s*KT_FL)*4u;
        const uint32_t cdst = smb + (uint32_t)(QBUF_FL + 3*KT_FL + s*CT_FL)*4u;
#pragma unroll
        for (int i = 0; i < 2; i++) {
            int idx4 = tid + i*512;
            int r = idx4 >> 4, c4 = idx4 & 15;
            cp_async16(kdst + (uint32_t)(r*SKT + c4*4)*4u, ksrc + r*64 + c4*4);
        }
        {
            int c = tid >> 4, rg = tid & 15;
            cp_async16(cdst + (uint32_t)(c*SCT + rg*4)*4u, csrc + c*64 + rg*4);
        }
    };

    issue_kv(0, 0); CP_COMMIT();
    issue_kv(1, 1); CP_COMMIT();

    float m0 = -1e30f, m1 = -1e30f, l0 = 0.f, l1 = 0.f;
    float o[4][4];
#pragma unroll
    for (int i = 0; i < 4; i++)
#pragma unroll
        for (int j = 0; j < 4; j++) o[i][j] = 0.f;

    const int srcA = (lane & ~3) + (tig >> 1);
    const int srcB = srcA + 2;
    const bool odd = (tig & 1);

    for (int kt = 0; kt < S_/64; kt++) {
        CP_WAIT1();
        __syncthreads();                 // tile kt visible; slot (kt+2)%3 free
        if (kt + 2 < S_/64) issue_kv((kt + 2) % 3, kt + 2);
        CP_COMMIT();
        const float* ks = kbuf + (kt % 3)*KT_FL;
        const float* cs = cbuf + (kt % 3)*CT_FL;

        // ---- S = Q~ K~^T ----
        float sa[8][4];
#pragma unroll
        for (int n = 0; n < 8; n++)
#pragma unroll
            for (int j = 0; j < 4; j++) sa[n][j] = 0.f;

#pragma unroll
        for (int kb = 0; kb < 8; kb++) {
#pragma unroll
            for (int nt = 0; nt < 8; nt++) {
                float2 bv = *(const float2*)(ks + (nt*8+gid)*SKT + kb*8 + 2*tig);
                float b[2] = {bv.x, bv.y};
                mma_tf32(sa[nt], qf[kb], b);
            }
        }

        // ---- online softmax ----
        float mx0 = -1e30f, mx1 = -1e30f;
#pragma unroll
        for (int n = 0; n < 8; n++) {
            mx0 = fmaxf(mx0, fmaxf(sa[n][0], sa[n][1]));
            mx1 = fmaxf(mx1, fmaxf(sa[n][2], sa[n][3]));
        }
        mx0 = fmaxf(mx0, __shfl_xor_sync(0xffffffffu, mx0, 1));
        mx0 = fmaxf(mx0, __shfl_xor_sync(0xffffffffu, mx0, 2));
        mx1 = fmaxf(mx1, __shfl_xor_sync(0xffffffffu, mx1, 1));
        mx1 = fmaxf(mx1, __shfl_xor_sync(0xffffffffu, mx1, 2));

        float nm0 = fmaxf(m0, mx0), nm1 = fmaxf(m1, mx1);
        float al0 = __expf(m0 - nm0), al1 = __expf(m1 - nm1);
        m0 = nm0; m1 = nm1;

#pragma unroll
        for (int n = 0; n < 4; n++) {
            o[n][0] *= al0; o[n][1] *= al0;
            o[n][2] *= al1; o[n][3] *= al1;
        }

        // ---- P (registers) -> PV via intra-quad shuffles ----
        float rs0 = 0.f, rs1 = 0.f;
#pragma unroll
        for (int kb = 0; kb < 8; kb++) {
            float p00 = __expf(sa[kb][0] - nm0);
            float p01 = __expf(sa[kb][1] - nm0);
            float p10 = __expf(sa[kb][2] - nm1);
            float p11 = __expf(sa[kb][3] - nm1);
            rs0 += p00 + p01; rs1 += p10 + p11;

            float q00A = __shfl_sync(0xffffffffu, p00, srcA);
            float q01A = __shfl_sync(0xffffffffu, p01, srcA);
            float q00B = __shfl_sync(0xffffffffu, p00, srcB);
            float q01B = __shfl_sync(0xffffffffu, p01, srcB);
            float q10A = __shfl_sync(0xffffffffu, p10, srcA);
            float q11A = __shfl_sync(0xffffffffu, p11, srcA);
            float q10B = __shfl_sync(0xffffffffu, p10, srcB);
            float q11B = __shfl_sync(0xffffffffu, p11, srcB);

            float a[4];
            a[0] = to_tf32(odd ? q01A : q00A);
            a[1] = to_tf32(odd ? q11A : q10A);
            a[2] = to_tf32(odd ? q01B : q00B);
            a[3] = to_tf32(odd ? q11B : q10B);
#pragma unroll
            for (int nt = 0; nt < 4; nt++) {
                float2 bv = *(const float2*)(cs + (nt*8+gid)*SCT + kb*8 + 2*tig);
                float b[2] = {bv.x, bv.y};
                mma_tf32(o[nt], a, b);
            }
        }
        rs0 += __shfl_xor_sync(0xffffffffu, rs0, 1);
        rs0 += __shfl_xor_sync(0xffffffffu, rs0, 2);
        rs1 += __shfl_xor_sync(0xffffffffu, rs1, 1);
        rs1 += __shfl_xor_sync(0xffffffffu, rs1, 2);
        l0 = l0*al0 + rs0; l1 = l1*al1 + rs1;
    }

    const float inv0 = 1.f / l0, inv1 = 1.f / l1;
    const int s0 = q0 + r0;
    float* op0 = g_ot + ((size_t)(bb*S_ + s0    )*H_ + hh)*32;
    float* op1 = g_ot + ((size_t)(bb*S_ + s0 + 8)*H_ + hh)*32;
#pragma unroll
    for (int nt = 0; nt < 4; nt++) {
        int col = nt*8 + 2*tig;
        *(float2*)(op0 + col) = make_float2(to_tf32(o[nt][0]*inv0), to_tf32(o[nt][1]*inv0));
        *(float2*)(op1 + col) = make_float2(to_tf32(o[nt][2]*inv1), to_tf32(o[nt][3]*inv1));
    }
}

// ---------------------------------------------------------------------------
// Launch 5: out = O~[8192x256] @ W_eff[256x1024] + b_eff, 3-stage pipeline
// ---------------------------------------------------------------------------
#define SA 36
#define SB 136
#define ABUF_FL (128*SA)
#define BBUF_FL (32*SB)
#define OUT_SMEM_FLOATS (3*ABUF_FL + 3*BBUF_FL)

__global__ void __launch_bounds__(256) out_proj_kernel(float* __restrict__ out)
{
    extern __shared__ float sm[];
    float* a_s = sm;
    float* b_s = sm + 3*ABUF_FL;
    const uint32_t smb = (uint32_t)__cvta_generic_to_shared(sm);

    const int tid  = threadIdx.x;
    const int lane = tid & 31;
    const int warp = tid >> 5;
    const int gid  = lane >> 2, tig = lane & 3;
    const int wm = warp >> 1, wn = warp & 1;
    const int col0 = blockIdx.x * 128;
    const int row0 = blockIdx.y * 128;

    auto issue_ab = [&](int s, int kc) {
        const uint32_t adst = smb + (uint32_t)(s*ABUF_FL)*4u;
        const uint32_t bdst = smb + (uint32_t)(3*ABUF_FL + s*BBUF_FL)*4u;
#pragma unroll
        for (int i = 0; i < 4; i++) {
            int idx4 = tid + i*256;
            int r = idx4 >> 3, c4 = idx4 & 7;
            cp_async16(adst + (uint32_t)(r*SA + c4*4)*4u,
                       g_ot + (size_t)(row0+r)*256 + kc*32 + c4*4);
        }
#pragma unroll
        for (int i = 0; i < 4; i++) {
            int idx4 = tid + i*256;
            int r = idx4 >> 5, c4 = idx4 & 31;
            cp_async16(bdst + (uint32_t)(r*SB + c4*4)*4u,
                       g_weff + (size_t)(kc*32+r)*DM + col0 + c4*4);
        }
    };

    float acc[2][8][4];
#pragma unroll
    for (int im = 0; im < 2; im++)
#pragma unroll
        for (int n = 0; n < 8; n++)
#pragma unroll
            for (int j = 0; j < 4; j++) acc[im][n][j] = 0.f;

    issue_ab(0, 0); CP_COMMIT();
    issue_ab(1, 1); CP_COMMIT();

    for (int kc = 0; kc < 8; kc++) {
        CP_WAIT1();
        __syncthreads();
        if (kc + 2 < 8) issue_ab((kc + 2) % 3, kc + 2);
        CP_COMMIT();
        const float* ap = a_s + (kc % 3)*ABUF_FL;
        const float* bp = b_s + (kc % 3)*BBUF_FL;

#pragma unroll
        for (int ks = 0; ks < 4; ks++) {
            const int c0 = ks*8 + tig;
            float a0[4], a1[4];
            int ra = wm*32 + gid;
            a0[0] = ap[ ra      *SA + c0    ];
            a0[1] = ap[(ra+8)   *SA + c0    ];
            a0[2] = ap[ ra      *SA + c0 + 4];
            a0[3] = ap[(ra+8)   *SA + c0 + 4];
            a1[0] = ap[(ra+16)  *SA + c0    ];
            a1[1] = ap[(ra+24)  *SA + c0    ];
            a1[2] = ap[(ra+16)  *SA + c0 + 4];
            a1[3] = ap[(ra+24)  *SA + c0 + 4];
#pragma unroll
            for (int nt = 0; nt < 8; nt++) {
                float b[2];
                int nb = wn*64 + nt*8 + gid;
                b[0] = bp[(ks*8 + tig    )*SB + nb];
                b[1] = bp[(ks*8 + tig + 4)*SB + nb];
                mma_tf32(acc[0][nt], a0, b);
                mma_tf32(acc[1][nt], a1, b);
            }
        }
    }

#pragma unroll
    for (int im = 0; im < 2; im++) {
        int rr = row0 + wm*32 + im*16 + gid;
#pragma unroll
        for (int nt = 0; nt < 8; nt++) {
            int cc = col0 + wn*64 + nt*8 + 2*tig;
            float bx = g_beff[cc], by = g_beff[cc+1];
            *(float2*)(out + (size_t)rr*DM + cc) =
                make_float2(acc[im][nt][0] + bx, acc[im][nt][1] + by);
            *(float2*)(out + (size_t)(rr+8)*DM + cc) =
                make_float2(acc[im][nt][2] + bx, acc[im][nt][3] + by);
        }
    }
}

// ---------------------------------------------------------------------------
extern "C" void kernel_launch(void* const* d_in, const int* in_sizes, int n_in,
                              void* d_out, int out_size)
{
    (void)in_sizes; (void)n_in; (void)out_size;
    const float* h    = (const float*)d_in[0];
    const float* Wdq  = (const float*)d_in[1];
    const float* bdq  = (const float*)d_in[2];
    const float* Wuq  = (const float*)d_in[3];
    const float* buq  = (const float*)d_in[4];
    const float* Wdkv = (const float*)d_in[5];
    const float* bdkv = (const float*)d_in[6];
    const float* Wuk  = (const float*)d_in[7];
    const float* buk  = (const float*)d_in[8];   (void)buk; // cancels in softmax
    const float* Wuv  = (const float*)d_in[9];
    const float* buv  = (const float*)d_in[10];
    const float* Wqr  = (const float*)d_in[11];
    const float* bqr  = (const float*)d_in[12];
    const float* Wkr  = (const float*)d_in[13];
    const float* bkr  = (const float*)d_in[14];
    const float* Wo   = (const float*)d_in[15];
    const float* bo   = (const float*)d_in[16];
    float* out = (float*)d_out;

    cudaFuncSetAttribute(attn_kernel, cudaFuncAttributeMaxDynamicSharedMemorySize,
                         ATTN_SMEM_FLOATS * (int)sizeof(float));
    cudaFuncSetAttribute(out_proj_kernel, cudaFuncAttributeMaxDynamicSharedMemorySize,
                         OUT_SMEM_FLOATS * (int)sizeof(float));
    cudaFuncSetAttribute(down_proj_kernel, cudaFuncAttributeMaxDynamicSharedMemorySize,
                         DOWN_SMEM_FLOATS * (int)sizeof(float));

    // attn is the 4th launch (ncu capture window)
    prep_kernel<<<116, 256>>>(Wuq, buq, Wuk, Wdq, Wdkv, Wkr, Wuv, buv, Wo, bo);
    down_proj_kernel<<<BS_/128, 256, DOWN_SMEM_FLOATS * sizeof(float)>>>(h, bdq, bdkv, bkr);
    q_proj_kernel<<<dim3(BS_/64, H_), 256>>>(Wqr, bqr);
    attn_kernel<<<dim3(S_/256, B_*H_), 512, ATTN_SMEM_FLOATS * sizeof(float)>>>();
    out_proj_kernel<<<dim3(DM/128, BS_/128), 256, OUT_SMEM_FLOATS * sizeof(float)>>>(out);
}

// round 15
// speedup vs baseline: 10.4245x; 1.0879x over previous
#include <cuda_runtime.h>
#include <math.h>
#include <stdint.h>

#define B_   4
#define S_   2048
#define DM   1024
#define H_   8
#define DK   128
#define DC   32
#define DHR  32
#define BS_  (B_*S_)        // 8192

// ---------------- scratch (device globals) ----------------------------------
__device__ float g_cq  [BS_*DC];               // fp32
__device__ float g_kt  [BS_*64];               // K~ pair-permuted cols, rounded
__device__ float g_cvT [BS_*DC];               // C^T tiles [tile][col][64 rows perm]
__device__ float g_qt  [(size_t)B_*H_*S_*64];  // Q~ pair-permuted, PRE-SCALED, rounded
__device__ float g_ot  [(size_t)BS_*H_*32];    // O~ [B,S,H*32], rounded
__device__ float g_M   [H_*DC*DC];
__device__ float g_m   [H_*DC];
__device__ float g_weff[256*DM];               // rounded
__device__ float g_beff[DM];
__device__ float g_wdown[1024*96];             // [Wdq|Wdkv|Wkr], rounded

// ---------------- helpers ----------------------------------------------------
__device__ __forceinline__ float to_tf32(float x) {
    uint32_t u;
    asm("cvt.rna.tf32.f32 %0, %1;" : "=r"(u) : "f"(x));
    return __uint_as_float(u);
}
__device__ __forceinline__ int perm8(int c) {
    return ((c & 3) << 1) | ((c >> 2) & 1);
}
__device__ __forceinline__ int ppos(int c) {
    return (c & ~7) | perm8(c & 7);
}
__device__ __forceinline__ void mma_tf32(float* d, const float* a, const float* b) {
    asm("mma.sync.aligned.m16n8k8.row.col.f32.tf32.tf32.f32 "
        "{%0,%1,%2,%3}, {%4,%5,%6,%7}, {%8,%9}, {%0,%1,%2,%3};"
        : "+f"(d[0]), "+f"(d[1]), "+f"(d[2]), "+f"(d[3])
        : "r"(__float_as_uint(a[0])), "r"(__float_as_uint(a[1])),
          "r"(__float_as_uint(a[2])), "r"(__float_as_uint(a[3])),
          "r"(__float_as_uint(b[0])), "r"(__float_as_uint(b[1])));
}
__device__ __forceinline__ void cp_async16(uint32_t saddr, const void* gptr) {
    asm volatile("cp.async.cg.shared.global [%0], [%1], 16;"
                 :: "r"(saddr), "l"(gptr));
}
#define CP_COMMIT()  asm volatile("cp.async.commit_group;")
#define CP_WAIT1()   asm volatile("cp.async.wait_group 1;")

// ---------------------------------------------------------------------------
// Launch 1: merged prep. blocks 0..7: M_h,m_h (smem-staged, coalesced);
// 8..19: wdown rounding; 20..83: W_eff; 84..115: b_eff.
// ---------------------------------------------------------------------------
__global__ void __launch_bounds__(256) prep_kernel(
    const float* __restrict__ Wuq, const float* __restrict__ buq,
    const float* __restrict__ Wuk,
    const float* __restrict__ Wdq, const float* __restrict__ Wdkv,
    const float* __restrict__ Wkr,
    const float* __restrict__ Wuv, const float* __restrict__ buv,
    const float* __restrict__ Wo,  const float* __restrict__ bo)
{
    const int tid = threadIdx.x;
    const int bx  = blockIdx.x;
    if (bx < 8) {
        // stage the two 32x128 head-slices in smem (coalesced f4 loads)
        __shared__ float wq_s[32*128];
        __shared__ float wk_s[32*128];
        const int h = bx;
#pragma unroll
        for (int i = 0; i < 4; i++) {
            int idx4 = tid + i*256;          // 1024 f4 per slice
            int r = idx4 >> 5, c4 = idx4 & 31;
            *(float4*)(wq_s + r*128 + c4*4) =
                *(const float4*)(Wuq + (size_t)r*DM + h*DK + c4*4);
            *(float4*)(wk_s + r*128 + c4*4) =
                *(const float4*)(Wuk + (size_t)r*DM + h*DK + c4*4);
        }
        __syncthreads();
        for (int idx = tid; idx < DC*DC; idx += 256) {
            int c = idx >> 5, i = idx & 31;
            float s = 0.f;
#pragma unroll 8
            for (int d = 0; d < DK; d++) s += wq_s[c*128 + d]*wk_s[i*128 + d];
            g_M[h*DC*DC + idx] = s;
        }
        if (tid < DC) {
            float s = 0.f;
#pragma unroll 8
            for (int d = 0; d < DK; d++) s += buq[h*DK + d]*wk_s[tid*128 + d];
            g_m[h*DC + tid] = s;
        }
    } else if (bx < 20) {
        int base = (bx - 8)*8192 + tid;
#pragma unroll
        for (int i = 0; i < 32; i++) {
            int idx = base + i*256;
            int k = idx / 96, c = idx - 96*k;
            float v;
            if (c < 32)      v = Wdq [k*32 + c];
            else if (c < 64) v = Wdkv[k*32 + (c-32)];
            else             v = Wkr [k*32 + (c-64)];
            g_wdown[idx] = to_tf32(v);
        }
    } else if (bx < 84) {
        const int h = (bx-20) >> 3, jt = (bx-20) & 7;
        const int i = tid >> 3, jg = tid & 7;
        const int j0 = jt*128 + jg*16;
        float acc[16];
#pragma unroll
        for (int k = 0; k < 16; k++) acc[k] = 0.f;
        for (int d = 0; d < DK; d++) {
            float wuv = Wuv[i*DM + h*DK + d];
            const float* wo = Wo + (size_t)(h*DK + d)*DM + j0;
#pragma unroll
            for (int k = 0; k < 16; k++) acc[k] += wuv*wo[k];
        }
#pragma unroll
        for (int k = 0; k < 16; k++)
            g_weff[(size_t)(h*32 + i)*DM + j0 + k] = to_tf32(acc[k]);
    } else {
        __shared__ float red[8][32];
        const int j0 = (bx - 84)*32;
        const int jj = tid & 31, ks = tid >> 5;
        float s = 0.f;
        const int k0 = ks*128;
        for (int k = 0; k < 128; k++)
            s += buv[k0 + k]*Wo[(size_t)(k0 + k)*DM + j0 + jj];
        red[ks][jj] = s;
        __syncthreads();
        if (ks == 0) {
            float acc = bo[j0 + jj];
#pragma unroll
            for (int r = 0; r < 8; r++) acc += red[r][jj];
            g_beff[j0 + jj] = acc;
        }
    }
}

// ---------------------------------------------------------------------------
// Launch 2: down projections via tf32 mma, 3-stage pipeline, 64-row tiles
// (128 blocks -> full chip). Warps: 4 row-bands x 2 col-bands, acc[6][4].
// ---------------------------------------------------------------------------
#define DSA 36
#define DSB 104
#define DABUF (64*DSA)     // 2304
#define DBBUF (32*DSB)     // 3328
#define DOWN_SMEM_FLOATS (3*DABUF + 3*DBBUF)   // 16896 fl = 67584 B

__global__ void __launch_bounds__(256) down_proj_kernel(
    const float* __restrict__ h,
    const float* __restrict__ bdq, const float* __restrict__ bdkv,
    const float* __restrict__ bkr)
{
    extern __shared__ float sm[];
    float* a_s = sm;
    float* b_s = sm + 3*DABUF;
    const uint32_t smb = (uint32_t)__cvta_generic_to_shared(sm);

    const int tid  = threadIdx.x;
    const int lane = tid & 31;
    const int warp = tid >> 5;
    const int gid  = lane >> 2, tig = lane & 3;
    const int wm = warp >> 1, wn = warp & 1;   // wm 0..3 (16-row band), wn 0..1
    const int row0 = blockIdx.x * 64;

    auto issue_ab = [&](int s, int kc) {
        const uint32_t adst = smb + (uint32_t)(s*DABUF)*4u;
        const uint32_t bdst = smb + (uint32_t)(3*DABUF + s*DBBUF)*4u;
        // A: 64 rows x 8 f4 = 512 chunks -> 2/thread
#pragma unroll
        for (int i = 0; i < 2; i++) {
            int idx4 = tid + i*256;
            int r = idx4 >> 3, c4 = idx4 & 7;
            cp_async16(adst + (uint32_t)(r*DSA + c4*4)*4u,
                       h + (size_t)(row0+r)*DM + kc*32 + c4*4);
        }
        // B: 32 rows x 24 f4 = 768 chunks -> 3/thread
#pragma unroll
        for (int i = 0; i < 3; i++) {
            int idx4 = tid + i*256;
            int r = idx4 / 24, cc = idx4 - 24*r;
            cp_async16(bdst + (uint32_t)(r*DSB + cc*4)*4u,
                       g_wdown + (size_t)(kc*32+r)*96 + cc*4);
        }
    };

    float acc[6][4];
#pragma unroll
    for (int n = 0; n < 6; n++)
#pragma unroll
        for (int j = 0; j < 4; j++) acc[n][j] = 0.f;

    issue_ab(0, 0); CP_COMMIT();
    issue_ab(1, 1); CP_COMMIT();

    for (int kc = 0; kc < 32; kc++) {
        CP_WAIT1();
        __syncthreads();
        if (kc + 2 < 32) issue_ab((kc + 2) % 3, kc + 2);
        CP_COMMIT();
        const float* ap = a_s + (kc % 3)*DABUF;
        const float* bp = b_s + (kc % 3)*DBBUF;

#pragma unroll
        for (int ks = 0; ks < 4; ks++) {
            const int c0 = ks*8 + tig;
            float a0[4];
            int ra = wm*16 + gid;
            a0[0] = ap[ ra      *DSA + c0    ];
            a0[1] = ap[(ra+8)   *DSA + c0    ];
            a0[2] = ap[ ra      *DSA + c0 + 4];
            a0[3] = ap[(ra+8)   *DSA + c0 + 4];
#pragma unroll
            for (int nt = 0; nt < 6; nt++) {
                float b[2];
                int nb = wn*48 + nt*8 + gid;
                b[0] = bp[(ks*8 + tig    )*DSB + nb];
                b[1] = bp[(ks*8 + tig + 4)*DSB + nb];
                mma_tf32(acc[nt], a0, b);
            }
        }
    }

    {
        int rbase = row0 + wm*16 + gid;
#pragma unroll
        for (int nt = 0; nt < 6; nt++) {
            int cc = wn*48 + nt*8 + 2*tig;
#pragma unroll
            for (int half = 0; half < 2; half++) {
                int rr = rbase + half*8;
#pragma unroll
                for (int e = 0; e < 2; e++) {
                    int col = cc + e;
                    float v = acc[nt][half*2 + e];
                    if (col < 32) {
                        g_cq[rr*32 + col] = v + bdq[col];
                    } else if (col < 64) {
                        float cv = to_tf32(v + bdkv[col-32]);
                        g_kt[rr*64 + ppos(col-32)] = cv;
                        int t = rr >> 6, lr = rr & 63;
                        g_cvT[((size_t)t*32 + (col-32))*64 + ppos(lr)] = cv;
                    } else {
                        g_kt[rr*64 + 32 + ppos(col-64)] =
                            to_tf32(v + bkr[col-64]);
                    }
                }
            }
        }
    }
}

// ---------------------------------------------------------------------------
// Launch 3: Q~ = scale * [c_q@M_h+m_h | c_q@W_QR_h+b_QR_h], pair-permuted
// ---------------------------------------------------------------------------
__global__ void __launch_bounds__(256) q_proj_kernel(
    const float* __restrict__ Wqr, const float* __restrict__ bqr)
{
    __shared__ float w_s[32*64];
    __shared__ float c_s[64*32];
    __shared__ float bias_s[64];

    const int tid  = threadIdx.x;
    const int hh   = blockIdx.y;
    const int row0 = blockIdx.x * 64;
    const float scale = 0.07905694150420948f;

#pragma unroll
    for (int i = 0; i < 8; i++) {
        int idx = tid + i*256;
        int k = idx >> 6, c = idx & 63;
        w_s[idx] = (c < 32) ? g_M[hh*DC*DC + k*32 + c]
                            : Wqr[k*256 + hh*32 + (c-32)];
    }
    if (tid < 64)
        bias_s[tid] = (tid < 32) ? g_m[hh*DC + tid] : bqr[hh*32 + tid - 32];
#pragma unroll
    for (int i = 0; i < 8; i++) {
        int idx = tid + i*256;
        c_s[idx] = g_cq[row0*32 + idx];
    }
    __syncthreads();

    const int col = tid & 63, rg = tid >> 6;
    const int pcol = ppos(col);
    for (int rr = 0; rr < 16; rr++) {
        int r = rg*16 + rr;
        float acc = bias_s[col];
#pragma unroll
        for (int k = 0; k < 32; k++) acc += c_s[r*32 + k]*w_s[k*64 + col];
        int row = row0 + r;
        int bb = row >> 11, ss = row & 2047;
        g_qt[((size_t)(bb*H_ + hh)*S_ + ss)*64 + pcol] = to_tf32(acc * scale);
    }
}

// ---------------------------------------------------------------------------
// Launch 4 (PROFILED): absorbed flash attention (unchanged from R14).
// ---------------------------------------------------------------------------
#define SKT 72
#define SCT 72
#define KT_FL (64*SKT)
#define CT_FL (32*SCT)
#define QBUF_FL (256*SKT)
#define ATTN_SMEM_FLOATS (QBUF_FL + 3*KT_FL + 3*CT_FL)

__global__ void __launch_bounds__(512, 1) attn_kernel()
{
    extern __shared__ float sm[];
    float* qbuf = sm;
    float* kbuf = sm + QBUF_FL;
    float* cbuf = kbuf + 3*KT_FL;
    const uint32_t smb = (uint32_t)__cvta_generic_to_shared(sm);

    const int tid  = threadIdx.x;
    const int lane = tid & 31;
    const int warp = tid >> 5;
    const int gid  = lane >> 2;
    const int tig  = lane & 3;
    const int bh   = blockIdx.y;
    const int bb   = bh >> 3, hh = bh & 7;
    const int q0   = blockIdx.x * 256;

    const float* qg = g_qt + ((size_t)bh*S_ + q0)*64;
    const float* kg = g_kt + (size_t)bb*S_*64;
    const float* cg = g_cvT + (size_t)bb*(S_/64)*2048;

#pragma unroll
    for (int i = 0; i < 8; i++) {
        int idx4 = tid + i*512;
        int r = idx4 >> 4, c4 = idx4 & 15;
        float4 v = *(const float4*)(qg + (size_t)r*64 + c4*4);
        *(float4*)(qbuf + r*SKT + c4*4) = v;
    }
    __syncthreads();

    const int r0 = warp*16 + gid;
    float qf[8][4];
#pragma unroll
    for (int kb = 0; kb < 8; kb++) {
        float2 f0 = *(const float2*)(qbuf +  r0   *SKT + kb*8 + 2*tig);
        float2 f1 = *(const float2*)(qbuf + (r0+8)*SKT + kb*8 + 2*tig);
        qf[kb][0] = f0.x; qf[kb][1] = f1.x; qf[kb][2] = f0.y; qf[kb][3] = f1.y;
    }

    auto issue_kv = [&](int s, int t) {
        const float* ksrc = kg + (size_t)t*64*64;
        const float* csrc = cg + (size_t)t*2048;
        const uint32_t kdst = smb + (uint32_t)(QBUF_FL + s*KT_FL)*4u;
        const uint32_t cdst = smb + (uint32_t)(QBUF_FL + 3*KT_FL + s*CT_FL)*4u;
#pragma unroll
        for (int i = 0; i < 2; i++) {
            int idx4 = tid + i*512;
            int r = idx4 >> 4, c4 = idx4 & 15;
            cp_async16(kdst + (uint32_t)(r*SKT + c4*4)*4u, ksrc + r*64 + c4*4);
        }
        {
            int c = tid >> 4, rg = tid & 15;
            cp_async16(cdst + (uint32_t)(c*SCT + rg*4)*4u, csrc + c*64 + rg*4);
        }
    };

    issue_kv(0, 0); CP_COMMIT();
    issue_kv(1, 1); CP_COMMIT();

    float m0 = -1e30f, m1 = -1e30f, l0 = 0.f, l1 = 0.f;
    float o[4][4];
#pragma unroll
    for (int i = 0; i < 4; i++)
#pragma unroll
        for (int j = 0; j < 4; j++) o[i][j] = 0.f;

    const int srcA = (lane & ~3) + (tig >> 1);
    const int srcB = srcA + 2;
    const bool odd = (tig & 1);

    for (int kt = 0; kt < S_/64; kt++) {
        CP_WAIT1();
        __syncthreads();
        if (kt + 2 < S_/64) issue_kv((kt + 2) % 3, kt + 2);
        CP_COMMIT();
        const float* ks = kbuf + (kt % 3)*KT_FL;
        const float* cs = cbuf + (kt % 3)*CT_FL;

        float sa[8][4];
#pragma unroll
        for (int n = 0; n < 8; n++)
#pragma unroll
            for (int j = 0; j < 4; j++) sa[n][j] = 0.f;

#pragma unroll
        for (int kb = 0; kb < 8; kb++) {
#pragma unroll
            for (int nt = 0; nt < 8; nt++) {
                float2 bv = *(const float2*)(ks + (nt*8+gid)*SKT + kb*8 + 2*tig);
                float b[2] = {bv.x, bv.y};
                mma_tf32(sa[nt], qf[kb], b);
            }
        }

        float mx0 = -1e30f, mx1 = -1e30f;
#pragma unroll
        for (int n = 0; n < 8; n++) {
            mx0 = fmaxf(mx0, fmaxf(sa[n][0], sa[n][1]));
            mx1 = fmaxf(mx1, fmaxf(sa[n][2], sa[n][3]));
        }
        mx0 = fmaxf(mx0, __shfl_xor_sync(0xffffffffu, mx0, 1));
        mx0 = fmaxf(mx0, __shfl_xor_sync(0xffffffffu, mx0, 2));
        mx1 = fmaxf(mx1, __shfl_xor_sync(0xffffffffu, mx1, 1));
        mx1 = fmaxf(mx1, __shfl_xor_sync(0xffffffffu, mx1, 2));

        float nm0 = fmaxf(m0, mx0), nm1 = fmaxf(m1, mx1);
        float al0 = __expf(m0 - nm0), al1 = __expf(m1 - nm1);
        m0 = nm0; m1 = nm1;

#pragma unroll
        for (int n = 0; n < 4; n++) {
            o[n][0] *= al0; o[n][1] *= al0;
            o[n][2] *= al1; o[n][3] *= al1;
        }

        float rs0 = 0.f, rs1 = 0.f;
#pragma unroll
        for (int kb = 0; kb < 8; kb++) {
            float p00 = __expf(sa[kb][0] - nm0);
            float p01 = __expf(sa[kb][1] - nm0);
            float p10 = __expf(sa[kb][2] - nm1);
            float p11 = __expf(sa[kb][3] - nm1);
            rs0 += p00 + p01; rs1 += p10 + p11;

            float q00A = __shfl_sync(0xffffffffu, p00, srcA);
            float q01A = __shfl_sync(0xffffffffu, p01, srcA);
            float q00B = __shfl_sync(0xffffffffu, p00, srcB);
            float q01B = __shfl_sync(0xffffffffu, p01, srcB);
            float q10A = __shfl_sync(0xffffffffu, p10, srcA);
            float q11A = __shfl_sync(0xffffffffu, p11, srcA);
            float q10B = __shfl_sync(0xffffffffu, p10, srcB);
            float q11B = __shfl_sync(0xffffffffu, p11, srcB);

            float a[4];
            a[0] = to_tf32(odd ? q01A : q00A);
            a[1] = to_tf32(odd ? q11A : q10A);
            a[2] = to_tf32(odd ? q01B : q00B);
            a[3] = to_tf32(odd ? q11B : q10B);
#pragma unroll
            for (int nt = 0; nt < 4; nt++) {
                float2 bv = *(const float2*)(cs + (nt*8+gid)*SCT + kb*8 + 2*tig);
                float b[2] = {bv.x, bv.y};
                mma_tf32(o[nt], a, b);
            }
        }
        rs0 += __shfl_xor_sync(0xffffffffu, rs0, 1);
        rs0 += __shfl_xor_sync(0xffffffffu, rs0, 2);
        rs1 += __shfl_xor_sync(0xffffffffu, rs1, 1);
        rs1 += __shfl_xor_sync(0xffffffffu, rs1, 2);
        l0 = l0*al0 + rs0; l1 = l1*al1 + rs1;
    }

    const float inv0 = 1.f / l0, inv1 = 1.f / l1;
    const int s0 = q0 + r0;
    float* op0 = g_ot + ((size_t)(bb*S_ + s0    )*H_ + hh)*32;
    float* op1 = g_ot + ((size_t)(bb*S_ + s0 + 8)*H_ + hh)*32;
#pragma unroll
    for (int nt = 0; nt < 4; nt++) {
        int col = nt*8 + 2*tig;
        *(float2*)(op0 + col) = make_float2(to_tf32(o[nt][0]*inv0), to_tf32(o[nt][1]*inv0));
        *(float2*)(op1 + col) = make_float2(to_tf32(o[nt][2]*inv1), to_tf32(o[nt][3]*inv1));
    }
}

// ---------------------------------------------------------------------------
// Launch 5: out = O~[8192x256] @ W_eff[256x1024] + b_eff, 3-stage pipeline
// ---------------------------------------------------------------------------
#define SA 36
#define SB 136
#define ABUF_FL (128*SA)
#define BBUF_FL (32*SB)
#define OUT_SMEM_FLOATS (3*ABUF_FL + 3*BBUF_FL)

__global__ void __launch_bounds__(256) out_proj_kernel(float* __restrict__ out)
{
    extern __shared__ float sm[];
    float* a_s = sm;
    float* b_s = sm + 3*ABUF_FL;
    const uint32_t smb = (uint32_t)__cvta_generic_to_shared(sm);

    const int tid  = threadIdx.x;
    const int lane = tid & 31;
    const int warp = tid >> 5;
    const int gid  = lane >> 2, tig = lane & 3;
    const int wm = warp >> 1, wn = warp & 1;
    const int col0 = blockIdx.x * 128;
    const int row0 = blockIdx.y * 128;

    auto issue_ab = [&](int s, int kc) {
        const uint32_t adst = smb + (uint32_t)(s*ABUF_FL)*4u;
        const uint32_t bdst = smb + (uint32_t)(3*ABUF_FL + s*BBUF_FL)*4u;
#pragma unroll
        for (int i = 0; i < 4; i++) {
            int idx4 = tid + i*256;
            int r = idx4 >> 3, c4 = idx4 & 7;
            cp_async16(adst + (uint32_t)(r*SA + c4*4)*4u,
                       g_ot + (size_t)(row0+r)*256 + kc*32 + c4*4);
        }
#pragma unroll
        for (int i = 0; i < 4; i++) {
            int idx4 = tid + i*256;
            int r = idx4 >> 5, c4 = idx4 & 31;
            cp_async16(bdst + (uint32_t)(r*SB + c4*4)*4u,
                       g_weff + (size_t)(kc*32+r)*DM + col0 + c4*4);
        }
    };

    float acc[2][8][4];
#pragma unroll
    for (int im = 0; im < 2; im++)
#pragma unroll
        for (int n = 0; n < 8; n++)
#pragma unroll
            for (int j = 0; j < 4; j++) acc[im][n][j] = 0.f;

    issue_ab(0, 0); CP_COMMIT();
    issue_ab(1, 1); CP_COMMIT();

    for (int kc = 0; kc < 8; kc++) {
        CP_WAIT1();
        __syncthreads();
        if (kc + 2 < 8) issue_ab((kc + 2) % 3, kc + 2);
        CP_COMMIT();
        const float* ap = a_s + (kc % 3)*ABUF_FL;
        const float* bp = b_s + (kc % 3)*BBUF_FL;

#pragma unroll
        for (int ks = 0; ks < 4; ks++) {
            const int c0 = ks*8 + tig;
            float a0[4], a1[4];
            int ra = wm*32 + gid;
            a0[0] = ap[ ra      *SA + c0    ];
            a0[1] = ap[(ra+8)   *SA + c0    ];
            a0[2] = ap[ ra      *SA + c0 + 4];
            a0[3] = ap[(ra+8)   *SA + c0 + 4];
            a1[0] = ap[(ra+16)  *SA + c0    ];
            a1[1] = ap[(ra+24)  *SA + c0    ];
            a1[2] = ap[(ra+16)  *SA + c0 + 4];
            a1[3] = ap[(ra+24)  *SA + c0 + 4];
#pragma unroll
            for (int nt = 0; nt < 8; nt++) {
                float b[2];
                int nb = wn*64 + nt*8 + gid;
                b[0] = bp[(ks*8 + tig    )*SB + nb];
                b[1] = bp[(ks*8 + tig + 4)*SB + nb];
                mma_tf32(acc[0][nt], a0, b);
                mma_tf32(acc[1][nt], a1, b);
            }
        }
    }

#pragma unroll
    for (int im = 0; im < 2; im++) {
        int rr = row0 + wm*32 + im*16 + gid;
#pragma unroll
        for (int nt = 0; nt < 8; nt++) {
            int cc = col0 + wn*64 + nt*8 + 2*tig;
            float bx = g_beff[cc], by = g_beff[cc+1];
            *(float2*)(out + (size_t)rr*DM + cc) =
                make_float2(acc[im][nt][0] + bx, acc[im][nt][1] + by);
            *(float2*)(out + (size_t)(rr+8)*DM + cc) =
                make_float2(acc[im][nt][2] + bx, acc[im][nt][3] + by);
        }
    }
}

// ---------------------------------------------------------------------------
extern "C" void kernel_launch(void* const* d_in, const int* in_sizes, int n_in,
                              void* d_out, int out_size)
{
    (void)in_sizes; (void)n_in; (void)out_size;
    const float* h    = (const float*)d_in[0];
    const float* Wdq  = (const float*)d_in[1];
    const float* bdq  = (const float*)d_in[2];
    const float* Wuq  = (const float*)d_in[3];
    const float* buq  = (const float*)d_in[4];
    const float* Wdkv = (const float*)d_in[5];
    const float* bdkv = (const float*)d_in[6];
    const float* Wuk  = (const float*)d_in[7];
    const float* buk  = (const float*)d_in[8];   (void)buk; // cancels in softmax
    const float* Wuv  = (const float*)d_in[9];
    const float* buv  = (const float*)d_in[10];
    const float* Wqr  = (const float*)d_in[11];
    const float* bqr  = (const float*)d_in[12];
    const float* Wkr  = (const float*)d_in[13];
    const float* bkr  = (const float*)d_in[14];
    const float* Wo   = (const float*)d_in[15];
    const float* bo   = (const float*)d_in[16];
    float* out = (float*)d_out;

    cudaFuncSetAttribute(attn_kernel, cudaFuncAttributeMaxDynamicSharedMemorySize,
                         ATTN_SMEM_FLOATS * (int)sizeof(float));
    cudaFuncSetAttribute(out_proj_kernel, cudaFuncAttributeMaxDynamicSharedMemorySize,
                         OUT_SMEM_FLOATS * (int)sizeof(float));
    cudaFuncSetAttribute(down_proj_kernel, cudaFuncAttributeMaxDynamicSharedMemorySize,
                         DOWN_SMEM_FLOATS * (int)sizeof(float));

    // attn is the 4th launch (ncu capture window)
    prep_kernel<<<116, 256>>>(Wuq, buq, Wuk, Wdq, Wdkv, Wkr, Wuv, buv, Wo, bo);
    down_proj_kernel<<<BS_/64, 256, DOWN_SMEM_FLOATS * sizeof(float)>>>(h, bdq, bdkv, bkr);
    q_proj_kernel<<<dim3(BS_/64, H_), 256>>>(Wqr, bqr);
    attn_kernel<<<dim3(S_/256, B_*H_), 512, ATTN_SMEM_FLOATS * sizeof(float)>>>();
    out_proj_kernel<<<dim3(DM/128, BS_/128), 256, OUT_SMEM_FLOATS * sizeof(float)>>>(out);
}